// round 10
// baseline (speedup 1.0000x reference)
#include <cuda_runtime.h>
#include <cuda_bf16.h>
#include <math.h>

#define BB 4
#define SS 512
#define DD 768
#define HH 12
#define LL 12
#define FF 3072
#define DH 64
#define PP 512
#define BH (BB*HH)
#define MM (BB*SS)
#define NC 2304            // concatenated q|k|v width

__device__ __align__(256) float g_h   [MM*DD];
__device__ __align__(256) float g_s1  [MM*DD];     // scratch (sk-GEMM half outputs)
__device__ __align__(256) float g_s2  [MM*DD];
__device__ __align__(256) float g_ctx [MM*DD];
__device__ __align__(256) float g_tmp [MM*FF];
__device__ __align__(256) float g_qkv [MM*NC];     // q|k|v concatenated, stride 2304
__device__ __align__(256) float g_pos [PP*NC];     // posq|posk (cols 0..1535 used)
__device__ __align__(256) float g_scores[(size_t)BH*SS*SS];
__device__ __align__(256) float g_wcat[(size_t)LL*DD*NC];  // per-layer Wq|Wk|Wv
__device__ __align__(256) float g_bcat[LL*NC];
__device__ int g_tab[1024];

__device__ __forceinline__ unsigned f2tf(float x) {
    unsigned u; asm("cvt.rna.tf32.f32 %0, %1;" : "=r"(u) : "f"(x)); return u;
}
__device__ __forceinline__ uint4 f2tf4(float4 v) {
    return make_uint4(f2tf(v.x), f2tf(v.y), f2tf(v.z), f2tf(v.w));
}
__device__ __forceinline__ void mma_tf32(float* d, const unsigned* a, const unsigned* b) {
    asm volatile(
        "mma.sync.aligned.m16n8k8.row.col.f32.tf32.tf32.f32 "
        "{%0,%1,%2,%3}, {%4,%5,%6,%7}, {%8,%9}, {%0,%1,%2,%3};\n"
        : "+f"(d[0]), "+f"(d[1]), "+f"(d[2]), "+f"(d[3])
        : "r"(a[0]), "r"(a[1]), "r"(a[2]), "r"(a[3]), "r"(b[0]), "r"(b[1]));
}

// ---------------- embeddings + LN + mask ----------------
__global__ void __launch_bounds__(256) embed_ln_kernel(
    const int* __restrict__ ids, const int* __restrict__ segs, const int* __restrict__ pins,
    const float* __restrict__ mask,
    const float* __restrict__ tok, const float* __restrict__ pin, const float* __restrict__ seg,
    const float* __restrict__ w, const float* __restrict__ b, float* __restrict__ out)
{
    int t = blockIdx.x, tid = threadIdx.x;
    __shared__ float xs[DD];
    __shared__ float red[256];
    size_t io = (size_t)ids[t] * DD, po = (size_t)pins[t] * DD, so = (size_t)segs[t] * DD;
    float s = 0.f;
    for (int d = tid; d < DD; d += 256) {
        float x = tok[io + d] + pin[po + d] + seg[so + d];
        xs[d] = x; s += x;
    }
    red[tid] = s; __syncthreads();
    for (int st = 128; st > 0; st >>= 1) { if (tid < st) red[tid] += red[tid + st]; __syncthreads(); }
    float mu = red[0] * (1.0f / DD); __syncthreads();
    float s2 = 0.f;
    for (int d = tid; d < DD; d += 256) { float dv = xs[d] - mu; s2 += dv * dv; }
    red[tid] = s2; __syncthreads();
    for (int st = 128; st > 0; st >>= 1) { if (tid < st) red[tid] += red[tid + st]; __syncthreads(); }
    float inv = rsqrtf(red[0] * (1.0f / DD) + 1e-12f);
    float m = mask[t];
    for (int d = tid; d < DD; d += 256)
        out[(size_t)t * DD + d] = ((xs[d] - mu) * inv * w[d] + b[d]) * m;
}

// ---------------- bucket table ----------------
__global__ void buckets_kernel(int* __restrict__ tab)
{
    int x = blockIdx.x * blockDim.x + threadIdx.x;
    if (x >= 1023) { if (x == 1023) tab[1023] = 0; return; }
    int rel = x - 511;
    const int mid = 128;
    int ap = (rel < mid && rel > -mid) ? (mid - 1) : (rel < 0 ? -rel : rel);
    int bucket;
    if (ap <= mid) bucket = rel;
    else {
        double lp = ceil(log((double)ap / (double)mid) / log(511.0 / 128.0) * (mid - 1)) + mid;
        int sgn = (rel > 0) - (rel < 0);
        bucket = (int)lp * sgn;
    }
    int c = bucket + 256; c = c < 0 ? 0 : (c > 511 ? 511 : c);
    tab[x] = c;
}

// ---------------- weight concat: wcat[l][k][0:768|768:1536|1536:2304] = Wq|Wk|Wv ----------------
__global__ void __launch_bounds__(256) concat_w(
    const float* __restrict__ Wq, const float* __restrict__ Wk, const float* __restrict__ Wv,
    const float* __restrict__ bq, const float* __restrict__ bk, const float* __restrict__ bv,
    float* __restrict__ wcat, float* __restrict__ bcat)
{
    int l = blockIdx.y;
    size_t i = (size_t)blockIdx.x * 256 + threadIdx.x;   // < 768*2304
    int krow = (int)(i / NC), j = (int)(i % NC);
    int sel = j / DD, jj = j - sel * DD;
    const float* W = (sel == 0) ? Wq : (sel == 1) ? Wk : Wv;
    wcat[(size_t)l * DD * NC + i] = W[(size_t)l * DD * DD + (size_t)krow * DD + jj];
    if (i < NC) {
        const float* bb = (sel == 0) ? bq : (sel == 1) ? bk : bv;
        bcat[l * NC + i] = bb[l * DD + jj];
    }
}

// ---------------- shared dense tf32 GEMM core (proven R4/R5 body), 128x128 tile ----------------
#define GEMM_SMEM (2 * (128 * 20 + 16 * 136) * 4)

__device__ __forceinline__ void gemm128_core(
    const float* __restrict__ A, const float* __restrict__ Bm,
    const float* __restrict__ bias, float* __restrict__ C,
    int m0, int n0, int N, int K, int kStart, int kLen, int act, int useBias)
{
    extern __shared__ unsigned dsm[];
    unsigned* Asm = dsm;
    unsigned* Bsm = dsm + 2 * 2560;

    int tid = threadIdx.x;
    int w = tid >> 5, lane = tid & 31;
    int lr = lane >> 2, lc = lane & 3;
    int wm = (w >> 2) * 64, wn = (w & 3) * 32;

    int arow = tid >> 2, acol = (tid & 3) * 4;
    int brow = tid >> 5, bcol = (tid & 31) * 4;

    const float* aptr  = A + (size_t)(m0 + arow) * K + kStart + acol;
    const float* aptr2 = aptr + (size_t)64 * K;
    const float* bptr  = Bm + (size_t)(kStart + brow) * N + n0 + bcol;
    const float* bptr2 = bptr + (size_t)8 * N;
    const size_t bstep = (size_t)16 * N;

    const int kTiles = kLen >> 4;

    float4 ra0 = *(const float4*)aptr;
    float4 ra1 = *(const float4*)aptr2;
    float4 rb0 = *(const float4*)bptr;
    float4 rb1 = *(const float4*)bptr2;

    float acc[4][4][4] = {};

    for (int kt = 0; kt < kTiles; kt++) {
        unsigned* as = Asm + (kt & 1) * 2560;
        unsigned* bs = Bsm + (kt & 1) * 2176;
        *(uint4*)(as + arow * 20 + acol)        = f2tf4(ra0);
        *(uint4*)(as + (arow + 64) * 20 + acol) = f2tf4(ra1);
        *(uint4*)(bs + brow * 136 + bcol)       = f2tf4(rb0);
        *(uint4*)(bs + (brow + 8) * 136 + bcol) = f2tf4(rb1);
        __syncthreads();

        if (kt + 1 < kTiles) {
            aptr += 16; aptr2 += 16; bptr += bstep; bptr2 += bstep;
            ra0 = *(const float4*)aptr;
            ra1 = *(const float4*)aptr2;
            rb0 = *(const float4*)bptr;
            rb1 = *(const float4*)bptr2;
        }

        #pragma unroll
        for (int ks = 0; ks < 16; ks += 8) {
            unsigned af[4][4], bf[4][2];
            #pragma unroll
            for (int mt = 0; mt < 4; mt++) {
                int m = wm + mt * 16 + lr;
                af[mt][0] = as[m * 20 + ks + lc];
                af[mt][1] = as[(m + 8) * 20 + ks + lc];
                af[mt][2] = as[m * 20 + ks + lc + 4];
                af[mt][3] = as[(m + 8) * 20 + ks + lc + 4];
            }
            #pragma unroll
            for (int nt = 0; nt < 4; nt++) {
                int n = wn + nt * 8 + lr;
                bf[nt][0] = bs[(ks + lc) * 136 + n];
                bf[nt][1] = bs[(ks + lc + 4) * 136 + n];
            }
            #pragma unroll
            for (int mt = 0; mt < 4; mt++)
                #pragma unroll
                for (int nt = 0; nt < 4; nt++)
                    mma_tf32(acc[mt][nt], af[mt], bf[nt]);
        }
    }

    #pragma unroll
    for (int mt = 0; mt < 4; mt++) {
        int r = m0 + wm + mt * 16 + lr;
        #pragma unroll
        for (int nt = 0; nt < 4; nt++) {
            int c = n0 + wn + nt * 8 + lc * 2;
            float bv0 = useBias ? bias[c] : 0.f, bv1 = useBias ? bias[c + 1] : 0.f;
            float v00 = acc[mt][nt][0] + bv0, v01 = acc[mt][nt][1] + bv1;
            float v10 = acc[mt][nt][2] + bv0, v11 = acc[mt][nt][3] + bv1;
            if (act) {
                v00 = 0.5f * v00 * (1.0f + erff(v00 * 0.70710678118654752f));
                v01 = 0.5f * v01 * (1.0f + erff(v01 * 0.70710678118654752f));
                v10 = 0.5f * v10 * (1.0f + erff(v10 * 0.70710678118654752f));
                v11 = 0.5f * v11 * (1.0f + erff(v11 * 0.70710678118654752f));
            }
            *(float2*)(C + (size_t)r * N + c)       = make_float2(v00, v01);
            *(float2*)(C + (size_t)(r + 8) * N + c) = make_float2(v10, v11);
        }
    }
}

// QKV(+pos) via concatenated weights: z=0 -> qkv[2048x2304], z=1 -> pos[512x1536]
__global__ void __launch_bounds__(256) gemm_qkv(
    const float* __restrict__ hbuf, const float* __restrict__ rel,
    const float* __restrict__ Wcat, const float* __restrict__ bcat,
    float* __restrict__ qkv, float* __restrict__ pos)
{
    int z = blockIdx.z;
    int m0 = blockIdx.y * 128, n0 = blockIdx.x * 128;
    if (z == 0) {
        gemm128_core(hbuf, Wcat, bcat, qkv, m0, n0, NC, DD, 0, DD, 0, 1);
    } else {
        if (m0 >= PP || n0 >= 1536) return;
        gemm128_core(rel, Wcat, bcat, pos, m0, n0, NC, DD, 0, DD, 0, 1);
    }
}

__global__ void __launch_bounds__(256) gemm_one(
    const float* __restrict__ A, const float* __restrict__ Bm, const float* __restrict__ bias,
    float* __restrict__ C, int N, int K, int act)
{
    gemm128_core(A, Bm, bias, C, blockIdx.y * 128, blockIdx.x * 128, N, K, 0, K, act, 1);
}

__global__ void __launch_bounds__(256) gemm_sk(
    const float* __restrict__ A, const float* __restrict__ Bm, const float* __restrict__ bias,
    float* __restrict__ C0, float* __restrict__ C1, int N, int K)
{
    const int z = blockIdx.z;
    gemm128_core(A, Bm, bias, z ? C1 : C0, blockIdx.y * 128, blockIdx.x * 128,
                 N, K, z * (K >> 1), K >> 1, 0, z == 0);
}

// ---------------- fused disentangled score kernel (strided qkv/pos views) ----------------
__global__ void __launch_bounds__(256) score_fused(
    const float* __restrict__ Q, const float* __restrict__ Kt,
    const float* __restrict__ PKg, const float* __restrict__ PQg,
    const int* __restrict__ tab, const float* __restrict__ mask,
    float* __restrict__ scores, float scale)
{
    int z = blockIdx.z; int b = z / HH, hh = z % HH;
    int m0 = blockIdx.y * 64, n0 = blockIdx.x * 64;
    const float* Aq = Q  + (size_t)b * SS * NC + hh * DH;
    const float* Ak = Kt + (size_t)b * SS * NC + hh * DH;
    const float* PK = PKg + hh * DH;
    const float* PQ = PQg + hh * DH;

    extern __shared__ unsigned ssm[];
    unsigned* Qs  = ssm;
    unsigned* Ks  = ssm + 4352;
    unsigned* PKs = ssm + 8704;
    unsigned* PQs = ssm + 17408;
    float* C1s = (float*)(ssm + 8704);
    float* C2s = (float*)(ssm + 17152);

    int tid = threadIdx.x;
    int w = tid >> 5, lane = tid & 31;
    int lr = lane >> 2, lc = lane & 3;
    int wr = w >> 2, wc = w & 3;
    const int dlo = m0 - n0 - 63;

    {
        int row = tid >> 2;
        int col = (tid & 3) * 16;
        #pragma unroll
        for (int c4 = 0; c4 < 4; c4++) {
            float4 v = *(const float4*)(Aq + (size_t)(m0 + row) * NC + col + c4 * 4);
            *(uint4*)(Qs + row * 68 + col + c4 * 4) = f2tf4(v);
        }
        #pragma unroll
        for (int c4 = 0; c4 < 4; c4++) {
            float4 v = *(const float4*)(Ak + (size_t)(n0 + row) * NC + col + c4 * 4);
            *(uint4*)(Ks + row * 68 + col + c4 * 4) = f2tf4(v);
        }
        #pragma unroll
        for (int half = 0; half < 2; half++) {
            int t = row + half * 64;
            int tt = t < 127 ? t : 126;
            int pidx = tab[dlo + tt + 511];
            #pragma unroll
            for (int c4 = 0; c4 < 4; c4++) {
                float4 vk = *(const float4*)(PK + (size_t)pidx * NC + col + c4 * 4);
                *(uint4*)(PKs + t * 68 + col + c4 * 4) = f2tf4(vk);
                float4 vq = *(const float4*)(PQ + (size_t)pidx * NC + col + c4 * 4);
                *(uint4*)(PQs + t * 68 + col + c4 * 4) = f2tf4(vq);
            }
        }
    }
    __syncthreads();

    float accS[2][2][4] = {};
    float acc1[2][4][4] = {};
    float acc2[2][4][4] = {};

    #pragma unroll
    for (int ks = 0; ks < DH; ks += 8) {
        unsigned aq[2][4], ak[2][4];
        #pragma unroll
        for (int mt = 0; mt < 2; mt++) {
            int m = wr * 32 + mt * 16 + lr;
            aq[mt][0] = Qs[m * 68 + ks + lc];       aq[mt][1] = Qs[(m + 8) * 68 + ks + lc];
            aq[mt][2] = Qs[m * 68 + ks + lc + 4];   aq[mt][3] = Qs[(m + 8) * 68 + ks + lc + 4];
            ak[mt][0] = Ks[m * 68 + ks + lc];       ak[mt][1] = Ks[(m + 8) * 68 + ks + lc];
            ak[mt][2] = Ks[m * 68 + ks + lc + 4];   ak[mt][3] = Ks[(m + 8) * 68 + ks + lc + 4];
        }
        unsigned bS[2][2], b1[4][2], b2[4][2];
        #pragma unroll
        for (int nt = 0; nt < 2; nt++) {
            int n = wc * 16 + nt * 8 + lr;
            bS[nt][0] = Ks[n * 68 + ks + lc];
            bS[nt][1] = Ks[n * 68 + ks + lc + 4];
        }
        #pragma unroll
        for (int nt = 0; nt < 4; nt++) {
            int n = wc * 32 + nt * 8 + lr;
            b1[nt][0] = PKs[n * 68 + ks + lc];
            b1[nt][1] = PKs[n * 68 + ks + lc + 4];
            b2[nt][0] = PQs[n * 68 + ks + lc];
            b2[nt][1] = PQs[n * 68 + ks + lc + 4];
        }
        #pragma unroll
        for (int mt = 0; mt < 2; mt++) {
            #pragma unroll
            for (int nt = 0; nt < 2; nt++) mma_tf32(accS[mt][nt], aq[mt], bS[nt]);
            #pragma unroll
            for (int nt = 0; nt < 4; nt++) { mma_tf32(acc1[mt][nt], aq[mt], b1[nt]); mma_tf32(acc2[mt][nt], ak[mt], b2[nt]); }
        }
    }
    __syncthreads();

    #pragma unroll
    for (int mt = 0; mt < 2; mt++) {
        int r = wr * 32 + mt * 16 + lr;
        #pragma unroll
        for (int nt = 0; nt < 4; nt++) {
            int c = wc * 32 + nt * 8 + lc * 2;
            C1s[r * 132 + c] = acc1[mt][nt][0]; C1s[r * 132 + c + 1] = acc1[mt][nt][1];
            C1s[(r + 8) * 132 + c] = acc1[mt][nt][2]; C1s[(r + 8) * 132 + c + 1] = acc1[mt][nt][3];
            C2s[r * 132 + c] = acc2[mt][nt][0]; C2s[r * 132 + c + 1] = acc2[mt][nt][1];
            C2s[(r + 8) * 132 + c] = acc2[mt][nt][2]; C2s[(r + 8) * 132 + c + 1] = acc2[mt][nt][3];
        }
    }
    __syncthreads();

    #pragma unroll
    for (int mt = 0; mt < 2; mt++) {
        #pragma unroll
        for (int nt = 0; nt < 2; nt++) {
            int r = wr * 32 + mt * 16 + lr;
            int c0 = wc * 16 + nt * 8 + lc * 2;
            #pragma unroll
            for (int half = 0; half < 2; half++) {
                int rr = r + half * 8;
                float o[2];
                #pragma unroll
                for (int e = 0; e < 2; e++) {
                    int cc = c0 + e;
                    int t = rr - cc + 63;
                    float val = (accS[mt][nt][half * 2 + e] + C1s[rr * 132 + t] + C2s[cc * 132 + t]) * scale;
                    val += (1.0f - mask[b * SS + n0 + cc]) * (-1e9f);
                    o[e] = val;
                }
                *(float2*)(scores + ((size_t)z * SS + m0 + rr) * SS + n0 + c0) = make_float2(o[0], o[1]);
            }
        }
    }
}

// ---------------- fused softmax + ctx GEMM (V strided in qkv) ----------------
__global__ void __launch_bounds__(256) softmax_ctx(
    const float* __restrict__ Sc, const float* __restrict__ V, float* __restrict__ O)
{
    int z = blockIdx.y; int b = z / HH, hh = z % HH;
    int m0 = blockIdx.x * 128;
    const float* A = Sc + (size_t)z * SS * SS;
    const float* Bv = V + (size_t)b * SS * NC + hh * DH;

    __shared__ float rmax[128], rinv[128];
    extern __shared__ unsigned dsm[];
    unsigned* Asm = dsm;
    unsigned* Bsm = dsm + 2 * 2560;

    int tid = threadIdx.x;
    int w = tid >> 5, lane = tid & 31;

    #pragma unroll
    for (int i = 0; i < 16; i++) {
        int row = w * 16 + i;
        const float* rp = A + (size_t)(m0 + row) * SS;
        float m = -1e30f, s = 0.f;
        #pragma unroll
        for (int j = 0; j < 4; j++) {
            float4 x = *(const float4*)(rp + j * 128 + lane * 4);
            float mx = fmaxf(fmaxf(x.x, x.y), fmaxf(x.z, x.w));
            float mn = fmaxf(m, mx);
            s = s * __expf(m - mn)
              + __expf(x.x - mn) + __expf(x.y - mn) + __expf(x.z - mn) + __expf(x.w - mn);
            m = mn;
        }
        #pragma unroll
        for (int o = 16; o > 0; o >>= 1) {
            float m2 = __shfl_xor_sync(0xffffffffu, m, o);
            float s2 = __shfl_xor_sync(0xffffffffu, s, o);
            float mn = fmaxf(m, m2);
            s = s * __expf(m - mn) + s2 * __expf(m2 - mn);
            m = mn;
        }
        if (lane == 0) { rmax[row] = m; rinv[row] = 1.0f / s; }
    }
    __syncthreads();

    int lr = lane >> 2, lc = lane & 3;
    int wm = (w >> 1) * 32, wn = (w & 1) * 32;

    int arow = tid & 127, acol = (tid >> 7) * 8;
    int brow = tid >> 4, bcol = (tid & 15) * 4;

    const float mx = rmax[arow];
    const float iv = rinv[arow];

    const float* aptr = A + (size_t)(m0 + arow) * SS + acol;
    const float* bptr = Bv + (size_t)brow * NC + bcol;
    const size_t bstep = (size_t)16 * NC;

    const int kTiles = SS / 16;

    float4 ra0 = *(const float4*)aptr;
    float4 ra1 = *(const float4*)(aptr + 4);
    float4 rb0 = *(const float4*)bptr;

    float acc[2][4][4] = {};

    for (int kt = 0; kt < kTiles; kt++) {
        unsigned* as = Asm + (kt & 1) * 2560;
        unsigned* bs = Bsm + (kt & 1) * 1152;
        float4 p0 = make_float4(__expf(ra0.x - mx) * iv, __expf(ra0.y - mx) * iv,
                                __expf(ra0.z - mx) * iv, __expf(ra0.w - mx) * iv);
        float4 p1 = make_float4(__expf(ra1.x - mx) * iv, __expf(ra1.y - mx) * iv,
                                __expf(ra1.z - mx) * iv, __expf(ra1.w - mx) * iv);
        *(uint4*)(as + arow * 20 + acol)     = f2tf4(p0);
        *(uint4*)(as + arow * 20 + acol + 4) = f2tf4(p1);
        *(uint4*)(bs + brow * 72 + bcol)     = f2tf4(rb0);
        __syncthreads();

        if (kt + 1 < kTiles) {
            aptr += 16; bptr += bstep;
            ra0 = *(const float4*)aptr;
            ra1 = *(const float4*)(aptr + 4);
            rb0 = *(const float4*)bptr;
        }

        #pragma unroll
        for (int ks = 0; ks < 16; ks += 8) {
            unsigned af[2][4], bf[4][2];
            #pragma unroll
            for (int mt = 0; mt < 2; mt++) {
                int m = wm + mt * 16 + lr;
                af[mt][0] = as[m * 20 + ks + lc];
                af[mt][1] = as[(m + 8) * 20 + ks + lc];
                af[mt][2] = as[m * 20 + ks + lc + 4];
                af[mt][3] = as[(m + 8) * 20 + ks + lc + 4];
            }
            #pragma unroll
            for (int nt = 0; nt < 4; nt++) {
                int n = wn + nt * 8 + lr;
                bf[nt][0] = bs[(ks + lc) * 72 + n];
                bf[nt][1] = bs[(ks + lc + 4) * 72 + n];
            }
            #pragma unroll
            for (int mt = 0; mt < 2; mt++)
                #pragma unroll
                for (int nt = 0; nt < 4; nt++)
                    mma_tf32(acc[mt][nt], af[mt], bf[nt]);
        }
    }

    #pragma unroll
    for (int mt = 0; mt < 2; mt++) {
        int r = m0 + wm + mt * 16 + lr;
        #pragma unroll
        for (int nt = 0; nt < 4; nt++) {
            int c = wn + nt * 8 + lc * 2;
            *(float2*)(O + ((size_t)b * SS + r) * DD + hh * DH + c)     = make_float2(acc[mt][nt][0], acc[mt][nt][1]);
            *(float2*)(O + ((size_t)b * SS + r + 8) * DD + hh * DH + c) = make_float2(acc[mt][nt][2], acc[mt][nt][3]);
        }
    }
}

// ---------------- residual add (two deltas) + LN ----------------
__global__ void __launch_bounds__(256) add_ln3_kernel(
    float* __restrict__ h, const float* __restrict__ d1, const float* __restrict__ d2,
    const float* __restrict__ w, const float* __restrict__ b)
{
    int t = blockIdx.x, tid = threadIdx.x;
    __shared__ float xs[DD];
    __shared__ float red[256];
    float* hr = h + (size_t)t * DD;
    const float* r1 = d1 + (size_t)t * DD;
    const float* r2 = d2 + (size_t)t * DD;

    float s = 0.f;
    for (int d = tid; d < DD; d += 256) { float x = hr[d] + r1[d] + r2[d]; xs[d] = x; s += x; }
    red[tid] = s; __syncthreads();
    for (int st = 128; st > 0; st >>= 1) { if (tid < st) red[tid] += red[tid + st]; __syncthreads(); }
    float mu = red[0] * (1.0f / DD); __syncthreads();
    float s2 = 0.f;
    for (int d = tid; d < DD; d += 256) { float dv = xs[d] - mu; s2 += dv * dv; }
    red[tid] = s2; __syncthreads();
    for (int st = 128; st > 0; st >>= 1) { if (tid < st) red[tid] += red[tid + st]; __syncthreads(); }
    float inv = rsqrtf(red[0] * (1.0f / DD) + 1e-12f);
    for (int d = tid; d < DD; d += 256) hr[d] = (xs[d] - mu) * inv * w[d] + b[d];
}

// ---------------- host orchestration ----------------
extern "C" void kernel_launch(void* const* d_in, const int* in_sizes, int n_in,
                              void* d_out, int out_size)
{
    const int*   input_ids   = (const int*)  d_in[0];
    const int*   segment_ids = (const int*)  d_in[1];
    const int*   pinyin_ids  = (const int*)  d_in[2];
    const float* attn_mask   = (const float*)d_in[3];
    const float* tok_emb     = (const float*)d_in[4];
    const float* pin_emb     = (const float*)d_in[5];
    const float* seg_emb     = (const float*)d_in[6];
    const float* emb_ln_w    = (const float*)d_in[7];
    const float* emb_ln_b    = (const float*)d_in[8];
    const float* rel_emb     = (const float*)d_in[9];
    const float* Wq = (const float*)d_in[10]; const float* bq = (const float*)d_in[11];
    const float* Wk = (const float*)d_in[12]; const float* bk = (const float*)d_in[13];
    const float* Wv = (const float*)d_in[14]; const float* bv = (const float*)d_in[15];
    const float* Wo = (const float*)d_in[16]; const float* bo = (const float*)d_in[17];
    const float* ln1w = (const float*)d_in[18]; const float* ln1b = (const float*)d_in[19];
    const float* W1 = (const float*)d_in[20]; const float* b1 = (const float*)d_in[21];
    const float* W2 = (const float*)d_in[22]; const float* b2 = (const float*)d_in[23];
    const float* ln2w = (const float*)d_in[24]; const float* ln2b = (const float*)d_in[25];

    float *h, *s1, *s2, *ctx, *tmp, *qkv, *pos, *scores, *wcat, *bcat;
    int *tab;
    cudaGetSymbolAddress((void**)&h,      g_h);
    cudaGetSymbolAddress((void**)&s1,     g_s1);
    cudaGetSymbolAddress((void**)&s2,     g_s2);
    cudaGetSymbolAddress((void**)&ctx,    g_ctx);
    cudaGetSymbolAddress((void**)&tmp,    g_tmp);
    cudaGetSymbolAddress((void**)&qkv,    g_qkv);
    cudaGetSymbolAddress((void**)&pos,    g_pos);
    cudaGetSymbolAddress((void**)&scores, g_scores);
    cudaGetSymbolAddress((void**)&wcat,   g_wcat);
    cudaGetSymbolAddress((void**)&bcat,   g_bcat);
    cudaGetSymbolAddress((void**)&tab,    g_tab);

    const int CTX_SMEM   = 2 * (128 * 20 + 16 * 72) * 4;
    const int SCORE_SMEM = (4352 * 2 + 8704 * 2) * 4;
    cudaFuncSetAttribute(gemm_qkv,    cudaFuncAttributeMaxDynamicSharedMemorySize, GEMM_SMEM);
    cudaFuncSetAttribute(gemm_one,    cudaFuncAttributeMaxDynamicSharedMemorySize, GEMM_SMEM);
    cudaFuncSetAttribute(gemm_sk,     cudaFuncAttributeMaxDynamicSharedMemorySize, GEMM_SMEM);
    cudaFuncSetAttribute(softmax_ctx, cudaFuncAttributeMaxDynamicSharedMemorySize, CTX_SMEM);
    cudaFuncSetAttribute(score_fused, cudaFuncAttributeMaxDynamicSharedMemorySize, SCORE_SMEM);

    const float scale = 0.07216878364870323f;  // 1/sqrt(3*DH)

    embed_ln_kernel<<<MM, 256>>>(input_ids, segment_ids, pinyin_ids, attn_mask,
                                 tok_emb, pin_emb, seg_emb, emb_ln_w, emb_ln_b, h);
    buckets_kernel<<<4, 256>>>(tab);
    concat_w<<<dim3(DD * NC / 256, LL), 256>>>(Wq, Wk, Wv, bq, bk, bv, wcat, bcat);

    for (int i = 0; i < LL; i++) {
        const float* wc_i = wcat + (size_t)i * DD * NC;
        const float* bc_i = bcat + (size_t)i * NC;
        const float* Wo_i = Wo + (size_t)i * DD * DD; const float* bo_i = bo + (size_t)i * DD;
        const float* W1_i = W1 + (size_t)i * DD * FF; const float* b1_i = b1 + (size_t)i * FF;
        const float* W2_i = W2 + (size_t)i * FF * DD; const float* b2_i = b2 + (size_t)i * DD;

        // QKV (z=0) + pos projections (z=1) in one launch, 336 effective CTAs
        gemm_qkv<<<dim3(NC / 128, MM / 128, 2), 256, GEMM_SMEM>>>(
            h, rel_emb, wc_i, bc_i, qkv, pos);

        // fused disentangled scores, then fused softmax + probs@V
        score_fused<<<dim3(8, 8, BH), 256, SCORE_SMEM>>>(
            qkv, qkv + DD, pos + DD, pos, tab, attn_mask, scores, scale);
        softmax_ctx<<<dim3(SS / 128, BH), 256, CTX_SMEM>>>(scores, qkv + 2 * DD, ctx);

        // output projection (split-K=2) + residual LN
        gemm_sk<<<dim3(DD / 128, MM / 128, 2), 256, GEMM_SMEM>>>(
            ctx, Wo_i, bo_i, s1, s2, DD, DD);
        add_ln3_kernel<<<MM, 256>>>(h, s1, s2, ln1w + (size_t)i * DD, ln1b + (size_t)i * DD);

        // feed-forward: FF1 full, FF2 split-K=2
        gemm_one<<<dim3(FF / 128, MM / 128), 256, GEMM_SMEM>>>(h, W1_i, b1_i, tmp, FF, DD, 1);
        gemm_sk<<<dim3(DD / 128, MM / 128, 2), 256, GEMM_SMEM>>>(
            tmp, W2_i, b2_i, s1, s2, DD, FF);
        add_ln3_kernel<<<MM, 256>>>(h, s1, s2, ln2w + (size_t)i * DD, ln2b + (size_t)i * DD);
    }

    cudaMemcpyAsync(d_out, h, sizeof(float) * (size_t)out_size, cudaMemcpyDeviceToDevice);
}

// round 11
// speedup vs baseline: 1.0584x; 1.0584x over previous
#include <cuda_runtime.h>
#include <cuda_bf16.h>
#include <math.h>

#define BB 4
#define SS 512
#define DD 768
#define HH 12
#define LL 12
#define FF 3072
#define DH 64
#define PP 512
#define BH (BB*HH)
#define MM (BB*SS)

__device__ __align__(256) float g_h   [MM*DD];
__device__ __align__(256) float g_q   [MM*DD];
__device__ __align__(256) float g_k   [MM*DD];
__device__ __align__(256) float g_v   [MM*DD];
__device__ __align__(256) float g_ctx [MM*DD];
__device__ __align__(256) float g_tmp [MM*FF];
__device__ __align__(256) float g_poskL[(size_t)LL*PP*DD];
__device__ __align__(256) float g_posqL[(size_t)LL*PP*DD];
__device__ __align__(256) float g_scores[(size_t)BH*SS*SS];
__device__ int g_tab[1024];

__device__ __forceinline__ unsigned f2tf(float x) {
    unsigned u; asm("cvt.rna.tf32.f32 %0, %1;" : "=r"(u) : "f"(x)); return u;
}
__device__ __forceinline__ uint4 f2tf4(float4 v) {
    return make_uint4(f2tf(v.x), f2tf(v.y), f2tf(v.z), f2tf(v.w));
}
__device__ __forceinline__ void mma_tf32(float* d, const unsigned* a, const unsigned* b) {
    asm volatile(
        "mma.sync.aligned.m16n8k8.row.col.f32.tf32.tf32.f32 "
        "{%0,%1,%2,%3}, {%4,%5,%6,%7}, {%8,%9}, {%0,%1,%2,%3};\n"
        : "+f"(d[0]), "+f"(d[1]), "+f"(d[2]), "+f"(d[3])
        : "r"(a[0]), "r"(a[1]), "r"(a[2]), "r"(a[3]), "r"(b[0]), "r"(b[1]));
}

// ---------------- embeddings + LN + mask ----------------
__global__ void __launch_bounds__(256) embed_ln_kernel(
    const int* __restrict__ ids, const int* __restrict__ segs, const int* __restrict__ pins,
    const float* __restrict__ mask,
    const float* __restrict__ tok, const float* __restrict__ pin, const float* __restrict__ seg,
    const float* __restrict__ w, const float* __restrict__ b, float* __restrict__ out)
{
    int t = blockIdx.x, tid = threadIdx.x;
    __shared__ float xs[DD];
    __shared__ float red[256];
    size_t io = (size_t)ids[t] * DD, po = (size_t)pins[t] * DD, so = (size_t)segs[t] * DD;
    float s = 0.f;
    for (int d = tid; d < DD; d += 256) {
        float x = tok[io + d] + pin[po + d] + seg[so + d];
        xs[d] = x; s += x;
    }
    red[tid] = s; __syncthreads();
    for (int st = 128; st > 0; st >>= 1) { if (tid < st) red[tid] += red[tid + st]; __syncthreads(); }
    float mu = red[0] * (1.0f / DD); __syncthreads();
    float s2 = 0.f;
    for (int d = tid; d < DD; d += 256) { float dv = xs[d] - mu; s2 += dv * dv; }
    red[tid] = s2; __syncthreads();
    for (int st = 128; st > 0; st >>= 1) { if (tid < st) red[tid] += red[tid + st]; __syncthreads(); }
    float inv = rsqrtf(red[0] * (1.0f / DD) + 1e-12f);
    float m = mask[t];
    for (int d = tid; d < DD; d += 256)
        out[(size_t)t * DD + d] = ((xs[d] - mu) * inv * w[d] + b[d]) * m;
}

// ---------------- bucket table ----------------
__global__ void buckets_kernel(int* __restrict__ tab)
{
    int x = blockIdx.x * blockDim.x + threadIdx.x;
    if (x >= 1023) { if (x == 1023) tab[1023] = 0; return; }
    int rel = x - 511;
    const int mid = 128;
    int ap = (rel < mid && rel > -mid) ? (mid - 1) : (rel < 0 ? -rel : rel);
    int bucket;
    if (ap <= mid) bucket = rel;
    else {
        double lp = ceil(log((double)ap / (double)mid) / log(511.0 / 128.0) * (mid - 1)) + mid;
        int sgn = (rel > 0) - (rel < 0);
        bucket = (int)lp * sgn;
    }
    int c = bucket + 256; c = c < 0 ? 0 : (c > 511 ? 511 : c);
    tab[x] = c;
}

// ---------------- shared dense tf32 GEMM body (proven R4), 128x128 tile ----------------
#define GEMM_SMEM (2 * (128 * 20 + 16 * 136) * 4)

__device__ __forceinline__ void gemm128_core(
    const float* __restrict__ A, const float* __restrict__ Bm,
    const float* __restrict__ bias, float* __restrict__ C,
    int m0, int n0, int N, int K, int kStart, int kLen, int act, int useBias)
{
    extern __shared__ unsigned dsm[];
    unsigned* Asm = dsm;
    unsigned* Bsm = dsm + 2 * 2560;

    int tid = threadIdx.x;
    int w = tid >> 5, lane = tid & 31;
    int lr = lane >> 2, lc = lane & 3;
    int wm = (w >> 2) * 64, wn = (w & 3) * 32;

    int arow = tid >> 2, acol = (tid & 3) * 4;
    int brow = tid >> 5, bcol = (tid & 31) * 4;

    const float* aptr  = A + (size_t)(m0 + arow) * K + kStart + acol;
    const float* aptr2 = aptr + (size_t)64 * K;
    const float* bptr  = Bm + (size_t)(kStart + brow) * N + n0 + bcol;
    const float* bptr2 = bptr + (size_t)8 * N;
    const size_t bstep = (size_t)16 * N;

    const int kTiles = kLen >> 4;

    float4 ra0 = *(const float4*)aptr;
    float4 ra1 = *(const float4*)aptr2;
    float4 rb0 = *(const float4*)bptr;
    float4 rb1 = *(const float4*)bptr2;

    float acc[4][4][4] = {};

    for (int kt = 0; kt < kTiles; kt++) {
        unsigned* as = Asm + (kt & 1) * 2560;
        unsigned* bs = Bsm + (kt & 1) * 2176;
        *(uint4*)(as + arow * 20 + acol)        = f2tf4(ra0);
        *(uint4*)(as + (arow + 64) * 20 + acol) = f2tf4(ra1);
        *(uint4*)(bs + brow * 136 + bcol)       = f2tf4(rb0);
        *(uint4*)(bs + (brow + 8) * 136 + bcol) = f2tf4(rb1);
        __syncthreads();

        if (kt + 1 < kTiles) {
            aptr += 16; aptr2 += 16; bptr += bstep; bptr2 += bstep;
            ra0 = *(const float4*)aptr;
            ra1 = *(const float4*)aptr2;
            rb0 = *(const float4*)bptr;
            rb1 = *(const float4*)bptr2;
        }

        #pragma unroll
        for (int ks = 0; ks < 16; ks += 8) {
            unsigned af[4][4], bf[4][2];
            #pragma unroll
            for (int mt = 0; mt < 4; mt++) {
                int m = wm + mt * 16 + lr;
                af[mt][0] = as[m * 20 + ks + lc];
                af[mt][1] = as[(m + 8) * 20 + ks + lc];
                af[mt][2] = as[m * 20 + ks + lc + 4];
                af[mt][3] = as[(m + 8) * 20 + ks + lc + 4];
            }
            #pragma unroll
            for (int nt = 0; nt < 4; nt++) {
                int n = wn + nt * 8 + lr;
                bf[nt][0] = bs[(ks + lc) * 136 + n];
                bf[nt][1] = bs[(ks + lc + 4) * 136 + n];
            }
            #pragma unroll
            for (int mt = 0; mt < 4; mt++)
                #pragma unroll
                for (int nt = 0; nt < 4; nt++)
                    mma_tf32(acc[mt][nt], af[mt], bf[nt]);
        }
    }

    #pragma unroll
    for (int mt = 0; mt < 4; mt++) {
        int r = m0 + wm + mt * 16 + lr;
        #pragma unroll
        for (int nt = 0; nt < 4; nt++) {
            int c = n0 + wn + nt * 8 + lc * 2;
            float bv0 = useBias ? bias[c] : 0.f, bv1 = useBias ? bias[c + 1] : 0.f;
            float v00 = acc[mt][nt][0] + bv0, v01 = acc[mt][nt][1] + bv1;
            float v10 = acc[mt][nt][2] + bv0, v11 = acc[mt][nt][3] + bv1;
            if (act) {
                v00 = 0.5f * v00 * (1.0f + erff(v00 * 0.70710678118654752f));
                v01 = 0.5f * v01 * (1.0f + erff(v01 * 0.70710678118654752f));
                v10 = 0.5f * v10 * (1.0f + erff(v10 * 0.70710678118654752f));
                v11 = 0.5f * v11 * (1.0f + erff(v11 * 0.70710678118654752f));
            }
            *(float2*)(C + (size_t)r * N + c)       = make_float2(v00, v01);
            *(float2*)(C + (size_t)(r + 8) * N + c) = make_float2(v10, v11);
        }
    }
}

// QKV projections (z = 0/1/2), 288 CTAs = 1 wave
__global__ void __launch_bounds__(256) gemm_qkv(
    const float* __restrict__ hbuf,
    const float* __restrict__ Wq, const float* __restrict__ Wk, const float* __restrict__ Wv,
    const float* __restrict__ bq, const float* __restrict__ bk, const float* __restrict__ bv,
    float* __restrict__ q, float* __restrict__ k, float* __restrict__ v)
{
    const int z = blockIdx.z;
    const float* Bm   = (z == 0) ? Wq : (z == 1) ? Wk : Wv;
    const float* bias = (z == 0) ? bq : (z == 1) ? bk : bv;
    float*       C    = (z == 0) ? q  : (z == 1) ? k  : v;
    gemm128_core(hbuf, Bm, bias, C, blockIdx.y * 128, blockIdx.x * 128, DD, DD, 0, DD, 0, 1);
}

// ALL-layer positional projections upfront: z = 0..23 (layer = z>>1; odd = posq, even = posk)
__global__ void __launch_bounds__(256) gemm_pos(
    const float* __restrict__ rel,
    const float* __restrict__ Wq, const float* __restrict__ Wk,
    const float* __restrict__ bq, const float* __restrict__ bk,
    float* __restrict__ posqL, float* __restrict__ poskL)
{
    const int z = blockIdx.z;
    const int l = z >> 1;
    const int isq = z & 1;
    const float* Bm   = (isq ? Wq : Wk) + (size_t)l * DD * DD;
    const float* bias = (isq ? bq : bk) + (size_t)l * DD;
    float*       C    = (isq ? posqL : poskL) + (size_t)l * PP * DD;
    gemm128_core(rel, Bm, bias, C, blockIdx.y * 128, blockIdx.x * 128, DD, DD, 0, DD, 0, 1);
}

// single dense GEMM (FF1)
__global__ void __launch_bounds__(256) gemm_one(
    const float* __restrict__ A, const float* __restrict__ Bm, const float* __restrict__ bias,
    float* __restrict__ C, int N, int K, int act)
{
    gemm128_core(A, Bm, bias, C, blockIdx.y * 128, blockIdx.x * 128, N, K, 0, K, act, 1);
}

// split-K=2 dense GEMM (deterministic)
__global__ void __launch_bounds__(256) gemm_sk(
    const float* __restrict__ A, const float* __restrict__ Bm, const float* __restrict__ bias,
    float* __restrict__ C0, float* __restrict__ C1, int N, int K)
{
    const int z = blockIdx.z;
    gemm128_core(A, Bm, bias, z ? C1 : C0, blockIdx.y * 128, blockIdx.x * 128,
                 N, K, z * (K >> 1), K >> 1, 0, z == 0);
}

// ---------------- fused disentangled score kernel (proven) ----------------
__global__ void __launch_bounds__(256) score_fused(
    const float* __restrict__ Q, const float* __restrict__ Kt,
    const float* __restrict__ PKg, const float* __restrict__ PQg,
    const int* __restrict__ tab, const float* __restrict__ mask,
    float* __restrict__ scores, float scale)
{
    int z = blockIdx.z; int b = z / HH, hh = z % HH;
    int m0 = blockIdx.y * 64, n0 = blockIdx.x * 64;
    const float* Aq = Q  + (size_t)b * SS * DD + hh * DH;
    const float* Ak = Kt + (size_t)b * SS * DD + hh * DH;
    const float* PK = PKg + hh * DH;
    const float* PQ = PQg + hh * DH;

    extern __shared__ unsigned ssm[];
    unsigned* Qs  = ssm;
    unsigned* Ks  = ssm + 4352;
    unsigned* PKs = ssm + 8704;
    unsigned* PQs = ssm + 17408;
    float* C1s = (float*)(ssm + 8704);
    float* C2s = (float*)(ssm + 17152);

    int tid = threadIdx.x;
    int w = tid >> 5, lane = tid & 31;
    int lr = lane >> 2, lc = lane & 3;
    int wr = w >> 2, wc = w & 3;
    const int dlo = m0 - n0 - 63;

    {
        int row = tid >> 2;
        int col = (tid & 3) * 16;
        #pragma unroll
        for (int c4 = 0; c4 < 4; c4++) {
            float4 v = *(const float4*)(Aq + (size_t)(m0 + row) * DD + col + c4 * 4);
            *(uint4*)(Qs + row * 68 + col + c4 * 4) = f2tf4(v);
        }
        #pragma unroll
        for (int c4 = 0; c4 < 4; c4++) {
            float4 v = *(const float4*)(Ak + (size_t)(n0 + row) * DD + col + c4 * 4);
            *(uint4*)(Ks + row * 68 + col + c4 * 4) = f2tf4(v);
        }
        #pragma unroll
        for (int half = 0; half < 2; half++) {
            int t = row + half * 64;
            int tt = t < 127 ? t : 126;
            int pidx = tab[dlo + tt + 511];
            #pragma unroll
            for (int c4 = 0; c4 < 4; c4++) {
                float4 vk = *(const float4*)(PK + (size_t)pidx * DD + col + c4 * 4);
                *(uint4*)(PKs + t * 68 + col + c4 * 4) = f2tf4(vk);
                float4 vq = *(const float4*)(PQ + (size_t)pidx * DD + col + c4 * 4);
                *(uint4*)(PQs + t * 68 + col + c4 * 4) = f2tf4(vq);
            }
        }
    }
    __syncthreads();

    float accS[2][2][4] = {};
    float acc1[2][4][4] = {};
    float acc2[2][4][4] = {};

    #pragma unroll
    for (int ks = 0; ks < DH; ks += 8) {
        unsigned aq[2][4], ak[2][4];
        #pragma unroll
        for (int mt = 0; mt < 2; mt++) {
            int m = wr * 32 + mt * 16 + lr;
            aq[mt][0] = Qs[m * 68 + ks + lc];       aq[mt][1] = Qs[(m + 8) * 68 + ks + lc];
            aq[mt][2] = Qs[m * 68 + ks + lc + 4];   aq[mt][3] = Qs[(m + 8) * 68 + ks + lc + 4];
            ak[mt][0] = Ks[m * 68 + ks + lc];       ak[mt][1] = Ks[(m + 8) * 68 + ks + lc];
            ak[mt][2] = Ks[m * 68 + ks + lc + 4];   ak[mt][3] = Ks[(m + 8) * 68 + ks + lc + 4];
        }
        unsigned bS[2][2], b1[4][2], b2[4][2];
        #pragma unroll
        for (int nt = 0; nt < 2; nt++) {
            int n = wc * 16 + nt * 8 + lr;
            bS[nt][0] = Ks[n * 68 + ks + lc];
            bS[nt][1] = Ks[n * 68 + ks + lc + 4];
        }
        #pragma unroll
        for (int nt = 0; nt < 4; nt++) {
            int n = wc * 32 + nt * 8 + lr;
            b1[nt][0] = PKs[n * 68 + ks + lc];
            b1[nt][1] = PKs[n * 68 + ks + lc + 4];
            b2[nt][0] = PQs[n * 68 + ks + lc];
            b2[nt][1] = PQs[n * 68 + ks + lc + 4];
        }
        #pragma unroll
        for (int mt = 0; mt < 2; mt++) {
            #pragma unroll
            for (int nt = 0; nt < 2; nt++) mma_tf32(accS[mt][nt], aq[mt], bS[nt]);
            #pragma unroll
            for (int nt = 0; nt < 4; nt++) { mma_tf32(acc1[mt][nt], aq[mt], b1[nt]); mma_tf32(acc2[mt][nt], ak[mt], b2[nt]); }
        }
    }
    __syncthreads();

    #pragma unroll
    for (int mt = 0; mt < 2; mt++) {
        int r = wr * 32 + mt * 16 + lr;
        #pragma unroll
        for (int nt = 0; nt < 4; nt++) {
            int c = wc * 32 + nt * 8 + lc * 2;
            C1s[r * 132 + c] = acc1[mt][nt][0]; C1s[r * 132 + c + 1] = acc1[mt][nt][1];
            C1s[(r + 8) * 132 + c] = acc1[mt][nt][2]; C1s[(r + 8) * 132 + c + 1] = acc1[mt][nt][3];
            C2s[r * 132 + c] = acc2[mt][nt][0]; C2s[r * 132 + c + 1] = acc2[mt][nt][1];
            C2s[(r + 8) * 132 + c] = acc2[mt][nt][2]; C2s[(r + 8) * 132 + c + 1] = acc2[mt][nt][3];
        }
    }
    __syncthreads();

    #pragma unroll
    for (int mt = 0; mt < 2; mt++) {
        #pragma unroll
        for (int nt = 0; nt < 2; nt++) {
            int r = wr * 32 + mt * 16 + lr;
            int c0 = wc * 16 + nt * 8 + lc * 2;
            #pragma unroll
            for (int half = 0; half < 2; half++) {
                int rr = r + half * 8;
                float o[2];
                #pragma unroll
                for (int e = 0; e < 2; e++) {
                    int cc = c0 + e;
                    int t = rr - cc + 63;
                    float val = (accS[mt][nt][half * 2 + e] + C1s[rr * 132 + t] + C2s[cc * 132 + t]) * scale;
                    val += (1.0f - mask[b * SS + n0 + cc]) * (-1e9f);
                    o[e] = val;
                }
                *(float2*)(scores + ((size_t)z * SS + m0 + rr) * SS + n0 + c0) = make_float2(o[0], o[1]);
            }
        }
    }
}

// ---------------- row softmax (proven R4) ----------------
__global__ void __launch_bounds__(128) softmax_kernel(float* __restrict__ scores)
{
    int q = blockIdx.x, z = blockIdx.y;
    int t = threadIdx.x;
    int lane = t & 31, wp = t >> 5;
    float4* row = (float4*)(scores + ((size_t)z * SS + q) * SS);

    float4 v = row[t];
    float mx = fmaxf(fmaxf(v.x, v.y), fmaxf(v.z, v.w));
    #pragma unroll
    for (int o = 16; o > 0; o >>= 1) mx = fmaxf(mx, __shfl_xor_sync(0xffffffffu, mx, o));
    __shared__ float sm[4];
    if (lane == 0) sm[wp] = mx;
    __syncthreads();
    mx = fmaxf(fmaxf(sm[0], sm[1]), fmaxf(sm[2], sm[3]));

    float4 e = make_float4(expf(v.x - mx), expf(v.y - mx), expf(v.z - mx), expf(v.w - mx));
    float s = e.x + e.y + e.z + e.w;
    #pragma unroll
    for (int o = 16; o > 0; o >>= 1) s += __shfl_xor_sync(0xffffffffu, s, o);
    __shared__ float sm2[4];
    if (lane == 0) sm2[wp] = s;
    __syncthreads();
    float inv = 1.0f / (sm2[0] + sm2[1] + sm2[2] + sm2[3]);
    row[t] = make_float4(e.x * inv, e.y * inv, e.z * inv, e.w * inv);
}

// ---------------- batched ctx GEMM (proven R4) ----------------
__global__ void __launch_bounds__(256) ctx_tf32(
    const float* __restrict__ Pm, const float* __restrict__ V, float* __restrict__ O)
{
    int z = blockIdx.y; int b = z / HH, hh = z % HH;
    int m0 = blockIdx.x * 128;
    const float* A = Pm + (size_t)z * SS * SS;
    const float* Bv = V + (size_t)b * SS * DD + hh * DH;

    extern __shared__ unsigned dsm[];
    unsigned* Asm = dsm;
    unsigned* Bsm = dsm + 2 * 2560;

    int tid = threadIdx.x;
    int w = tid >> 5, lane = tid & 31;
    int lr = lane >> 2, lc = lane & 3;
    int wm = (w >> 1) * 32, wn = (w & 1) * 32;

    int arow = tid & 127, acol = (tid >> 7) * 8;
    int brow = tid >> 4, bcol = (tid & 15) * 4;

    const float* aptr = A + (size_t)(m0 + arow) * SS + acol;
    const float* bptr = Bv + (size_t)brow * DD + bcol;
    const size_t bstep = (size_t)16 * DD;

    const int kTiles = SS / 16;

    float4 ra0 = *(const float4*)aptr;
    float4 ra1 = *(const float4*)(aptr + 4);
    float4 rb0 = *(const float4*)bptr;

    float acc[2][4][4] = {};

    for (int kt = 0; kt < kTiles; kt++) {
        unsigned* as = Asm + (kt & 1) * 2560;
        unsigned* bs = Bsm + (kt & 1) * 1152;
        *(uint4*)(as + arow * 20 + acol)     = f2tf4(ra0);
        *(uint4*)(as + arow * 20 + acol + 4) = f2tf4(ra1);
        *(uint4*)(bs + brow * 72 + bcol)     = f2tf4(rb0);
        __syncthreads();

        if (kt + 1 < kTiles) {
            aptr += 16; bptr += bstep;
            ra0 = *(const float4*)aptr;
            ra1 = *(const float4*)(aptr + 4);
            rb0 = *(const float4*)bptr;
        }

        #pragma unroll
        for (int ks = 0; ks < 16; ks += 8) {
            unsigned af[2][4], bf[4][2];
            #pragma unroll
            for (int mt = 0; mt < 2; mt++) {
                int m = wm + mt * 16 + lr;
                af[mt][0] = as[m * 20 + ks + lc];
                af[mt][1] = as[(m + 8) * 20 + ks + lc];
                af[mt][2] = as[m * 20 + ks + lc + 4];
                af[mt][3] = as[(m + 8) * 20 + ks + lc + 4];
            }
            #pragma unroll
            for (int nt = 0; nt < 4; nt++) {
                int n = wn + nt * 8 + lr;
                bf[nt][0] = bs[(ks + lc) * 72 + n];
                bf[nt][1] = bs[(ks + lc + 4) * 72 + n];
            }
            #pragma unroll
            for (int mt = 0; mt < 2; mt++)
                #pragma unroll
                for (int nt = 0; nt < 4; nt++)
                    mma_tf32(acc[mt][nt], af[mt], bf[nt]);
        }
    }

    #pragma unroll
    for (int mt = 0; mt < 2; mt++) {
        int r = m0 + wm + mt * 16 + lr;
        #pragma unroll
        for (int nt = 0; nt < 4; nt++) {
            int c = wn + nt * 8 + lc * 2;
            *(float2*)(O + ((size_t)b * SS + r) * DD + hh * DH + c)     = make_float2(acc[mt][nt][0], acc[mt][nt][1]);
            *(float2*)(O + ((size_t)b * SS + r + 8) * DD + hh * DH + c) = make_float2(acc[mt][nt][2], acc[mt][nt][3]);
        }
    }
}

// ---------------- residual add (two deltas) + LN ----------------
__global__ void __launch_bounds__(256) add_ln3_kernel(
    float* __restrict__ h, const float* __restrict__ d1, const float* __restrict__ d2,
    const float* __restrict__ w, const float* __restrict__ b)
{
    int t = blockIdx.x, tid = threadIdx.x;
    __shared__ float xs[DD];
    __shared__ float red[256];
    float* hr = h + (size_t)t * DD;
    const float* r1 = d1 + (size_t)t * DD;
    const float* r2 = d2 + (size_t)t * DD;

    float s = 0.f;
    for (int d = tid; d < DD; d += 256) { float x = hr[d] + r1[d] + r2[d]; xs[d] = x; s += x; }
    red[tid] = s; __syncthreads();
    for (int st = 128; st > 0; st >>= 1) { if (tid < st) red[tid] += red[tid + st]; __syncthreads(); }
    float mu = red[0] * (1.0f / DD); __syncthreads();
    float s2 = 0.f;
    for (int d = tid; d < DD; d += 256) { float dv = xs[d] - mu; s2 += dv * dv; }
    red[tid] = s2; __syncthreads();
    for (int st = 128; st > 0; st >>= 1) { if (tid < st) red[tid] += red[tid + st]; __syncthreads(); }
    float inv = rsqrtf(red[0] * (1.0f / DD) + 1e-12f);
    for (int d = tid; d < DD; d += 256) hr[d] = (xs[d] - mu) * inv * w[d] + b[d];
}

// ---------------- host orchestration ----------------
extern "C" void kernel_launch(void* const* d_in, const int* in_sizes, int n_in,
                              void* d_out, int out_size)
{
    const int*   input_ids   = (const int*)  d_in[0];
    const int*   segment_ids = (const int*)  d_in[1];
    const int*   pinyin_ids  = (const int*)  d_in[2];
    const float* attn_mask   = (const float*)d_in[3];
    const float* tok_emb     = (const float*)d_in[4];
    const float* pin_emb     = (const float*)d_in[5];
    const float* seg_emb     = (const float*)d_in[6];
    const float* emb_ln_w    = (const float*)d_in[7];
    const float* emb_ln_b    = (const float*)d_in[8];
    const float* rel_emb     = (const float*)d_in[9];
    const float* Wq = (const float*)d_in[10]; const float* bq = (const float*)d_in[11];
    const float* Wk = (const float*)d_in[12]; const float* bk = (const float*)d_in[13];
    const float* Wv = (const float*)d_in[14]; const float* bv = (const float*)d_in[15];
    const float* Wo = (const float*)d_in[16]; const float* bo = (const float*)d_in[17];
    const float* ln1w = (const float*)d_in[18]; const float* ln1b = (const float*)d_in[19];
    const float* W1 = (const float*)d_in[20]; const float* b1 = (const float*)d_in[21];
    const float* W2 = (const float*)d_in[22]; const float* b2 = (const float*)d_in[23];
    const float* ln2w = (const float*)d_in[24]; const float* ln2b = (const float*)d_in[25];

    float *h, *q, *k, *v, *ctx, *tmp, *poskL, *posqL, *scores;
    int *tab;
    cudaGetSymbolAddress((void**)&h,      g_h);
    cudaGetSymbolAddress((void**)&q,      g_q);
    cudaGetSymbolAddress((void**)&k,      g_k);
    cudaGetSymbolAddress((void**)&v,      g_v);
    cudaGetSymbolAddress((void**)&ctx,    g_ctx);
    cudaGetSymbolAddress((void**)&tmp,    g_tmp);
    cudaGetSymbolAddress((void**)&poskL,  g_poskL);
    cudaGetSymbolAddress((void**)&posqL,  g_posqL);
    cudaGetSymbolAddress((void**)&scores, g_scores);
    cudaGetSymbolAddress((void**)&tab,    g_tab);

    const int CTX_SMEM   = 2 * (128 * 20 + 16 * 72) * 4;
    const int SCORE_SMEM = (4352 * 2 + 8704 * 2) * 4;
    cudaFuncSetAttribute(gemm_qkv,    cudaFuncAttributeMaxDynamicSharedMemorySize, GEMM_SMEM);
    cudaFuncSetAttribute(gemm_pos,    cudaFuncAttributeMaxDynamicSharedMemorySize, GEMM_SMEM);
    cudaFuncSetAttribute(gemm_one,    cudaFuncAttributeMaxDynamicSharedMemorySize, GEMM_SMEM);
    cudaFuncSetAttribute(gemm_sk,     cudaFuncAttributeMaxDynamicSharedMemorySize, GEMM_SMEM);
    cudaFuncSetAttribute(ctx_tf32,    cudaFuncAttributeMaxDynamicSharedMemorySize, CTX_SMEM);
    cudaFuncSetAttribute(score_fused, cudaFuncAttributeMaxDynamicSharedMemorySize, SCORE_SMEM);

    const float scale = 0.07216878364870323f;  // 1/sqrt(3*DH)

    embed_ln_kernel<<<MM, 256>>>(input_ids, segment_ids, pinyin_ids, attn_mask,
                                 tok_emb, pin_emb, seg_emb, emb_ln_w, emb_ln_b, h);
    buckets_kernel<<<4, 256>>>(tab);

    // ALL positional projections for all 12 layers, one launch (576 CTAs)
    gemm_pos<<<dim3(DD / 128, PP / 128, 2 * LL), 256, GEMM_SMEM>>>(
        rel_emb, Wq, Wk, bq, bk, posqL, poskL);

    for (int i = 0; i < LL; i++) {
        const float* Wq_i = Wq + (size_t)i * DD * DD; const float* bq_i = bq + (size_t)i * DD;
        const float* Wk_i = Wk + (size_t)i * DD * DD; const float* bk_i = bk + (size_t)i * DD;
        const float* Wv_i = Wv + (size_t)i * DD * DD; const float* bv_i = bv + (size_t)i * DD;
        const float* Wo_i = Wo + (size_t)i * DD * DD; const float* bo_i = bo + (size_t)i * DD;
        const float* W1_i = W1 + (size_t)i * DD * FF; const float* b1_i = b1 + (size_t)i * FF;
        const float* W2_i = W2 + (size_t)i * FF * DD; const float* b2_i = b2 + (size_t)i * DD;
        const float* posk_i = poskL + (size_t)i * PP * DD;
        const float* posq_i = posqL + (size_t)i * PP * DD;

        // QKV only (288 CTAs = 1 wave)
        gemm_qkv<<<dim3(DD / 128, MM / 128, 3), 256, GEMM_SMEM>>>(
            h, Wq_i, Wk_i, Wv_i, bq_i, bk_i, bv_i, q, k, v);

        // fused disentangled scores + softmax + probs@V
        score_fused<<<dim3(8, 8, BH), 256, SCORE_SMEM>>>(
            q, k, posk_i, posq_i, tab, attn_mask, scores, scale);
        softmax_kernel<<<dim3(SS, BH), 128>>>(scores);
        ctx_tf32<<<dim3(SS / 128, BH), 256, CTX_SMEM>>>(scores, v, ctx);

        // output projection (split-K=2 -> tmp, q) + residual LN
        gemm_sk<<<dim3(DD / 128, MM / 128, 2), 256, GEMM_SMEM>>>(
            ctx, Wo_i, bo_i, tmp, q, DD, DD);
        add_ln3_kernel<<<MM, 256>>>(h, tmp, q, ln1w + (size_t)i * DD, ln1b + (size_t)i * DD);

        // feed-forward: FF1 full, FF2 split-K=2 (-> ctx, k)
        gemm_one<<<dim3(FF / 128, MM / 128), 256, GEMM_SMEM>>>(h, W1_i, b1_i, tmp, FF, DD, 1);
        gemm_sk<<<dim3(DD / 128, MM / 128, 2), 256, GEMM_SMEM>>>(
            tmp, W2_i, b2_i, ctx, k, DD, FF);
        add_ln3_kernel<<<MM, 256>>>(h, ctx, k, ln2w + (size_t)i * DD, ln2b + (size_t)i * DD);
    }

    cudaMemcpyAsync(d_out, h, sizeof(float) * (size_t)out_size, cudaMemcpyDeviceToDevice);
}

// round 12
// speedup vs baseline: 1.3414x; 1.2674x over previous
#include <cuda_runtime.h>
#include <cuda_bf16.h>
#include <cuda_fp16.h>
#include <math.h>

#define BB 4
#define SS 512
#define DD 768
#define HH 12
#define LL 12
#define FF 3072
#define DH 64
#define PP 512
#define BH (BB*HH)
#define MM (BB*SS)

__device__ __align__(256) float g_h   [MM*DD];
__device__ __align__(256) float g_q   [MM*DD];
__device__ __align__(256) float g_k   [MM*DD];
__device__ __align__(256) float g_v   [MM*DD];
__device__ __align__(256) float g_ctx [MM*DD];
__device__ __align__(256) float g_tmp [MM*FF];
__device__ __align__(256) float g_poskL[(size_t)LL*PP*DD];
__device__ __align__(256) float g_posqL[(size_t)LL*PP*DD];
__device__ __align__(256) float g_scores[(size_t)BH*SS*SS];
__device__ int g_tab[1024];

__device__ __forceinline__ unsigned f2tf(float x) {
    unsigned u; asm("cvt.rna.tf32.f32 %0, %1;" : "=r"(u) : "f"(x)); return u;
}
__device__ __forceinline__ uint4 f2tf4(float4 v) {
    return make_uint4(f2tf(v.x), f2tf(v.y), f2tf(v.z), f2tf(v.w));
}
__device__ __forceinline__ void mma_tf32(float* d, const unsigned* a, const unsigned* b) {
    asm volatile(
        "mma.sync.aligned.m16n8k8.row.col.f32.tf32.tf32.f32 "
        "{%0,%1,%2,%3}, {%4,%5,%6,%7}, {%8,%9}, {%0,%1,%2,%3};\n"
        : "+f"(d[0]), "+f"(d[1]), "+f"(d[2]), "+f"(d[3])
        : "r"(a[0]), "r"(a[1]), "r"(a[2]), "r"(a[3]), "r"(b[0]), "r"(b[1]));
}
__device__ __forceinline__ unsigned pack2(float lo, float hi) {
    __half2 h = __floats2half2_rn(lo, hi);
    return *reinterpret_cast<unsigned*>(&h);
}
__device__ __forceinline__ void mma_f16(float* d, const unsigned* a, const unsigned* b) {
    asm volatile(
        "mma.sync.aligned.m16n8k16.row.col.f32.f16.f16.f32 "
        "{%0,%1,%2,%3}, {%4,%5,%6,%7}, {%8,%9}, {%0,%1,%2,%3};\n"
        : "+f"(d[0]), "+f"(d[1]), "+f"(d[2]), "+f"(d[3])
        : "r"(a[0]), "r"(a[1]), "r"(a[2]), "r"(a[3]), "r"(b[0]), "r"(b[1]));
}

// ---------------- embeddings + LN + mask ----------------
__global__ void __launch_bounds__(256) embed_ln_kernel(
    const int* __restrict__ ids, const int* __restrict__ segs, const int* __restrict__ pins,
    const float* __restrict__ mask,
    const float* __restrict__ tok, const float* __restrict__ pin, const float* __restrict__ seg,
    const float* __restrict__ w, const float* __restrict__ b, float* __restrict__ out)
{
    int t = blockIdx.x, tid = threadIdx.x;
    __shared__ float xs[DD];
    __shared__ float red[256];
    size_t io = (size_t)ids[t] * DD, po = (size_t)pins[t] * DD, so = (size_t)segs[t] * DD;
    float s = 0.f;
    for (int d = tid; d < DD; d += 256) {
        float x = tok[io + d] + pin[po + d] + seg[so + d];
        xs[d] = x; s += x;
    }
    red[tid] = s; __syncthreads();
    for (int st = 128; st > 0; st >>= 1) { if (tid < st) red[tid] += red[tid + st]; __syncthreads(); }
    float mu = red[0] * (1.0f / DD); __syncthreads();
    float s2 = 0.f;
    for (int d = tid; d < DD; d += 256) { float dv = xs[d] - mu; s2 += dv * dv; }
    red[tid] = s2; __syncthreads();
    for (int st = 128; st > 0; st >>= 1) { if (tid < st) red[tid] += red[tid + st]; __syncthreads(); }
    float inv = rsqrtf(red[0] * (1.0f / DD) + 1e-12f);
    float m = mask[t];
    for (int d = tid; d < DD; d += 256)
        out[(size_t)t * DD + d] = ((xs[d] - mu) * inv * w[d] + b[d]) * m;
}

// ---------------- bucket table ----------------
__global__ void buckets_kernel(int* __restrict__ tab)
{
    int x = blockIdx.x * blockDim.x + threadIdx.x;
    if (x >= 1023) { if (x == 1023) tab[1023] = 0; return; }
    int rel = x - 511;
    const int mid = 128;
    int ap = (rel < mid && rel > -mid) ? (mid - 1) : (rel < 0 ? -rel : rel);
    int bucket;
    if (ap <= mid) bucket = rel;
    else {
        double lp = ceil(log((double)ap / (double)mid) / log(511.0 / 128.0) * (mid - 1)) + mid;
        int sgn = (rel > 0) - (rel < 0);
        bucket = (int)lp * sgn;
    }
    int c = bucket + 256; c = c < 0 ? 0 : (c > 511 ? 511 : c);
    tab[x] = c;
}

// ---------------- dense fp16 GEMM body, 128x128 tile, BK=16, reg-staged dbl buffer ----------------
// Per 16-k tile: one m16n8k16 step = 24 frag LDS + 16 MMA per warp (half of tf32-k8).
#define A_STR 12
#define B_STR 136
#define A_STG (128*A_STR)   // 1536 u32 per stage
#define B_STG (8*B_STR)     // 1088 u32 per stage
#define GEMM_SMEM ((A_STG + B_STG) * 2 * 4)

__device__ __forceinline__ void gemm128_core(
    const float* __restrict__ A, const float* __restrict__ Bm,
    const float* __restrict__ bias, float* __restrict__ C,
    int m0, int n0, int N, int K, int kStart, int kLen, int act, int useBias)
{
    extern __shared__ unsigned dsm[];
    unsigned* Asm = dsm;
    unsigned* Bsm = dsm + 2 * A_STG;

    int tid = threadIdx.x;
    int w = tid >> 5, lane = tid & 31;
    int lr = lane >> 2, lc = lane & 3;
    int wm = (w >> 2) * 64, wn = (w & 3) * 32;

    int arow = tid >> 2, acolf = (tid & 3) * 4;     // A rows arow, arow+64; 4 floats each
    int brow2 = tid >> 5, bcolf = (tid & 31) * 4;   // B k-pair row brow2 (k=2*brow2, 2*brow2+1)

    const float* aptr  = A + (size_t)(m0 + arow) * K + kStart + acolf;
    const float* aptr2 = aptr + (size_t)64 * K;
    const float* bptr0 = Bm + (size_t)(kStart + 2 * brow2) * N + n0 + bcolf;
    const float* bptr1 = bptr0 + N;
    const size_t bstep = (size_t)16 * N;

    const int kTiles = kLen >> 4;

    float4 ra0 = *(const float4*)aptr;
    float4 ra1 = *(const float4*)aptr2;
    float4 rb0 = *(const float4*)bptr0;
    float4 rb1 = *(const float4*)bptr1;

    float acc[4][4][4] = {};

    for (int kt = 0; kt < kTiles; kt++) {
        unsigned* as = Asm + (kt & 1) * A_STG;
        unsigned* bs = Bsm + (kt & 1) * B_STG;
        *(uint2*)(as + arow * A_STR + (tid & 3) * 2) =
            make_uint2(pack2(ra0.x, ra0.y), pack2(ra0.z, ra0.w));
        *(uint2*)(as + (arow + 64) * A_STR + (tid & 3) * 2) =
            make_uint2(pack2(ra1.x, ra1.y), pack2(ra1.z, ra1.w));
        *(uint4*)(bs + brow2 * B_STR + bcolf) =
            make_uint4(pack2(rb0.x, rb1.x), pack2(rb0.y, rb1.y),
                       pack2(rb0.z, rb1.z), pack2(rb0.w, rb1.w));
        __syncthreads();

        if (kt + 1 < kTiles) {
            aptr += 16; aptr2 += 16; bptr0 += bstep; bptr1 += bstep;
            ra0 = *(const float4*)aptr;
            ra1 = *(const float4*)aptr2;
            rb0 = *(const float4*)bptr0;
            rb1 = *(const float4*)bptr1;
        }

        unsigned af[4][4], bf[4][2];
        #pragma unroll
        for (int mt = 0; mt < 4; mt++) {
            int m = wm + mt * 16 + lr;
            af[mt][0] = as[m * A_STR + lc];
            af[mt][1] = as[(m + 8) * A_STR + lc];
            af[mt][2] = as[m * A_STR + lc + 4];
            af[mt][3] = as[(m + 8) * A_STR + lc + 4];
        }
        #pragma unroll
        for (int nt = 0; nt < 4; nt++) {
            int n = wn + nt * 8 + lr;
            bf[nt][0] = bs[lc * B_STR + n];
            bf[nt][1] = bs[(lc + 4) * B_STR + n];
        }
        #pragma unroll
        for (int mt = 0; mt < 4; mt++)
            #pragma unroll
            for (int nt = 0; nt < 4; nt++)
                mma_f16(acc[mt][nt], af[mt], bf[nt]);
    }

    #pragma unroll
    for (int mt = 0; mt < 4; mt++) {
        int r = m0 + wm + mt * 16 + lr;
        #pragma unroll
        for (int nt = 0; nt < 4; nt++) {
            int c = n0 + wn + nt * 8 + lc * 2;
            float bv0 = useBias ? bias[c] : 0.f, bv1 = useBias ? bias[c + 1] : 0.f;
            float v00 = acc[mt][nt][0] + bv0, v01 = acc[mt][nt][1] + bv1;
            float v10 = acc[mt][nt][2] + bv0, v11 = acc[mt][nt][3] + bv1;
            if (act) {
                v00 = 0.5f * v00 * (1.0f + erff(v00 * 0.70710678118654752f));
                v01 = 0.5f * v01 * (1.0f + erff(v01 * 0.70710678118654752f));
                v10 = 0.5f * v10 * (1.0f + erff(v10 * 0.70710678118654752f));
                v11 = 0.5f * v11 * (1.0f + erff(v11 * 0.70710678118654752f));
            }
            *(float2*)(C + (size_t)r * N + c)       = make_float2(v00, v01);
            *(float2*)(C + (size_t)(r + 8) * N + c) = make_float2(v10, v11);
        }
    }
}

// QKV projections (z = 0/1/2), 288 CTAs = 1 wave
__global__ void __launch_bounds__(256) gemm_qkv(
    const float* __restrict__ hbuf,
    const float* __restrict__ Wq, const float* __restrict__ Wk, const float* __restrict__ Wv,
    const float* __restrict__ bq, const float* __restrict__ bk, const float* __restrict__ bv,
    float* __restrict__ q, float* __restrict__ k, float* __restrict__ v)
{
    const int z = blockIdx.z;
    const float* Bm   = (z == 0) ? Wq : (z == 1) ? Wk : Wv;
    const float* bias = (z == 0) ? bq : (z == 1) ? bk : bv;
    float*       C    = (z == 0) ? q  : (z == 1) ? k  : v;
    gemm128_core(hbuf, Bm, bias, C, blockIdx.y * 128, blockIdx.x * 128, DD, DD, 0, DD, 0, 1);
}

// ALL-layer positional projections upfront
__global__ void __launch_bounds__(256) gemm_pos(
    const float* __restrict__ rel,
    const float* __restrict__ Wq, const float* __restrict__ Wk,
    const float* __restrict__ bq, const float* __restrict__ bk,
    float* __restrict__ posqL, float* __restrict__ poskL)
{
    const int z = blockIdx.z;
    const int l = z >> 1;
    const int isq = z & 1;
    const float* Bm   = (isq ? Wq : Wk) + (size_t)l * DD * DD;
    const float* bias = (isq ? bq : bk) + (size_t)l * DD;
    float*       C    = (isq ? posqL : poskL) + (size_t)l * PP * DD;
    gemm128_core(rel, Bm, bias, C, blockIdx.y * 128, blockIdx.x * 128, DD, DD, 0, DD, 0, 1);
}

__global__ void __launch_bounds__(256) gemm_one(
    const float* __restrict__ A, const float* __restrict__ Bm, const float* __restrict__ bias,
    float* __restrict__ C, int N, int K, int act)
{
    gemm128_core(A, Bm, bias, C, blockIdx.y * 128, blockIdx.x * 128, N, K, 0, K, act, 1);
}

__global__ void __launch_bounds__(256) gemm_sk(
    const float* __restrict__ A, const float* __restrict__ Bm, const float* __restrict__ bias,
    float* __restrict__ C0, float* __restrict__ C1, int N, int K)
{
    const int z = blockIdx.z;
    gemm128_core(A, Bm, bias, z ? C1 : C0, blockIdx.y * 128, blockIdx.x * 128,
                 N, K, z * (K >> 1), K >> 1, 0, z == 0);
}

// ---------------- fused disentangled score kernel (tf32, proven) ----------------
__global__ void __launch_bounds__(256) score_fused(
    const float* __restrict__ Q, const float* __restrict__ Kt,
    const float* __restrict__ PKg, const float* __restrict__ PQg,
    const int* __restrict__ tab, const float* __restrict__ mask,
    float* __restrict__ scores, float scale)
{
    int z = blockIdx.z; int b = z / HH, hh = z % HH;
    int m0 = blockIdx.y * 64, n0 = blockIdx.x * 64;
    const float* Aq = Q  + (size_t)b * SS * DD + hh * DH;
    const float* Ak = Kt + (size_t)b * SS * DD + hh * DH;
    const float* PK = PKg + hh * DH;
    const float* PQ = PQg + hh * DH;

    extern __shared__ unsigned ssm[];
    unsigned* Qs  = ssm;
    unsigned* Ks  = ssm + 4352;
    unsigned* PKs = ssm + 8704;
    unsigned* PQs = ssm + 17408;
    float* C1s = (float*)(ssm + 8704);
    float* C2s = (float*)(ssm + 17152);

    int tid = threadIdx.x;
    int w = tid >> 5, lane = tid & 31;
    int lr = lane >> 2, lc = lane & 3;
    int wr = w >> 2, wc = w & 3;
    const int dlo = m0 - n0 - 63;

    {
        int row = tid >> 2;
        int col = (tid & 3) * 16;
        #pragma unroll
        for (int c4 = 0; c4 < 4; c4++) {
            float4 v = *(const float4*)(Aq + (size_t)(m0 + row) * DD + col + c4 * 4);
            *(uint4*)(Qs + row * 68 + col + c4 * 4) = f2tf4(v);
        }
        #pragma unroll
        for (int c4 = 0; c4 < 4; c4++) {
            float4 v = *(const float4*)(Ak + (size_t)(n0 + row) * DD + col + c4 * 4);
            *(uint4*)(Ks + row * 68 + col + c4 * 4) = f2tf4(v);
        }
        #pragma unroll
        for (int half = 0; half < 2; half++) {
            int t = row + half * 64;
            int tt = t < 127 ? t : 126;
            int pidx = tab[dlo + tt + 511];
            #pragma unroll
            for (int c4 = 0; c4 < 4; c4++) {
                float4 vk = *(const float4*)(PK + (size_t)pidx * DD + col + c4 * 4);
                *(uint4*)(PKs + t * 68 + col + c4 * 4) = f2tf4(vk);
                float4 vq = *(const float4*)(PQ + (size_t)pidx * DD + col + c4 * 4);
                *(uint4*)(PQs + t * 68 + col + c4 * 4) = f2tf4(vq);
            }
        }
    }
    __syncthreads();

    float accS[2][2][4] = {};
    float acc1[2][4][4] = {};
    float acc2[2][4][4] = {};

    #pragma unroll
    for (int ks = 0; ks < DH; ks += 8) {
        unsigned aq[2][4], ak[2][4];
        #pragma unroll
        for (int mt = 0; mt < 2; mt++) {
            int m = wr * 32 + mt * 16 + lr;
            aq[mt][0] = Qs[m * 68 + ks + lc];       aq[mt][1] = Qs[(m + 8) * 68 + ks + lc];
            aq[mt][2] = Qs[m * 68 + ks + lc + 4];   aq[mt][3] = Qs[(m + 8) * 68 + ks + lc + 4];
            ak[mt][0] = Ks[m * 68 + ks + lc];       ak[mt][1] = Ks[(m + 8) * 68 + ks + lc];
            ak[mt][2] = Ks[m * 68 + ks + lc + 4];   ak[mt][3] = Ks[(m + 8) * 68 + ks + lc + 4];
        }
        unsigned bS[2][2], b1[4][2], b2[4][2];
        #pragma unroll
        for (int nt = 0; nt < 2; nt++) {
            int n = wc * 16 + nt * 8 + lr;
            bS[nt][0] = Ks[n * 68 + ks + lc];
            bS[nt][1] = Ks[n * 68 + ks + lc + 4];
        }
        #pragma unroll
        for (int nt = 0; nt < 4; nt++) {
            int n = wc * 32 + nt * 8 + lr;
            b1[nt][0] = PKs[n * 68 + ks + lc];
            b1[nt][1] = PKs[n * 68 + ks + lc + 4];
            b2[nt][0] = PQs[n * 68 + ks + lc];
            b2[nt][1] = PQs[n * 68 + ks + lc + 4];
        }
        #pragma unroll
        for (int mt = 0; mt < 2; mt++) {
            #pragma unroll
            for (int nt = 0; nt < 2; nt++) mma_tf32(accS[mt][nt], aq[mt], bS[nt]);
            #pragma unroll
            for (int nt = 0; nt < 4; nt++) { mma_tf32(acc1[mt][nt], aq[mt], b1[nt]); mma_tf32(acc2[mt][nt], ak[mt], b2[nt]); }
        }
    }
    __syncthreads();

    #pragma unroll
    for (int mt = 0; mt < 2; mt++) {
        int r = wr * 32 + mt * 16 + lr;
        #pragma unroll
        for (int nt = 0; nt < 4; nt++) {
            int c = wc * 32 + nt * 8 + lc * 2;
            C1s[r * 132 + c] = acc1[mt][nt][0]; C1s[r * 132 + c + 1] = acc1[mt][nt][1];
            C1s[(r + 8) * 132 + c] = acc1[mt][nt][2]; C1s[(r + 8) * 132 + c + 1] = acc1[mt][nt][3];
            C2s[r * 132 + c] = acc2[mt][nt][0]; C2s[r * 132 + c + 1] = acc2[mt][nt][1];
            C2s[(r + 8) * 132 + c] = acc2[mt][nt][2]; C2s[(r + 8) * 132 + c + 1] = acc2[mt][nt][3];
        }
    }
    __syncthreads();

    #pragma unroll
    for (int mt = 0; mt < 2; mt++) {
        #pragma unroll
        for (int nt = 0; nt < 2; nt++) {
            int r = wr * 32 + mt * 16 + lr;
            int c0 = wc * 16 + nt * 8 + lc * 2;
            #pragma unroll
            for (int half = 0; half < 2; half++) {
                int rr = r + half * 8;
                float o[2];
                #pragma unroll
                for (int e = 0; e < 2; e++) {
                    int cc = c0 + e;
                    int t = rr - cc + 63;
                    float val = (accS[mt][nt][half * 2 + e] + C1s[rr * 132 + t] + C2s[cc * 132 + t]) * scale;
                    val += (1.0f - mask[b * SS + n0 + cc]) * (-1e9f);
                    o[e] = val;
                }
                *(float2*)(scores + ((size_t)z * SS + m0 + rr) * SS + n0 + c0) = make_float2(o[0], o[1]);
            }
        }
    }
}

// ---------------- row softmax ----------------
__global__ void __launch_bounds__(128) softmax_kernel(float* __restrict__ scores)
{
    int q = blockIdx.x, z = blockIdx.y;
    int t = threadIdx.x;
    int lane = t & 31, wp = t >> 5;
    float4* row = (float4*)(scores + ((size_t)z * SS + q) * SS);

    float4 v = row[t];
    float mx = fmaxf(fmaxf(v.x, v.y), fmaxf(v.z, v.w));
    #pragma unroll
    for (int o = 16; o > 0; o >>= 1) mx = fmaxf(mx, __shfl_xor_sync(0xffffffffu, mx, o));
    __shared__ float sm[4];
    if (lane == 0) sm[wp] = mx;
    __syncthreads();
    mx = fmaxf(fmaxf(sm[0], sm[1]), fmaxf(sm[2], sm[3]));

    float4 e = make_float4(expf(v.x - mx), expf(v.y - mx), expf(v.z - mx), expf(v.w - mx));
    float s = e.x + e.y + e.z + e.w;
    #pragma unroll
    for (int o = 16; o > 0; o >>= 1) s += __shfl_xor_sync(0xffffffffu, s, o);
    __shared__ float sm2[4];
    if (lane == 0) sm2[wp] = s;
    __syncthreads();
    float inv = 1.0f / (sm2[0] + sm2[1] + sm2[2] + sm2[3]);
    row[t] = make_float4(e.x * inv, e.y * inv, e.z * inv, e.w * inv);
}

// ---------------- batched ctx GEMM (tf32, proven) ----------------
__global__ void __launch_bounds__(256) ctx_tf32(
    const float* __restrict__ Pm, const float* __restrict__ V, float* __restrict__ O)
{
    int z = blockIdx.y; int b = z / HH, hh = z % HH;
    int m0 = blockIdx.x * 128;
    const float* A = Pm + (size_t)z * SS * SS;
    const float* Bv = V + (size_t)b * SS * DD + hh * DH;

    extern __shared__ unsigned dsm[];
    unsigned* Asm = dsm;
    unsigned* Bsm = dsm + 2 * 2560;

    int tid = threadIdx.x;
    int w = tid >> 5, lane = tid & 31;
    int lr = lane >> 2, lc = lane & 3;
    int wm = (w >> 1) * 32, wn = (w & 1) * 32;

    int arow = tid & 127, acol = (tid >> 7) * 8;
    int brow = tid >> 4, bcol = (tid & 15) * 4;

    const float* aptr = A + (size_t)(m0 + arow) * SS + acol;
    const float* bptr = Bv + (size_t)brow * DD + bcol;
    const size_t bstep = (size_t)16 * DD;

    const int kTiles = SS / 16;

    float4 ra0 = *(const float4*)aptr;
    float4 ra1 = *(const float4*)(aptr + 4);
    float4 rb0 = *(const float4*)bptr;

    float acc[2][4][4] = {};

    for (int kt = 0; kt < kTiles; kt++) {
        unsigned* as = Asm + (kt & 1) * 2560;
        unsigned* bs = Bsm + (kt & 1) * 1152;
        *(uint4*)(as + arow * 20 + acol)     = f2tf4(ra0);
        *(uint4*)(as + arow * 20 + acol + 4) = f2tf4(ra1);
        *(uint4*)(bs + brow * 72 + bcol)     = f2tf4(rb0);
        __syncthreads();

        if (kt + 1 < kTiles) {
            aptr += 16; bptr += bstep;
            ra0 = *(const float4*)aptr;
            ra1 = *(const float4*)(aptr + 4);
            rb0 = *(const float4*)bptr;
        }

        #pragma unroll
        for (int ks = 0; ks < 16; ks += 8) {
            unsigned af[2][4], bf[4][2];
            #pragma unroll
            for (int mt = 0; mt < 2; mt++) {
                int m = wm + mt * 16 + lr;
                af[mt][0] = as[m * 20 + ks + lc];
                af[mt][1] = as[(m + 8) * 20 + ks + lc];
                af[mt][2] = as[m * 20 + ks + lc + 4];
                af[mt][3] = as[(m + 8) * 20 + ks + lc + 4];
            }
            #pragma unroll
            for (int nt = 0; nt < 4; nt++) {
                int n = wn + nt * 8 + lr;
                bf[nt][0] = bs[(ks + lc) * 72 + n];
                bf[nt][1] = bs[(ks + lc + 4) * 72 + n];
            }
            #pragma unroll
            for (int mt = 0; mt < 2; mt++)
                #pragma unroll
                for (int nt = 0; nt < 4; nt++)
                    mma_tf32(acc[mt][nt], af[mt], bf[nt]);
        }
    }

    #pragma unroll
    for (int mt = 0; mt < 2; mt++) {
        int r = m0 + wm + mt * 16 + lr;
        #pragma unroll
        for (int nt = 0; nt < 4; nt++) {
            int c = wn + nt * 8 + lc * 2;
            *(float2*)(O + ((size_t)b * SS + r) * DD + hh * DH + c)     = make_float2(acc[mt][nt][0], acc[mt][nt][1]);
            *(float2*)(O + ((size_t)b * SS + r + 8) * DD + hh * DH + c) = make_float2(acc[mt][nt][2], acc[mt][nt][3]);
        }
    }
}

// ---------------- residual add (two deltas) + LN ----------------
__global__ void __launch_bounds__(256) add_ln3_kernel(
    float* __restrict__ h, const float* __restrict__ d1, const float* __restrict__ d2,
    const float* __restrict__ w, const float* __restrict__ b)
{
    int t = blockIdx.x, tid = threadIdx.x;
    __shared__ float xs[DD];
    __shared__ float red[256];
    float* hr = h + (size_t)t * DD;
    const float* r1 = d1 + (size_t)t * DD;
    const float* r2 = d2 + (size_t)t * DD;

    float s = 0.f;
    for (int d = tid; d < DD; d += 256) { float x = hr[d] + r1[d] + r2[d]; xs[d] = x; s += x; }
    red[tid] = s; __syncthreads();
    for (int st = 128; st > 0; st >>= 1) { if (tid < st) red[tid] += red[tid + st]; __syncthreads(); }
    float mu = red[0] * (1.0f / DD); __syncthreads();
    float s2 = 0.f;
    for (int d = tid; d < DD; d += 256) { float dv = xs[d] - mu; s2 += dv * dv; }
    red[tid] = s2; __syncthreads();
    for (int st = 128; st > 0; st >>= 1) { if (tid < st) red[tid] += red[tid + st]; __syncthreads(); }
    float inv = rsqrtf(red[0] * (1.0f / DD) + 1e-12f);
    for (int d = tid; d < DD; d += 256) hr[d] = (xs[d] - mu) * inv * w[d] + b[d];
}

// ---------------- host orchestration ----------------
extern "C" void kernel_launch(void* const* d_in, const int* in_sizes, int n_in,
                              void* d_out, int out_size)
{
    const int*   input_ids   = (const int*)  d_in[0];
    const int*   segment_ids = (const int*)  d_in[1];
    const int*   pinyin_ids  = (const int*)  d_in[2];
    const float* attn_mask   = (const float*)d_in[3];
    const float* tok_emb     = (const float*)d_in[4];
    const float* pin_emb     = (const float*)d_in[5];
    const float* seg_emb     = (const float*)d_in[6];
    const float* emb_ln_w    = (const float*)d_in[7];
    const float* emb_ln_b    = (const float*)d_in[8];
    const float* rel_emb     = (const float*)d_in[9];
    const float* Wq = (const float*)d_in[10]; const float* bq = (const float*)d_in[11];
    const float* Wk = (const float*)d_in[12]; const float* bk = (const float*)d_in[13];
    const float* Wv = (const float*)d_in[14]; const float* bv = (const float*)d_in[15];
    const float* Wo = (const float*)d_in[16]; const float* bo = (const float*)d_in[17];
    const float* ln1w = (const float*)d_in[18]; const float* ln1b = (const float*)d_in[19];
    const float* W1 = (const float*)d_in[20]; const float* b1 = (const float*)d_in[21];
    const float* W2 = (const float*)d_in[22]; const float* b2 = (const float*)d_in[23];
    const float* ln2w = (const float*)d_in[24]; const float* ln2b = (const float*)d_in[25];

    float *h, *q, *k, *v, *ctx, *tmp, *poskL, *posqL, *scores;
    int *tab;
    cudaGetSymbolAddress((void**)&h,      g_h);
    cudaGetSymbolAddress((void**)&q,      g_q);
    cudaGetSymbolAddress((void**)&k,      g_k);
    cudaGetSymbolAddress((void**)&v,      g_v);
    cudaGetSymbolAddress((void**)&ctx,    g_ctx);
    cudaGetSymbolAddress((void**)&tmp,    g_tmp);
    cudaGetSymbolAddress((void**)&poskL,  g_poskL);
    cudaGetSymbolAddress((void**)&posqL,  g_posqL);
    cudaGetSymbolAddress((void**)&scores, g_scores);
    cudaGetSymbolAddress((void**)&tab,    g_tab);

    const int CTX_SMEM   = 2 * (128 * 20 + 16 * 72) * 4;
    const int SCORE_SMEM = (4352 * 2 + 8704 * 2) * 4;
    cudaFuncSetAttribute(gemm_qkv,    cudaFuncAttributeMaxDynamicSharedMemorySize, GEMM_SMEM);
    cudaFuncSetAttribute(gemm_pos,    cudaFuncAttributeMaxDynamicSharedMemorySize, GEMM_SMEM);
    cudaFuncSetAttribute(gemm_one,    cudaFuncAttributeMaxDynamicSharedMemorySize, GEMM_SMEM);
    cudaFuncSetAttribute(gemm_sk,     cudaFuncAttributeMaxDynamicSharedMemorySize, GEMM_SMEM);
    cudaFuncSetAttribute(ctx_tf32,    cudaFuncAttributeMaxDynamicSharedMemorySize, CTX_SMEM);
    cudaFuncSetAttribute(score_fused, cudaFuncAttributeMaxDynamicSharedMemorySize, SCORE_SMEM);

    const float scale = 0.07216878364870323f;  // 1/sqrt(3*DH)

    embed_ln_kernel<<<MM, 256>>>(input_ids, segment_ids, pinyin_ids, attn_mask,
                                 tok_emb, pin_emb, seg_emb, emb_ln_w, emb_ln_b, h);
    buckets_kernel<<<4, 256>>>(tab);

    // ALL positional projections for all 12 layers, one launch (576 CTAs)
    gemm_pos<<<dim3(DD / 128, PP / 128, 2 * LL), 256, GEMM_SMEM>>>(
        rel_emb, Wq, Wk, bq, bk, posqL, poskL);

    for (int i = 0; i < LL; i++) {
        const float* Wq_i = Wq + (size_t)i * DD * DD; const float* bq_i = bq + (size_t)i * DD;
        const float* Wk_i = Wk + (size_t)i * DD * DD; const float* bk_i = bk + (size_t)i * DD;
        const float* Wv_i = Wv + (size_t)i * DD * DD; const float* bv_i = bv + (size_t)i * DD;
        const float* Wo_i = Wo + (size_t)i * DD * DD; const float* bo_i = bo + (size_t)i * DD;
        const float* W1_i = W1 + (size_t)i * DD * FF; const float* b1_i = b1 + (size_t)i * FF;
        const float* W2_i = W2 + (size_t)i * FF * DD; const float* b2_i = b2 + (size_t)i * DD;
        const float* posk_i = poskL + (size_t)i * PP * DD;
        const float* posq_i = posqL + (size_t)i * PP * DD;

        gemm_qkv<<<dim3(DD / 128, MM / 128, 3), 256, GEMM_SMEM>>>(
            h, Wq_i, Wk_i, Wv_i, bq_i, bk_i, bv_i, q, k, v);

        score_fused<<<dim3(8, 8, BH), 256, SCORE_SMEM>>>(
            q, k, posk_i, posq_i, tab, attn_mask, scores, scale);
        softmax_kernel<<<dim3(SS, BH), 128>>>(scores);
        ctx_tf32<<<dim3(SS / 128, BH), 256, CTX_SMEM>>>(scores, v, ctx);

        gemm_sk<<<dim3(DD / 128, MM / 128, 2), 256, GEMM_SMEM>>>(
            ctx, Wo_i, bo_i, tmp, q, DD, DD);
        add_ln3_kernel<<<MM, 256>>>(h, tmp, q, ln1w + (size_t)i * DD, ln1b + (size_t)i * DD);

        gemm_one<<<dim3(FF / 128, MM / 128), 256, GEMM_SMEM>>>(h, W1_i, b1_i, tmp, FF, DD, 1);
        gemm_sk<<<dim3(DD / 128, MM / 128, 2), 256, GEMM_SMEM>>>(
            tmp, W2_i, b2_i, ctx, k, DD, FF);
        add_ln3_kernel<<<MM, 256>>>(h, ctx, k, ln2w + (size_t)i * DD, ln2b + (size_t)i * DD);
    }

    cudaMemcpyAsync(d_out, h, sizeof(float) * (size_t)out_size, cudaMemcpyDeviceToDevice);
}

// round 13
// speedup vs baseline: 1.4138x; 1.0540x over previous
#include <cuda_runtime.h>
#include <cuda_bf16.h>
#include <cuda_fp16.h>
#include <math.h>

#define BB 4
#define SS 512
#define DD 768
#define HH 12
#define LL 12
#define FF 3072
#define DH 64
#define PP 512
#define BH (BB*HH)
#define MM (BB*SS)

__device__ __align__(256) float g_h   [MM*DD];
__device__ __align__(256) float g_q   [MM*DD];
__device__ __align__(256) float g_k   [MM*DD];
__device__ __align__(256) float g_v   [MM*DD];
__device__ __align__(256) float g_ctx [MM*DD];
__device__ __align__(256) float g_tmp [MM*FF];
__device__ __align__(256) float g_poskL[(size_t)LL*PP*DD];
__device__ __align__(256) float g_posqL[(size_t)LL*PP*DD];
__device__ __align__(256) float g_scores[(size_t)BH*SS*SS];
__device__ int g_tab[1024];

__device__ __forceinline__ unsigned pack2(float lo, float hi) {
    __half2 h = __floats2half2_rn(lo, hi);
    return *reinterpret_cast<unsigned*>(&h);
}
__device__ __forceinline__ uint4 pack8(float4 a, float4 b) {
    return make_uint4(pack2(a.x, a.y), pack2(a.z, a.w), pack2(b.x, b.y), pack2(b.z, b.w));
}
__device__ __forceinline__ void mma_f16(float* d, const unsigned* a, const unsigned* b) {
    asm volatile(
        "mma.sync.aligned.m16n8k16.row.col.f32.f16.f16.f32 "
        "{%0,%1,%2,%3}, {%4,%5,%6,%7}, {%8,%9}, {%0,%1,%2,%3};\n"
        : "+f"(d[0]), "+f"(d[1]), "+f"(d[2]), "+f"(d[3])
        : "r"(a[0]), "r"(a[1]), "r"(a[2]), "r"(a[3]), "r"(b[0]), "r"(b[1]));
}

// ---------------- embeddings + LN + mask ----------------
__global__ void __launch_bounds__(256) embed_ln_kernel(
    const int* __restrict__ ids, const int* __restrict__ segs, const int* __restrict__ pins,
    const float* __restrict__ mask,
    const float* __restrict__ tok, const float* __restrict__ pin, const float* __restrict__ seg,
    const float* __restrict__ w, const float* __restrict__ b, float* __restrict__ out)
{
    int t = blockIdx.x, tid = threadIdx.x;
    __shared__ float xs[DD];
    __shared__ float red[256];
    size_t io = (size_t)ids[t] * DD, po = (size_t)pins[t] * DD, so = (size_t)segs[t] * DD;
    float s = 0.f;
    for (int d = tid; d < DD; d += 256) {
        float x = tok[io + d] + pin[po + d] + seg[so + d];
        xs[d] = x; s += x;
    }
    red[tid] = s; __syncthreads();
    for (int st = 128; st > 0; st >>= 1) { if (tid < st) red[tid] += red[tid + st]; __syncthreads(); }
    float mu = red[0] * (1.0f / DD); __syncthreads();
    float s2 = 0.f;
    for (int d = tid; d < DD; d += 256) { float dv = xs[d] - mu; s2 += dv * dv; }
    red[tid] = s2; __syncthreads();
    for (int st = 128; st > 0; st >>= 1) { if (tid < st) red[tid] += red[tid + st]; __syncthreads(); }
    float inv = rsqrtf(red[0] * (1.0f / DD) + 1e-12f);
    float m = mask[t];
    for (int d = tid; d < DD; d += 256)
        out[(size_t)t * DD + d] = ((xs[d] - mu) * inv * w[d] + b[d]) * m;
}

// ---------------- bucket table ----------------
__global__ void buckets_kernel(int* __restrict__ tab)
{
    int x = blockIdx.x * blockDim.x + threadIdx.x;
    if (x >= 1023) { if (x == 1023) tab[1023] = 0; return; }
    int rel = x - 511;
    const int mid = 128;
    int ap = (rel < mid && rel > -mid) ? (mid - 1) : (rel < 0 ? -rel : rel);
    int bucket;
    if (ap <= mid) bucket = rel;
    else {
        double lp = ceil(log((double)ap / (double)mid) / log(511.0 / 128.0) * (mid - 1)) + mid;
        int sgn = (rel > 0) - (rel < 0);
        bucket = (int)lp * sgn;
    }
    int c = bucket + 256; c = c < 0 ? 0 : (c > 511 ? 511 : c);
    tab[x] = c;
}

// ---------------- dense fp16 GEMM body (proven R12), 128x128 tile ----------------
#define A_STR 12
#define B_STR 136
#define A_STG (128*A_STR)
#define B_STG (8*B_STR)
#define GEMM_SMEM ((A_STG + B_STG) * 2 * 4)

__device__ __forceinline__ void gemm128_core(
    const float* __restrict__ A, const float* __restrict__ Bm,
    const float* __restrict__ bias, float* __restrict__ C,
    int m0, int n0, int N, int K, int kStart, int kLen, int act, int useBias)
{
    extern __shared__ unsigned dsm[];
    unsigned* Asm = dsm;
    unsigned* Bsm = dsm + 2 * A_STG;

    int tid = threadIdx.x;
    int w = tid >> 5, lane = tid & 31;
    int lr = lane >> 2, lc = lane & 3;
    int wm = (w >> 2) * 64, wn = (w & 3) * 32;

    int arow = tid >> 2, acolf = (tid & 3) * 4;
    int brow2 = tid >> 5, bcolf = (tid & 31) * 4;

    const float* aptr  = A + (size_t)(m0 + arow) * K + kStart + acolf;
    const float* aptr2 = aptr + (size_t)64 * K;
    const float* bptr0 = Bm + (size_t)(kStart + 2 * brow2) * N + n0 + bcolf;
    const float* bptr1 = bptr0 + N;
    const size_t bstep = (size_t)16 * N;

    const int kTiles = kLen >> 4;

    float4 ra0 = *(const float4*)aptr;
    float4 ra1 = *(const float4*)aptr2;
    float4 rb0 = *(const float4*)bptr0;
    float4 rb1 = *(const float4*)bptr1;

    float acc[4][4][4] = {};

    for (int kt = 0; kt < kTiles; kt++) {
        unsigned* as = Asm + (kt & 1) * A_STG;
        unsigned* bs = Bsm + (kt & 1) * B_STG;
        *(uint2*)(as + arow * A_STR + (tid & 3) * 2) =
            make_uint2(pack2(ra0.x, ra0.y), pack2(ra0.z, ra0.w));
        *(uint2*)(as + (arow + 64) * A_STR + (tid & 3) * 2) =
            make_uint2(pack2(ra1.x, ra1.y), pack2(ra1.z, ra1.w));
        *(uint4*)(bs + brow2 * B_STR + bcolf) =
            make_uint4(pack2(rb0.x, rb1.x), pack2(rb0.y, rb1.y),
                       pack2(rb0.z, rb1.z), pack2(rb0.w, rb1.w));
        __syncthreads();

        if (kt + 1 < kTiles) {
            aptr += 16; aptr2 += 16; bptr0 += bstep; bptr1 += bstep;
            ra0 = *(const float4*)aptr;
            ra1 = *(const float4*)aptr2;
            rb0 = *(const float4*)bptr0;
            rb1 = *(const float4*)bptr1;
        }

        unsigned af[4][4], bf[4][2];
        #pragma unroll
        for (int mt = 0; mt < 4; mt++) {
            int m = wm + mt * 16 + lr;
            af[mt][0] = as[m * A_STR + lc];
            af[mt][1] = as[(m + 8) * A_STR + lc];
            af[mt][2] = as[m * A_STR + lc + 4];
            af[mt][3] = as[(m + 8) * A_STR + lc + 4];
        }
        #pragma unroll
        for (int nt = 0; nt < 4; nt++) {
            int n = wn + nt * 8 + lr;
            bf[nt][0] = bs[lc * B_STR + n];
            bf[nt][1] = bs[(lc + 4) * B_STR + n];
        }
        #pragma unroll
        for (int mt = 0; mt < 4; mt++)
            #pragma unroll
            for (int nt = 0; nt < 4; nt++)
                mma_f16(acc[mt][nt], af[mt], bf[nt]);
    }

    #pragma unroll
    for (int mt = 0; mt < 4; mt++) {
        int r = m0 + wm + mt * 16 + lr;
        #pragma unroll
        for (int nt = 0; nt < 4; nt++) {
            int c = n0 + wn + nt * 8 + lc * 2;
            float bv0 = useBias ? bias[c] : 0.f, bv1 = useBias ? bias[c + 1] : 0.f;
            float v00 = acc[mt][nt][0] + bv0, v01 = acc[mt][nt][1] + bv1;
            float v10 = acc[mt][nt][2] + bv0, v11 = acc[mt][nt][3] + bv1;
            if (act) {
                v00 = 0.5f * v00 * (1.0f + erff(v00 * 0.70710678118654752f));
                v01 = 0.5f * v01 * (1.0f + erff(v01 * 0.70710678118654752f));
                v10 = 0.5f * v10 * (1.0f + erff(v10 * 0.70710678118654752f));
                v11 = 0.5f * v11 * (1.0f + erff(v11 * 0.70710678118654752f));
            }
            *(float2*)(C + (size_t)r * N + c)       = make_float2(v00, v01);
            *(float2*)(C + (size_t)(r + 8) * N + c) = make_float2(v10, v11);
        }
    }
}

__global__ void __launch_bounds__(256) gemm_qkv(
    const float* __restrict__ hbuf,
    const float* __restrict__ Wq, const float* __restrict__ Wk, const float* __restrict__ Wv,
    const float* __restrict__ bq, const float* __restrict__ bk, const float* __restrict__ bv,
    float* __restrict__ q, float* __restrict__ k, float* __restrict__ v)
{
    const int z = blockIdx.z;
    const float* Bm   = (z == 0) ? Wq : (z == 1) ? Wk : Wv;
    const float* bias = (z == 0) ? bq : (z == 1) ? bk : bv;
    float*       C    = (z == 0) ? q  : (z == 1) ? k  : v;
    gemm128_core(hbuf, Bm, bias, C, blockIdx.y * 128, blockIdx.x * 128, DD, DD, 0, DD, 0, 1);
}

__global__ void __launch_bounds__(256) gemm_pos(
    const float* __restrict__ rel,
    const float* __restrict__ Wq, const float* __restrict__ Wk,
    const float* __restrict__ bq, const float* __restrict__ bk,
    float* __restrict__ posqL, float* __restrict__ poskL)
{
    const int z = blockIdx.z;
    const int l = z >> 1;
    const int isq = z & 1;
    const float* Bm   = (isq ? Wq : Wk) + (size_t)l * DD * DD;
    const float* bias = (isq ? bq : bk) + (size_t)l * DD;
    float*       C    = (isq ? posqL : poskL) + (size_t)l * PP * DD;
    gemm128_core(rel, Bm, bias, C, blockIdx.y * 128, blockIdx.x * 128, DD, DD, 0, DD, 0, 1);
}

__global__ void __launch_bounds__(256) gemm_one(
    const float* __restrict__ A, const float* __restrict__ Bm, const float* __restrict__ bias,
    float* __restrict__ C, int N, int K, int act)
{
    gemm128_core(A, Bm, bias, C, blockIdx.y * 128, blockIdx.x * 128, N, K, 0, K, act, 1);
}

__global__ void __launch_bounds__(256) gemm_sk(
    const float* __restrict__ A, const float* __restrict__ Bm, const float* __restrict__ bias,
    float* __restrict__ C0, float* __restrict__ C1, int N, int K)
{
    const int z = blockIdx.z;
    gemm128_core(A, Bm, bias, z ? C1 : C0, blockIdx.y * 128, blockIdx.x * 128,
                 N, K, z * (K >> 1), K >> 1, 0, z == 0);
}

// ---------------- fused disentangled score kernel — fp16 MMA ----------------
// smem (u32): Qs@0 (64x36), Ks@2304, PKs@4608 (128x36), PQs@9216. Overlay after MMA:
// C1s (float) @0 (64x132), C2s @8448. Total = 16896 u32 = 67584 B.
#define SC_STR 36
#define SCORE_SMEM (16896 * 4)
__global__ void __launch_bounds__(256) score_fused(
    const float* __restrict__ Q, const float* __restrict__ Kt,
    const float* __restrict__ PKg, const float* __restrict__ PQg,
    const int* __restrict__ tab, const float* __restrict__ mask,
    float* __restrict__ scores, float scale)
{
    int z = blockIdx.z; int b = z / HH, hh = z % HH;
    int m0 = blockIdx.y * 64, n0 = blockIdx.x * 64;
    const float* Aq = Q  + (size_t)b * SS * DD + hh * DH;
    const float* Ak = Kt + (size_t)b * SS * DD + hh * DH;
    const float* PK = PKg + hh * DH;
    const float* PQ = PQg + hh * DH;

    extern __shared__ unsigned ssm[];
    unsigned* Qs  = ssm;
    unsigned* Ks  = ssm + 2304;
    unsigned* PKs = ssm + 4608;
    unsigned* PQs = ssm + 9216;
    float* C1s = (float*)ssm;            // overlay (post-MMA)
    float* C2s = (float*)(ssm + 8448);

    int tid = threadIdx.x;
    int w = tid >> 5, lane = tid & 31;
    int lr = lane >> 2, lc = lane & 3;
    int wr = w >> 2, wc = w & 3;
    const int dlo = m0 - n0 - 63;

    {
        int row = tid >> 2;
        int colf = (tid & 3) * 16;        // 16 floats -> 8 u32
        int colu = colf >> 1;
        {
            const float* p = Aq + (size_t)(m0 + row) * DD + colf;
            *(uint4*)(Qs + row * SC_STR + colu)     = pack8(*(const float4*)p,       *(const float4*)(p + 4));
            *(uint4*)(Qs + row * SC_STR + colu + 4) = pack8(*(const float4*)(p + 8), *(const float4*)(p + 12));
        }
        {
            const float* p = Ak + (size_t)(n0 + row) * DD + colf;
            *(uint4*)(Ks + row * SC_STR + colu)     = pack8(*(const float4*)p,       *(const float4*)(p + 4));
            *(uint4*)(Ks + row * SC_STR + colu + 4) = pack8(*(const float4*)(p + 8), *(const float4*)(p + 12));
        }
        #pragma unroll
        for (int half = 0; half < 2; half++) {
            int t = row + half * 64;
            int tt = t < 127 ? t : 126;
            int pidx = tab[dlo + tt + 511];
            const float* pk = PK + (size_t)pidx * DD + colf;
            *(uint4*)(PKs + t * SC_STR + colu)     = pack8(*(const float4*)pk,       *(const float4*)(pk + 4));
            *(uint4*)(PKs + t * SC_STR + colu + 4) = pack8(*(const float4*)(pk + 8), *(const float4*)(pk + 12));
            const float* pq = PQ + (size_t)pidx * DD + colf;
            *(uint4*)(PQs + t * SC_STR + colu)     = pack8(*(const float4*)pq,       *(const float4*)(pq + 4));
            *(uint4*)(PQs + t * SC_STR + colu + 4) = pack8(*(const float4*)(pq + 8), *(const float4*)(pq + 12));
        }
    }
    __syncthreads();

    float accS[2][2][4] = {};
    float acc1[2][4][4] = {};
    float acc2[2][4][4] = {};

    #pragma unroll
    for (int c = 0; c < 4; c++) {        // 4 chunks of k=16
        int cu = c * 8;
        unsigned aq[2][4], ak[2][4];
        #pragma unroll
        for (int mt = 0; mt < 2; mt++) {
            int m = wr * 32 + mt * 16 + lr;
            aq[mt][0] = Qs[m * SC_STR + cu + lc];       aq[mt][1] = Qs[(m + 8) * SC_STR + cu + lc];
            aq[mt][2] = Qs[m * SC_STR + cu + lc + 4];   aq[mt][3] = Qs[(m + 8) * SC_STR + cu + lc + 4];
            ak[mt][0] = Ks[m * SC_STR + cu + lc];       ak[mt][1] = Ks[(m + 8) * SC_STR + cu + lc];
            ak[mt][2] = Ks[m * SC_STR + cu + lc + 4];   ak[mt][3] = Ks[(m + 8) * SC_STR + cu + lc + 4];
        }
        unsigned bS[2][2], b1[4][2], b2[4][2];
        #pragma unroll
        for (int nt = 0; nt < 2; nt++) {
            int n = wc * 16 + nt * 8 + lr;
            bS[nt][0] = Ks[n * SC_STR + cu + lc];
            bS[nt][1] = Ks[n * SC_STR + cu + lc + 4];
        }
        #pragma unroll
        for (int nt = 0; nt < 4; nt++) {
            int n = wc * 32 + nt * 8 + lr;
            b1[nt][0] = PKs[n * SC_STR + cu + lc];
            b1[nt][1] = PKs[n * SC_STR + cu + lc + 4];
            b2[nt][0] = PQs[n * SC_STR + cu + lc];
            b2[nt][1] = PQs[n * SC_STR + cu + lc + 4];
        }
        #pragma unroll
        for (int mt = 0; mt < 2; mt++) {
            #pragma unroll
            for (int nt = 0; nt < 2; nt++) mma_f16(accS[mt][nt], aq[mt], bS[nt]);
            #pragma unroll
            for (int nt = 0; nt < 4; nt++) { mma_f16(acc1[mt][nt], aq[mt], b1[nt]); mma_f16(acc2[mt][nt], ak[mt], b2[nt]); }
        }
    }
    __syncthreads();

    #pragma unroll
    for (int mt = 0; mt < 2; mt++) {
        int r = wr * 32 + mt * 16 + lr;
        #pragma unroll
        for (int nt = 0; nt < 4; nt++) {
            int c = wc * 32 + nt * 8 + lc * 2;
            C1s[r * 132 + c] = acc1[mt][nt][0]; C1s[r * 132 + c + 1] = acc1[mt][nt][1];
            C1s[(r + 8) * 132 + c] = acc1[mt][nt][2]; C1s[(r + 8) * 132 + c + 1] = acc1[mt][nt][3];
            C2s[r * 132 + c] = acc2[mt][nt][0]; C2s[r * 132 + c + 1] = acc2[mt][nt][1];
            C2s[(r + 8) * 132 + c] = acc2[mt][nt][2]; C2s[(r + 8) * 132 + c + 1] = acc2[mt][nt][3];
        }
    }
    __syncthreads();

    #pragma unroll
    for (int mt = 0; mt < 2; mt++) {
        #pragma unroll
        for (int nt = 0; nt < 2; nt++) {
            int r = wr * 32 + mt * 16 + lr;
            int c0 = wc * 16 + nt * 8 + lc * 2;
            #pragma unroll
            for (int half = 0; half < 2; half++) {
                int rr = r + half * 8;
                float o[2];
                #pragma unroll
                for (int e = 0; e < 2; e++) {
                    int cc = c0 + e;
                    int t = rr - cc + 63;
                    float val = (accS[mt][nt][half * 2 + e] + C1s[rr * 132 + t] + C2s[cc * 132 + t]) * scale;
                    val += (1.0f - mask[b * SS + n0 + cc]) * (-1e9f);
                    o[e] = val;
                }
                *(float2*)(scores + ((size_t)z * SS + m0 + rr) * SS + n0 + c0) = make_float2(o[0], o[1]);
            }
        }
    }
}

// ---------------- row softmax ----------------
__global__ void __launch_bounds__(128) softmax_kernel(float* __restrict__ scores)
{
    int q = blockIdx.x, z = blockIdx.y;
    int t = threadIdx.x;
    int lane = t & 31, wp = t >> 5;
    float4* row = (float4*)(scores + ((size_t)z * SS + q) * SS);

    float4 v = row[t];
    float mx = fmaxf(fmaxf(v.x, v.y), fmaxf(v.z, v.w));
    #pragma unroll
    for (int o = 16; o > 0; o >>= 1) mx = fmaxf(mx, __shfl_xor_sync(0xffffffffu, mx, o));
    __shared__ float sm[4];
    if (lane == 0) sm[wp] = mx;
    __syncthreads();
    mx = fmaxf(fmaxf(sm[0], sm[1]), fmaxf(sm[2], sm[3]));

    float4 e = make_float4(expf(v.x - mx), expf(v.y - mx), expf(v.z - mx), expf(v.w - mx));
    float s = e.x + e.y + e.z + e.w;
    #pragma unroll
    for (int o = 16; o > 0; o >>= 1) s += __shfl_xor_sync(0xffffffffu, s, o);
    __shared__ float sm2[4];
    if (lane == 0) sm2[wp] = s;
    __syncthreads();
    float inv = 1.0f / (sm2[0] + sm2[1] + sm2[2] + sm2[3]);
    row[t] = make_float4(e.x * inv, e.y * inv, e.z * inv, e.w * inv);
}

// ---------------- batched ctx GEMM — fp16 MMA: O = P @ V ----------------
// 128(m) x 64(n) tile, BK=16. A: probs packed along k (stride 12); B: V k-pair packed (stride 72).
#define CTXB_STR 72
#define CTX_SMEM ((2 * (128 * A_STR) + 2 * (8 * CTXB_STR)) * 4)
__global__ void __launch_bounds__(256) ctx_f16(
    const float* __restrict__ Pm, const float* __restrict__ V, float* __restrict__ O)
{
    int z = blockIdx.y; int b = z / HH, hh = z % HH;
    int m0 = blockIdx.x * 128;
    const float* A = Pm + (size_t)z * SS * SS;
    const float* Bv = V + (size_t)b * SS * DD + hh * DH;

    extern __shared__ unsigned dsm[];
    unsigned* Asm = dsm;                      // 2 x 1536
    unsigned* Bsm = dsm + 2 * 128 * A_STR;    // 2 x 576

    int tid = threadIdx.x;
    int w = tid >> 5, lane = tid & 31;
    int lr = lane >> 2, lc = lane & 3;
    int wm = (w >> 1) * 32, wn = (w & 1) * 32;

    int arow = tid & 127, acolf = (tid >> 7) * 8;   // 8 floats -> 4 u32
    int brow2 = (tid >> 4) & 7, bcolf = (tid & 15) * 4;
    bool bload = tid < 128;

    const float* aptr  = A + (size_t)(m0 + arow) * SS + acolf;
    const float* bptr0 = Bv + (size_t)(2 * brow2) * DD + bcolf;
    const float* bptr1 = bptr0 + DD;
    const size_t bstep = (size_t)16 * DD;

    const int kTiles = SS / 16;

    float4 ra0 = *(const float4*)aptr;
    float4 ra1 = *(const float4*)(aptr + 4);
    float4 rb0 = make_float4(0.f, 0.f, 0.f, 0.f), rb1 = rb0;
    if (bload) { rb0 = *(const float4*)bptr0; rb1 = *(const float4*)bptr1; }

    float acc[2][4][4] = {};

    for (int kt = 0; kt < kTiles; kt++) {
        unsigned* as = Asm + (kt & 1) * (128 * A_STR);
        unsigned* bs = Bsm + (kt & 1) * (8 * CTXB_STR);
        *(uint4*)(as + arow * A_STR + (acolf >> 1)) = pack8(ra0, ra1);
        if (bload)
            *(uint4*)(bs + brow2 * CTXB_STR + bcolf) =
                make_uint4(pack2(rb0.x, rb1.x), pack2(rb0.y, rb1.y),
                           pack2(rb0.z, rb1.z), pack2(rb0.w, rb1.w));
        __syncthreads();

        if (kt + 1 < kTiles) {
            aptr += 16;
            ra0 = *(const float4*)aptr;
            ra1 = *(const float4*)(aptr + 4);
            if (bload) {
                bptr0 += bstep; bptr1 += bstep;
                rb0 = *(const float4*)bptr0;
                rb1 = *(const float4*)bptr1;
            }
        }

        unsigned af[2][4], bf[4][2];
        #pragma unroll
        for (int mt = 0; mt < 2; mt++) {
            int m = wm + mt * 16 + lr;
            af[mt][0] = as[m * A_STR + lc];
            af[mt][1] = as[(m + 8) * A_STR + lc];
            af[mt][2] = as[m * A_STR + lc + 4];
            af[mt][3] = as[(m + 8) * A_STR + lc + 4];
        }
        #pragma unroll
        for (int nt = 0; nt < 4; nt++) {
            int n = wn + nt * 8 + lr;
            bf[nt][0] = bs[lc * CTXB_STR + n];
            bf[nt][1] = bs[(lc + 4) * CTXB_STR + n];
        }
        #pragma unroll
        for (int mt = 0; mt < 2; mt++)
            #pragma unroll
            for (int nt = 0; nt < 4; nt++)
                mma_f16(acc[mt][nt], af[mt], bf[nt]);
    }

    #pragma unroll
    for (int mt = 0; mt < 2; mt++) {
        int r = m0 + wm + mt * 16 + lr;
        #pragma unroll
        for (int nt = 0; nt < 4; nt++) {
            int c = wn + nt * 8 + lc * 2;
            *(float2*)(O + ((size_t)b * SS + r) * DD + hh * DH + c)     = make_float2(acc[mt][nt][0], acc[mt][nt][1]);
            *(float2*)(O + ((size_t)b * SS + r + 8) * DD + hh * DH + c) = make_float2(acc[mt][nt][2], acc[mt][nt][3]);
        }
    }
}

// ---------------- residual add (two deltas) + LN ----------------
__global__ void __launch_bounds__(256) add_ln3_kernel(
    float* __restrict__ h, const float* __restrict__ d1, const float* __restrict__ d2,
    const float* __restrict__ w, const float* __restrict__ b)
{
    int t = blockIdx.x, tid = threadIdx.x;
    __shared__ float xs[DD];
    __shared__ float red[256];
    float* hr = h + (size_t)t * DD;
    const float* r1 = d1 + (size_t)t * DD;
    const float* r2 = d2 + (size_t)t * DD;

    float s = 0.f;
    for (int d = tid; d < DD; d += 256) { float x = hr[d] + r1[d] + r2[d]; xs[d] = x; s += x; }
    red[tid] = s; __syncthreads();
    for (int st = 128; st > 0; st >>= 1) { if (tid < st) red[tid] += red[tid + st]; __syncthreads(); }
    float mu = red[0] * (1.0f / DD); __syncthreads();
    float s2 = 0.f;
    for (int d = tid; d < DD; d += 256) { float dv = xs[d] - mu; s2 += dv * dv; }
    red[tid] = s2; __syncthreads();
    for (int st = 128; st > 0; st >>= 1) { if (tid < st) red[tid] += red[tid + st]; __syncthreads(); }
    float inv = rsqrtf(red[0] * (1.0f / DD) + 1e-12f);
    for (int d = tid; d < DD; d += 256) hr[d] = (xs[d] - mu) * inv * w[d] + b[d];
}

// ---------------- host orchestration ----------------
extern "C" void kernel_launch(void* const* d_in, const int* in_sizes, int n_in,
                              void* d_out, int out_size)
{
    const int*   input_ids   = (const int*)  d_in[0];
    const int*   segment_ids = (const int*)  d_in[1];
    const int*   pinyin_ids  = (const int*)  d_in[2];
    const float* attn_mask   = (const float*)d_in[3];
    const float* tok_emb     = (const float*)d_in[4];
    const float* pin_emb     = (const float*)d_in[5];
    const float* seg_emb     = (const float*)d_in[6];
    const float* emb_ln_w    = (const float*)d_in[7];
    const float* emb_ln_b    = (const float*)d_in[8];
    const float* rel_emb     = (const float*)d_in[9];
    const float* Wq = (const float*)d_in[10]; const float* bq = (const float*)d_in[11];
    const float* Wk = (const float*)d_in[12]; const float* bk = (const float*)d_in[13];
    const float* Wv = (const float*)d_in[14]; const float* bv = (const float*)d_in[15];
    const float* Wo = (const float*)d_in[16]; const float* bo = (const float*)d_in[17];
    const float* ln1w = (const float*)d_in[18]; const float* ln1b = (const float*)d_in[19];
    const float* W1 = (const float*)d_in[20]; const float* b1 = (const float*)d_in[21];
    const float* W2 = (const float*)d_in[22]; const float* b2 = (const float*)d_in[23];
    const float* ln2w = (const float*)d_in[24]; const float* ln2b = (const float*)d_in[25];

    float *h, *q, *k, *v, *ctx, *tmp, *poskL, *posqL, *scores;
    int *tab;
    cudaGetSymbolAddress((void**)&h,      g_h);
    cudaGetSymbolAddress((void**)&q,      g_q);
    cudaGetSymbolAddress((void**)&k,      g_k);
    cudaGetSymbolAddress((void**)&v,      g_v);
    cudaGetSymbolAddress((void**)&ctx,    g_ctx);
    cudaGetSymbolAddress((void**)&tmp,    g_tmp);
    cudaGetSymbolAddress((void**)&poskL,  g_poskL);
    cudaGetSymbolAddress((void**)&posqL,  g_posqL);
    cudaGetSymbolAddress((void**)&scores, g_scores);
    cudaGetSymbolAddress((void**)&tab,    g_tab);

    cudaFuncSetAttribute(gemm_qkv,    cudaFuncAttributeMaxDynamicSharedMemorySize, GEMM_SMEM);
    cudaFuncSetAttribute(gemm_pos,    cudaFuncAttributeMaxDynamicSharedMemorySize, GEMM_SMEM);
    cudaFuncSetAttribute(gemm_one,    cudaFuncAttributeMaxDynamicSharedMemorySize, GEMM_SMEM);
    cudaFuncSetAttribute(gemm_sk,     cudaFuncAttributeMaxDynamicSharedMemorySize, GEMM_SMEM);
    cudaFuncSetAttribute(ctx_f16,     cudaFuncAttributeMaxDynamicSharedMemorySize, CTX_SMEM);
    cudaFuncSetAttribute(score_fused, cudaFuncAttributeMaxDynamicSharedMemorySize, SCORE_SMEM);

    const float scale = 0.07216878364870323f;  // 1/sqrt(3*DH)

    embed_ln_kernel<<<MM, 256>>>(input_ids, segment_ids, pinyin_ids, attn_mask,
                                 tok_emb, pin_emb, seg_emb, emb_ln_w, emb_ln_b, h);
    buckets_kernel<<<4, 256>>>(tab);

    // ALL positional projections for all 12 layers, one launch
    gemm_pos<<<dim3(DD / 128, PP / 128, 2 * LL), 256, GEMM_SMEM>>>(
        rel_emb, Wq, Wk, bq, bk, posqL, poskL);

    for (int i = 0; i < LL; i++) {
        const float* Wq_i = Wq + (size_t)i * DD * DD; const float* bq_i = bq + (size_t)i * DD;
        const float* Wk_i = Wk + (size_t)i * DD * DD; const float* bk_i = bk + (size_t)i * DD;
        const float* Wv_i = Wv + (size_t)i * DD * DD; const float* bv_i = bv + (size_t)i * DD;
        const float* Wo_i = Wo + (size_t)i * DD * DD; const float* bo_i = bo + (size_t)i * DD;
        const float* W1_i = W1 + (size_t)i * DD * FF; const float* b1_i = b1 + (size_t)i * FF;
        const float* W2_i = W2 + (size_t)i * FF * DD; const float* b2_i = b2 + (size_t)i * DD;
        const float* posk_i = poskL + (size_t)i * PP * DD;
        const float* posq_i = posqL + (size_t)i * PP * DD;

        gemm_qkv<<<dim3(DD / 128, MM / 128, 3), 256, GEMM_SMEM>>>(
            h, Wq_i, Wk_i, Wv_i, bq_i, bk_i, bv_i, q, k, v);

        score_fused<<<dim3(8, 8, BH), 256, SCORE_SMEM>>>(
            q, k, posk_i, posq_i, tab, attn_mask, scores, scale);
        softmax_kernel<<<dim3(SS, BH), 128>>>(scores);
        ctx_f16<<<dim3(SS / 128, BH), 256, CTX_SMEM>>>(scores, v, ctx);

        gemm_sk<<<dim3(DD / 128, MM / 128, 2), 256, GEMM_SMEM>>>(
            ctx, Wo_i, bo_i, tmp, q, DD, DD);
        add_ln3_kernel<<<MM, 256>>>(h, tmp, q, ln1w + (size_t)i * DD, ln1b + (size_t)i * DD);

        gemm_one<<<dim3(FF / 128, MM / 128), 256, GEMM_SMEM>>>(h, W1_i, b1_i, tmp, FF, DD, 1);
        gemm_sk<<<dim3(DD / 128, MM / 128, 2), 256, GEMM_SMEM>>>(
            tmp, W2_i, b2_i, ctx, k, DD, FF);
        add_ln3_kernel<<<MM, 256>>>(h, ctx, k, ln2w + (size_t)i * DD, ln2b + (size_t)i * DD);
    }

    cudaMemcpyAsync(d_out, h, sizeof(float) * (size_t)out_size, cudaMemcpyDeviceToDevice);
}

// round 14
// speedup vs baseline: 1.6290x; 1.1522x over previous
#include <cuda_runtime.h>
#include <cuda_bf16.h>
#include <cuda_fp16.h>
#include <math.h>

#define BB 4
#define SS 512
#define DD 768
#define HH 12
#define LL 12
#define FF 3072
#define DH 64
#define PP 512
#define BH (BB*HH)
#define MM (BB*SS)

// fp32 buffers (residual stream + logits)
__device__ __align__(256) float g_h   [MM*DD];
__device__ __align__(256) float g_s1  [MM*DD];
__device__ __align__(256) float g_s2  [MM*DD];
__device__ __align__(256) float g_scores[(size_t)BH*SS*SS];
// fp16 activation buffers
__device__ __align__(256) __half g_h16 [MM*DD];
__device__ __align__(256) __half g_q16 [MM*DD];
__device__ __align__(256) __half g_k16 [MM*DD];
__device__ __align__(256) __half g_v16 [MM*DD];
__device__ __align__(256) __half g_ctx16[MM*DD];
__device__ __align__(256) __half g_tmp16[MM*FF];
__device__ __align__(256) __half g_probs16[(size_t)BH*SS*SS];
__device__ __align__(256) __half g_posk16[(size_t)LL*PP*DD];
__device__ __align__(256) __half g_posq16[(size_t)LL*PP*DD];
__device__ __align__(256) __half g_rel16[PP*DD];
// k-pair-packed fp16 weights: per layer [Wq|Wk|Wv|Wo|W1|W2]
#define OQ 0
#define OK 589824
#define OV 1179648
#define OO 1769472
#define OW1 2359296
#define OW2 4718592
#define LSTR 7077888
__device__ __align__(256) __half g_wh[(size_t)LL*LSTR];
__device__ int g_tab[1024];

__device__ __forceinline__ void mma_f16(float* d, const unsigned* a, const unsigned* b) {
    asm volatile(
        "mma.sync.aligned.m16n8k16.row.col.f32.f16.f16.f32 "
        "{%0,%1,%2,%3}, {%4,%5,%6,%7}, {%8,%9}, {%0,%1,%2,%3};\n"
        : "+f"(d[0]), "+f"(d[1]), "+f"(d[2]), "+f"(d[3])
        : "r"(a[0]), "r"(a[1]), "r"(a[2]), "r"(a[3]), "r"(b[0]), "r"(b[1]));
}
__device__ __forceinline__ void cp16(void* smem, const void* gmem) {
    unsigned sa = (unsigned)__cvta_generic_to_shared(smem);
    asm volatile("cp.async.cg.shared.global [%0], [%1], 16;" :: "r"(sa), "l"(gmem));
}
#define CP_COMMIT asm volatile("cp.async.commit_group;")
#define CP_WAIT1  asm volatile("cp.async.wait_group 1;")

// ---------------- embeddings + LN + mask (dual fp32/fp16 store) ----------------
__global__ void __launch_bounds__(256) embed_ln_kernel(
    const int* __restrict__ ids, const int* __restrict__ segs, const int* __restrict__ pins,
    const float* __restrict__ mask,
    const float* __restrict__ tok, const float* __restrict__ pin, const float* __restrict__ seg,
    const float* __restrict__ w, const float* __restrict__ b,
    float* __restrict__ out, __half* __restrict__ out16)
{
    int t = blockIdx.x, tid = threadIdx.x;
    __shared__ float xs[DD];
    __shared__ float red[256];
    size_t io = (size_t)ids[t] * DD, po = (size_t)pins[t] * DD, so = (size_t)segs[t] * DD;
    float s = 0.f;
    for (int d = tid; d < DD; d += 256) {
        float x = tok[io + d] + pin[po + d] + seg[so + d];
        xs[d] = x; s += x;
    }
    red[tid] = s; __syncthreads();
    for (int st = 128; st > 0; st >>= 1) { if (tid < st) red[tid] += red[tid + st]; __syncthreads(); }
    float mu = red[0] * (1.0f / DD); __syncthreads();
    float s2 = 0.f;
    for (int d = tid; d < DD; d += 256) { float dv = xs[d] - mu; s2 += dv * dv; }
    red[tid] = s2; __syncthreads();
    for (int st = 128; st > 0; st >>= 1) { if (tid < st) red[tid] += red[tid + st]; __syncthreads(); }
    float inv = rsqrtf(red[0] * (1.0f / DD) + 1e-12f);
    float m = mask[t];
    for (int d = tid; d < DD; d += 256) {
        float val = ((xs[d] - mu) * inv * w[d] + b[d]) * m;
        out[(size_t)t * DD + d] = val;
        out16[(size_t)t * DD + d] = __float2half_rn(val);
    }
}

// ---------------- bucket table ----------------
__global__ void buckets_kernel(int* __restrict__ tab)
{
    int x = blockIdx.x * blockDim.x + threadIdx.x;
    if (x >= 1023) { if (x == 1023) tab[1023] = 0; return; }
    int rel = x - 511;
    const int mid = 128;
    int ap = (rel < mid && rel > -mid) ? (mid - 1) : (rel < 0 ? -rel : rel);
    int bucket;
    if (ap <= mid) bucket = rel;
    else {
        double lp = ceil(log((double)ap / (double)mid) / log(511.0 / 128.0) * (mid - 1)) + mid;
        int sgn = (rel > 0) - (rel < 0);
        bucket = (int)lp * sgn;
    }
    int c = bucket + 256; c = c < 0 ? 0 : (c > 511 ? 511 : c);
    tab[x] = c;
}

// ---------------- weight convert to k-pair-packed fp16: out[(k2*N+n)*2+j] = in[(2k2+j)*N+n] ----------------
__global__ void __launch_bounds__(256) convert_w(
    const float* __restrict__ in, __half* __restrict__ out,
    int K, int N, size_t lstr_in, size_t lstr_out)
{
    const float* ip = in + (size_t)blockIdx.z * lstr_in;
    __half* op = out + (size_t)blockIdx.z * lstr_out;
    size_t i = (size_t)blockIdx.x * 256 + threadIdx.x;   // < (K/2)*N
    int k2 = (int)(i / N), n = (int)(i % N);
    float a = ip[(size_t)(2 * k2) * N + n];
    float b = ip[(size_t)(2 * k2 + 1) * N + n];
    *(__half2*)(op + i * 2) = __floats2half2_rn(a, b);
}

// ---------------- elementwise fp32 -> fp16 ----------------
__global__ void __launch_bounds__(256) convert_h(
    const float* __restrict__ in, __half* __restrict__ out, size_t n)
{
    size_t i = (size_t)blockIdx.x * 256 + threadIdx.x;
    if (i < n) out[i] = __float2half_rn(in[i]);
}

// ---------------- dense fp16 GEMM core, 128x128 tile, BK=16, 3-stage cp.async ----------------
#define A_STR 12
#define B_STR 136
#define A_STG (128*A_STR)
#define B_STG (8*B_STR)
#define GEMM_SMEM ((A_STG + B_STG) * 3 * 4)

__device__ __forceinline__ void gemm128h_core(
    const __half* __restrict__ A, const __half* __restrict__ Bp,
    const float* __restrict__ bias, void* Cout, int outHalf,
    int m0, int n0, int N, int K, int kStart, int kLen, int act, int useBias)
{
    extern __shared__ unsigned dsm[];
    unsigned* Asm = dsm;
    unsigned* Bsm = dsm + 3 * A_STG;

    int tid = threadIdx.x;
    int w = tid >> 5, lane = tid & 31;
    int lr = lane >> 2, lc = lane & 3;
    int wm = (w >> 2) * 64, wn = (w & 3) * 32;

    int arow = tid >> 1, apart = tid & 1;
    int brow = tid >> 5;

    const __half* abase = A + (size_t)(m0 + arow) * K + kStart + apart * 8;
    const __half* bbase = Bp + ((size_t)(kStart / 2 + brow) * N + n0 + lane * 4) * 2;

    const int kTiles = kLen >> 4;

    #define GISSUE(s, kt) do { \
        unsigned* as_ = Asm + (s) * A_STG; \
        unsigned* bs_ = Bsm + (s) * B_STG; \
        cp16(as_ + arow * A_STR + apart * 4, abase + (size_t)(kt) * 16); \
        cp16(bs_ + brow * B_STR + lane * 4, bbase + (size_t)(kt) * 16 * N); \
    } while (0)

    GISSUE(0, 0); CP_COMMIT;
    GISSUE(1, 1); CP_COMMIT;

    float acc[4][4][4] = {};

    for (int kt = 0; kt < kTiles; kt++) {
        CP_WAIT1;
        __syncthreads();
        if (kt + 2 < kTiles) GISSUE((kt + 2) % 3, kt + 2);
        CP_COMMIT;

        const unsigned* as = Asm + (kt % 3) * A_STG;
        const unsigned* bs = Bsm + (kt % 3) * B_STG;

        unsigned af[4][4], bf[4][2];
        #pragma unroll
        for (int mt = 0; mt < 4; mt++) {
            int m = wm + mt * 16 + lr;
            af[mt][0] = as[m * A_STR + lc];
            af[mt][1] = as[(m + 8) * A_STR + lc];
            af[mt][2] = as[m * A_STR + lc + 4];
            af[mt][3] = as[(m + 8) * A_STR + lc + 4];
        }
        #pragma unroll
        for (int nt = 0; nt < 4; nt++) {
            int n = wn + nt * 8 + lr;
            bf[nt][0] = bs[lc * B_STR + n];
            bf[nt][1] = bs[(lc + 4) * B_STR + n];
        }
        #pragma unroll
        for (int mt = 0; mt < 4; mt++)
            #pragma unroll
            for (int nt = 0; nt < 4; nt++)
                mma_f16(acc[mt][nt], af[mt], bf[nt]);
    }
    #undef GISSUE

    #pragma unroll
    for (int mt = 0; mt < 4; mt++) {
        int r = m0 + wm + mt * 16 + lr;
        #pragma unroll
        for (int nt = 0; nt < 4; nt++) {
            int c = n0 + wn + nt * 8 + lc * 2;
            float bv0 = useBias ? bias[c] : 0.f, bv1 = useBias ? bias[c + 1] : 0.f;
            float v00 = acc[mt][nt][0] + bv0, v01 = acc[mt][nt][1] + bv1;
            float v10 = acc[mt][nt][2] + bv0, v11 = acc[mt][nt][3] + bv1;
            if (act) {
                v00 = 0.5f * v00 * (1.0f + erff(v00 * 0.70710678118654752f));
                v01 = 0.5f * v01 * (1.0f + erff(v01 * 0.70710678118654752f));
                v10 = 0.5f * v10 * (1.0f + erff(v10 * 0.70710678118654752f));
                v11 = 0.5f * v11 * (1.0f + erff(v11 * 0.70710678118654752f));
            }
            if (outHalf) {
                __half* C = (__half*)Cout;
                *(__half2*)(C + (size_t)r * N + c)       = __floats2half2_rn(v00, v01);
                *(__half2*)(C + (size_t)(r + 8) * N + c) = __floats2half2_rn(v10, v11);
            } else {
                float* C = (float*)Cout;
                *(float2*)(C + (size_t)r * N + c)       = make_float2(v00, v01);
                *(float2*)(C + (size_t)(r + 8) * N + c) = make_float2(v10, v11);
            }
        }
    }
}

__global__ void __launch_bounds__(256) gemm_qkv(
    const __half* __restrict__ h16, const __half* __restrict__ wh,
    const float* __restrict__ bq, const float* __restrict__ bk, const float* __restrict__ bv,
    __half* __restrict__ q, __half* __restrict__ k, __half* __restrict__ v)
{
    const int z = blockIdx.z;
    const __half* Bp   = wh + ((z == 0) ? OQ : (z == 1) ? OK : OV);
    const float*  bias = (z == 0) ? bq : (z == 1) ? bk : bv;
    __half*       C    = (z == 0) ? q  : (z == 1) ? k  : v;
    gemm128h_core(h16, Bp, bias, C, 1, blockIdx.y * 128, blockIdx.x * 128, DD, DD, 0, DD, 0, 1);
}

__global__ void __launch_bounds__(256) gemm_pos(
    const __half* __restrict__ rel16, const __half* __restrict__ wh,
    const float* __restrict__ bq, const float* __restrict__ bk,
    __half* __restrict__ posqL, __half* __restrict__ poskL)
{
    const int z = blockIdx.z;
    const int l = z >> 1;
    const int isq = z & 1;
    const __half* Bp   = wh + (size_t)l * LSTR + (isq ? OQ : OK);
    const float*  bias = (isq ? bq : bk) + (size_t)l * DD;
    __half*       C    = (isq ? posqL : poskL) + (size_t)l * PP * DD;
    gemm128h_core(rel16, Bp, bias, C, 1, blockIdx.y * 128, blockIdx.x * 128, DD, DD, 0, DD, 0, 1);
}

__global__ void __launch_bounds__(256) gemm_one(
    const __half* __restrict__ A, const __half* __restrict__ Bp, const float* __restrict__ bias,
    __half* __restrict__ C, int N, int K, int act)
{
    gemm128h_core(A, Bp, bias, C, 1, blockIdx.y * 128, blockIdx.x * 128, N, K, 0, K, act, 1);
}

__global__ void __launch_bounds__(256) gemm_sk(
    const __half* __restrict__ A, const __half* __restrict__ Bp, const float* __restrict__ bias,
    float* __restrict__ C0, float* __restrict__ C1, int N, int K)
{
    const int z = blockIdx.z;
    gemm128h_core(A, Bp, bias, z ? C1 : C0, 0, blockIdx.y * 128, blockIdx.x * 128,
                  N, K, z * (K >> 1), K >> 1, 0, z == 0);
}

// ---------------- fused disentangled score kernel — fp16 inputs, zero-CVT loads ----------------
#define SC_STR 36
#define SCORE_SMEM (16896 * 4)
__global__ void __launch_bounds__(256) score_fused(
    const __half* __restrict__ Q, const __half* __restrict__ Kt,
    const __half* __restrict__ PKg, const __half* __restrict__ PQg,
    const int* __restrict__ tab, const float* __restrict__ mask,
    float* __restrict__ scores, float scale)
{
    int z = blockIdx.z; int b = z / HH, hh = z % HH;
    int m0 = blockIdx.y * 64, n0 = blockIdx.x * 64;
    const __half* Aq = Q  + (size_t)b * SS * DD + hh * DH;
    const __half* Ak = Kt + (size_t)b * SS * DD + hh * DH;
    const __half* PK = PKg + hh * DH;
    const __half* PQ = PQg + hh * DH;

    extern __shared__ unsigned ssm[];
    unsigned* Qs  = ssm;
    unsigned* Ks  = ssm + 2304;
    unsigned* PKs = ssm + 4608;
    unsigned* PQs = ssm + 9216;
    float* C1s = (float*)ssm;
    float* C2s = (float*)(ssm + 8448);

    int tid = threadIdx.x;
    int w = tid >> 5, lane = tid & 31;
    int lr = lane >> 2, lc = lane & 3;
    int wr = w >> 2, wc = w & 3;
    const int dlo = m0 - n0 - 63;

    {
        int row = tid >> 2;
        int colh = (tid & 3) * 16;
        int colu = colh >> 1;
        {
            const __half* p = Aq + (size_t)(m0 + row) * DD + colh;
            *(uint4*)(Qs + row * SC_STR + colu)     = *(const uint4*)p;
            *(uint4*)(Qs + row * SC_STR + colu + 4) = *(const uint4*)(p + 8);
        }
        {
            const __half* p = Ak + (size_t)(n0 + row) * DD + colh;
            *(uint4*)(Ks + row * SC_STR + colu)     = *(const uint4*)p;
            *(uint4*)(Ks + row * SC_STR + colu + 4) = *(const uint4*)(p + 8);
        }
        #pragma unroll
        for (int half_ = 0; half_ < 2; half_++) {
            int t = row + half_ * 64;
            int tt = t < 127 ? t : 126;
            int pidx = tab[dlo + tt + 511];
            const __half* pk = PK + (size_t)pidx * DD + colh;
            *(uint4*)(PKs + t * SC_STR + colu)     = *(const uint4*)pk;
            *(uint4*)(PKs + t * SC_STR + colu + 4) = *(const uint4*)(pk + 8);
            const __half* pq = PQ + (size_t)pidx * DD + colh;
            *(uint4*)(PQs + t * SC_STR + colu)     = *(const uint4*)pq;
            *(uint4*)(PQs + t * SC_STR + colu + 4) = *(const uint4*)(pq + 8);
        }
    }
    __syncthreads();

    float accS[2][2][4] = {};
    float acc1[2][4][4] = {};
    float acc2[2][4][4] = {};

    #pragma unroll
    for (int c = 0; c < 4; c++) {
        int cu = c * 8;
        unsigned aq[2][4], ak[2][4];
        #pragma unroll
        for (int mt = 0; mt < 2; mt++) {
            int m = wr * 32 + mt * 16 + lr;
            aq[mt][0] = Qs[m * SC_STR + cu + lc];       aq[mt][1] = Qs[(m + 8) * SC_STR + cu + lc];
            aq[mt][2] = Qs[m * SC_STR + cu + lc + 4];   aq[mt][3] = Qs[(m + 8) * SC_STR + cu + lc + 4];
            ak[mt][0] = Ks[m * SC_STR + cu + lc];       ak[mt][1] = Ks[(m + 8) * SC_STR + cu + lc];
            ak[mt][2] = Ks[m * SC_STR + cu + lc + 4];   ak[mt][3] = Ks[(m + 8) * SC_STR + cu + lc + 4];
        }
        unsigned bS[2][2], b1[4][2], b2[4][2];
        #pragma unroll
        for (int nt = 0; nt < 2; nt++) {
            int n = wc * 16 + nt * 8 + lr;
            bS[nt][0] = Ks[n * SC_STR + cu + lc];
            bS[nt][1] = Ks[n * SC_STR + cu + lc + 4];
        }
        #pragma unroll
        for (int nt = 0; nt < 4; nt++) {
            int n = wc * 32 + nt * 8 + lr;
            b1[nt][0] = PKs[n * SC_STR + cu + lc];
            b1[nt][1] = PKs[n * SC_STR + cu + lc + 4];
            b2[nt][0] = PQs[n * SC_STR + cu + lc];
            b2[nt][1] = PQs[n * SC_STR + cu + lc + 4];
        }
        #pragma unroll
        for (int mt = 0; mt < 2; mt++) {
            #pragma unroll
            for (int nt = 0; nt < 2; nt++) mma_f16(accS[mt][nt], aq[mt], bS[nt]);
            #pragma unroll
            for (int nt = 0; nt < 4; nt++) { mma_f16(acc1[mt][nt], aq[mt], b1[nt]); mma_f16(acc2[mt][nt], ak[mt], b2[nt]); }
        }
    }
    __syncthreads();

    #pragma unroll
    for (int mt = 0; mt < 2; mt++) {
        int r = wr * 32 + mt * 16 + lr;
        #pragma unroll
        for (int nt = 0; nt < 4; nt++) {
            int c = wc * 32 + nt * 8 + lc * 2;
            C1s[r * 132 + c] = acc1[mt][nt][0]; C1s[r * 132 + c + 1] = acc1[mt][nt][1];
            C1s[(r + 8) * 132 + c] = acc1[mt][nt][2]; C1s[(r + 8) * 132 + c + 1] = acc1[mt][nt][3];
            C2s[r * 132 + c] = acc2[mt][nt][0]; C2s[r * 132 + c + 1] = acc2[mt][nt][1];
            C2s[(r + 8) * 132 + c] = acc2[mt][nt][2]; C2s[(r + 8) * 132 + c + 1] = acc2[mt][nt][3];
        }
    }
    __syncthreads();

    #pragma unroll
    for (int mt = 0; mt < 2; mt++) {
        #pragma unroll
        for (int nt = 0; nt < 2; nt++) {
            int r = wr * 32 + mt * 16 + lr;
            int c0 = wc * 16 + nt * 8 + lc * 2;
            #pragma unroll
            for (int half_ = 0; half_ < 2; half_++) {
                int rr = r + half_ * 8;
                float o[2];
                #pragma unroll
                for (int e = 0; e < 2; e++) {
                    int cc = c0 + e;
                    int t = rr - cc + 63;
                    float val = (accS[mt][nt][half_ * 2 + e] + C1s[rr * 132 + t] + C2s[cc * 132 + t]) * scale;
                    val += (1.0f - mask[b * SS + n0 + cc]) * (-1e9f);
                    o[e] = val;
                }
                *(float2*)(scores + ((size_t)z * SS + m0 + rr) * SS + n0 + c0) = make_float2(o[0], o[1]);
            }
        }
    }
}

// ---------------- row softmax: fp32 logits -> fp16 probs ----------------
__global__ void __launch_bounds__(128) softmax_kernel(
    const float* __restrict__ scores, __half* __restrict__ probs)
{
    int q = blockIdx.x, z = blockIdx.y;
    int t = threadIdx.x;
    int lane = t & 31, wp = t >> 5;
    const float4* row = (const float4*)(scores + ((size_t)z * SS + q) * SS);
    __half* orow = probs + ((size_t)z * SS + q) * SS;

    float4 v = row[t];
    float mx = fmaxf(fmaxf(v.x, v.y), fmaxf(v.z, v.w));
    #pragma unroll
    for (int o = 16; o > 0; o >>= 1) mx = fmaxf(mx, __shfl_xor_sync(0xffffffffu, mx, o));
    __shared__ float sm[4];
    if (lane == 0) sm[wp] = mx;
    __syncthreads();
    mx = fmaxf(fmaxf(sm[0], sm[1]), fmaxf(sm[2], sm[3]));

    float4 e = make_float4(expf(v.x - mx), expf(v.y - mx), expf(v.z - mx), expf(v.w - mx));
    float s = e.x + e.y + e.z + e.w;
    #pragma unroll
    for (int o = 16; o > 0; o >>= 1) s += __shfl_xor_sync(0xffffffffu, s, o);
    __shared__ float sm2[4];
    if (lane == 0) sm2[wp] = s;
    __syncthreads();
    float inv = 1.0f / (sm2[0] + sm2[1] + sm2[2] + sm2[3]);
    *(__half2*)(orow + t * 4)     = __floats2half2_rn(e.x * inv, e.y * inv);
    *(__half2*)(orow + t * 4 + 2) = __floats2half2_rn(e.z * inv, e.w * inv);
}

// ---------------- batched ctx GEMM — fp16 probs/V, PRMT interleave ----------------
#define CTXB_STR 72
#define CTX_SMEM ((2 * (128 * A_STR) + 2 * (8 * CTXB_STR)) * 4)
__global__ void __launch_bounds__(256) ctx_f16(
    const __half* __restrict__ Pm, const __half* __restrict__ V, __half* __restrict__ O)
{
    int z = blockIdx.y; int b = z / HH, hh = z % HH;
    int m0 = blockIdx.x * 128;
    const __half* A = Pm + (size_t)z * SS * SS;
    const __half* Bv = V + (size_t)b * SS * DD + hh * DH;

    extern __shared__ unsigned dsm[];
    unsigned* Asm = dsm;
    unsigned* Bsm = dsm + 2 * 128 * A_STR;

    int tid = threadIdx.x;
    int w = tid >> 5, lane = tid & 31;
    int lr = lane >> 2, lc = lane & 3;
    int wm = (w >> 1) * 32, wn = (w & 1) * 32;

    int arow = tid & 127, apart = tid >> 7;
    int brow2 = (tid >> 4) & 7, bcoln = (tid & 15) * 4;
    bool bload = tid < 128;

    const __half* aptr  = A + (size_t)(m0 + arow) * SS + apart * 8;
    const __half* bptr0 = Bv + (size_t)(2 * brow2) * DD + bcoln;
    const __half* bptr1 = bptr0 + DD;
    const size_t bstep = (size_t)16 * DD;

    const int kTiles = SS / 16;

    uint4 ra = *(const uint4*)aptr;
    uint2 xb0 = make_uint2(0, 0), xb1 = xb0;
    if (bload) { xb0 = *(const uint2*)bptr0; xb1 = *(const uint2*)bptr1; }

    float acc[2][4][4] = {};

    for (int kt = 0; kt < kTiles; kt++) {
        unsigned* as = Asm + (kt & 1) * (128 * A_STR);
        unsigned* bs = Bsm + (kt & 1) * (8 * CTXB_STR);
        *(uint4*)(as + arow * A_STR + apart * 4) = ra;
        if (bload) {
            uint4 o;
            o.x = __byte_perm(xb0.x, xb1.x, 0x5410);
            o.y = __byte_perm(xb0.x, xb1.x, 0x7632);
            o.z = __byte_perm(xb0.y, xb1.y, 0x5410);
            o.w = __byte_perm(xb0.y, xb1.y, 0x7632);
            *(uint4*)(bs + brow2 * CTXB_STR + bcoln) = o;
        }
        __syncthreads();

        if (kt + 1 < kTiles) {
            aptr += 16;
            ra = *(const uint4*)aptr;
            if (bload) {
                bptr0 += bstep; bptr1 += bstep;
                xb0 = *(const uint2*)bptr0;
                xb1 = *(const uint2*)bptr1;
            }
        }

        unsigned af[2][4], bf[4][2];
        #pragma unroll
        for (int mt = 0; mt < 2; mt++) {
            int m = wm + mt * 16 + lr;
            af[mt][0] = as[m * A_STR + lc];
            af[mt][1] = as[(m + 8) * A_STR + lc];
            af[mt][2] = as[m * A_STR + lc + 4];
            af[mt][3] = as[(m + 8) * A_STR + lc + 4];
        }
        #pragma unroll
        for (int nt = 0; nt < 4; nt++) {
            int n = wn + nt * 8 + lr;
            bf[nt][0] = bs[lc * CTXB_STR + n];
            bf[nt][1] = bs[(lc + 4) * CTXB_STR + n];
        }
        #pragma unroll
        for (int mt = 0; mt < 2; mt++)
            #pragma unroll
            for (int nt = 0; nt < 4; nt++)
                mma_f16(acc[mt][nt], af[mt], bf[nt]);
    }

    #pragma unroll
    for (int mt = 0; mt < 2; mt++) {
        int r = m0 + wm + mt * 16 + lr;
        #pragma unroll
        for (int nt = 0; nt < 4; nt++) {
            int c = wn + nt * 8 + lc * 2;
            *(__half2*)(O + ((size_t)b * SS + r) * DD + hh * DH + c)     = __floats2half2_rn(acc[mt][nt][0], acc[mt][nt][1]);
            *(__half2*)(O + ((size_t)b * SS + r + 8) * DD + hh * DH + c) = __floats2half2_rn(acc[mt][nt][2], acc[mt][nt][3]);
        }
    }
}

// ---------------- residual add (two deltas) + LN (dual fp32/fp16 store) ----------------
__global__ void __launch_bounds__(256) add_ln3_kernel(
    float* __restrict__ h, __half* __restrict__ h16,
    const float* __restrict__ d1, const float* __restrict__ d2,
    const float* __restrict__ w, const float* __restrict__ b)
{
    int t = blockIdx.x, tid = threadIdx.x;
    __shared__ float xs[DD];
    __shared__ float red[256];
    float* hr = h + (size_t)t * DD;
    __half* hr16 = h16 + (size_t)t * DD;
    const float* r1 = d1 + (size_t)t * DD;
    const float* r2 = d2 + (size_t)t * DD;

    float s = 0.f;
    for (int d = tid; d < DD; d += 256) { float x = hr[d] + r1[d] + r2[d]; xs[d] = x; s += x; }
    red[tid] = s; __syncthreads();
    for (int st = 128; st > 0; st >>= 1) { if (tid < st) red[tid] += red[tid + st]; __syncthreads(); }
    float mu = red[0] * (1.0f / DD); __syncthreads();
    float s2 = 0.f;
    for (int d = tid; d < DD; d += 256) { float dv = xs[d] - mu; s2 += dv * dv; }
    red[tid] = s2; __syncthreads();
    for (int st = 128; st > 0; st >>= 1) { if (tid < st) red[tid] += red[tid + st]; __syncthreads(); }
    float inv = rsqrtf(red[0] * (1.0f / DD) + 1e-12f);
    for (int d = tid; d < DD; d += 256) {
        float val = (xs[d] - mu) * inv * w[d] + b[d];
        hr[d] = val;
        hr16[d] = __float2half_rn(val);
    }
}

// ---------------- host orchestration ----------------
extern "C" void kernel_launch(void* const* d_in, const int* in_sizes, int n_in,
                              void* d_out, int out_size)
{
    const int*   input_ids   = (const int*)  d_in[0];
    const int*   segment_ids = (const int*)  d_in[1];
    const int*   pinyin_ids  = (const int*)  d_in[2];
    const float* attn_mask   = (const float*)d_in[3];
    const float* tok_emb     = (const float*)d_in[4];
    const float* pin_emb     = (const float*)d_in[5];
    const float* seg_emb     = (const float*)d_in[6];
    const float* emb_ln_w    = (const float*)d_in[7];
    const float* emb_ln_b    = (const float*)d_in[8];
    const float* rel_emb     = (const float*)d_in[9];
    const float* Wq = (const float*)d_in[10]; const float* bq = (const float*)d_in[11];
    const float* Wk = (const float*)d_in[12]; const float* bk = (const float*)d_in[13];
    const float* Wv = (const float*)d_in[14]; const float* bv = (const float*)d_in[15];
    const float* Wo = (const float*)d_in[16]; const float* bo = (const float*)d_in[17];
    const float* ln1w = (const float*)d_in[18]; const float* ln1b = (const float*)d_in[19];
    const float* W1 = (const float*)d_in[20]; const float* b1 = (const float*)d_in[21];
    const float* W2 = (const float*)d_in[22]; const float* b2 = (const float*)d_in[23];
    const float* ln2w = (const float*)d_in[24]; const float* ln2b = (const float*)d_in[25];

    float *h, *s1, *s2, *scores;
    __half *h16, *q16, *k16, *v16, *ctx16, *tmp16, *probs16, *posk16, *posq16, *rel16, *wh;
    int *tab;
    cudaGetSymbolAddress((void**)&h,       g_h);
    cudaGetSymbolAddress((void**)&s1,      g_s1);
    cudaGetSymbolAddress((void**)&s2,      g_s2);
    cudaGetSymbolAddress((void**)&scores,  g_scores);
    cudaGetSymbolAddress((void**)&h16,     g_h16);
    cudaGetSymbolAddress((void**)&q16,     g_q16);
    cudaGetSymbolAddress((void**)&k16,     g_k16);
    cudaGetSymbolAddress((void**)&v16,     g_v16);
    cudaGetSymbolAddress((void**)&ctx16,   g_ctx16);
    cudaGetSymbolAddress((void**)&tmp16,   g_tmp16);
    cudaGetSymbolAddress((void**)&probs16, g_probs16);
    cudaGetSymbolAddress((void**)&posk16,  g_posk16);
    cudaGetSymbolAddress((void**)&posq16,  g_posq16);
    cudaGetSymbolAddress((void**)&rel16,   g_rel16);
    cudaGetSymbolAddress((void**)&wh,      g_wh);
    cudaGetSymbolAddress((void**)&tab,     g_tab);

    cudaFuncSetAttribute(gemm_qkv,    cudaFuncAttributeMaxDynamicSharedMemorySize, GEMM_SMEM);
    cudaFuncSetAttribute(gemm_pos,    cudaFuncAttributeMaxDynamicSharedMemorySize, GEMM_SMEM);
    cudaFuncSetAttribute(gemm_one,    cudaFuncAttributeMaxDynamicSharedMemorySize, GEMM_SMEM);
    cudaFuncSetAttribute(gemm_sk,     cudaFuncAttributeMaxDynamicSharedMemorySize, GEMM_SMEM);
    cudaFuncSetAttribute(ctx_f16,     cudaFuncAttributeMaxDynamicSharedMemorySize, CTX_SMEM);
    cudaFuncSetAttribute(score_fused, cudaFuncAttributeMaxDynamicSharedMemorySize, SCORE_SMEM);

    const float scale = 0.07216878364870323f;  // 1/sqrt(3*DH)

    embed_ln_kernel<<<MM, 256>>>(input_ids, segment_ids, pinyin_ids, attn_mask,
                                 tok_emb, pin_emb, seg_emb, emb_ln_w, emb_ln_b, h, h16);
    buckets_kernel<<<4, 256>>>(tab);
    convert_h<<<(PP * DD + 255) / 256, 256>>>(rel_emb, rel16, (size_t)PP * DD);

    // pack all weights to fp16 k-pair layout (once per call)
    convert_w<<<dim3(1152, 1, LL), 256>>>(Wq, wh + OQ,  DD, DD, (size_t)DD * DD, LSTR);
    convert_w<<<dim3(1152, 1, LL), 256>>>(Wk, wh + OK,  DD, DD, (size_t)DD * DD, LSTR);
    convert_w<<<dim3(1152, 1, LL), 256>>>(Wv, wh + OV,  DD, DD, (size_t)DD * DD, LSTR);
    convert_w<<<dim3(1152, 1, LL), 256>>>(Wo, wh + OO,  DD, DD, (size_t)DD * DD, LSTR);
    convert_w<<<dim3(4608, 1, LL), 256>>>(W1, wh + OW1, DD, FF, (size_t)DD * FF, LSTR);
    convert_w<<<dim3(4608, 1, LL), 256>>>(W2, wh + OW2, FF, DD, (size_t)FF * DD, LSTR);

    // all positional projections upfront
    gemm_pos<<<dim3(DD / 128, PP / 128, 2 * LL), 256, GEMM_SMEM>>>(
        rel16, wh, bq, bk, posq16, posk16);

    for (int i = 0; i < LL; i++) {
        const __half* wl = wh + (size_t)i * LSTR;
        const float* bq_i = bq + (size_t)i * DD;
        const float* bk_i = bk + (size_t)i * DD;
        const float* bv_i = bv + (size_t)i * DD;
        const float* bo_i = bo + (size_t)i * DD;
        const float* b1_i = b1 + (size_t)i * FF;
        const float* b2_i = b2 + (size_t)i * DD;
        const __half* posk_i = posk16 + (size_t)i * PP * DD;
        const __half* posq_i = posq16 + (size_t)i * PP * DD;

        gemm_qkv<<<dim3(DD / 128, MM / 128, 3), 256, GEMM_SMEM>>>(
            h16, wl, bq_i, bk_i, bv_i, q16, k16, v16);

        score_fused<<<dim3(8, 8, BH), 256, SCORE_SMEM>>>(
            q16, k16, posk_i, posq_i, tab, attn_mask, scores, scale);
        softmax_kernel<<<dim3(SS, BH), 128>>>(scores, probs16);
        ctx_f16<<<dim3(SS / 128, BH), 256, CTX_SMEM>>>(probs16, v16, ctx16);

        gemm_sk<<<dim3(DD / 128, MM / 128, 2), 256, GEMM_SMEM>>>(
            ctx16, wl + OO, bo_i, s1, s2, DD, DD);
        add_ln3_kernel<<<MM, 256>>>(h, h16, s1, s2, ln1w + (size_t)i * DD, ln1b + (size_t)i * DD);

        gemm_one<<<dim3(FF / 128, MM / 128), 256, GEMM_SMEM>>>(h16, wl + OW1, b1_i, tmp16, FF, DD, 1);
        gemm_sk<<<dim3(DD / 128, MM / 128, 2), 256, GEMM_SMEM>>>(
            tmp16, wl + OW2, b2_i, s1, s2, DD, FF);
        add_ln3_kernel<<<MM, 256>>>(h, h16, s1, s2, ln2w + (size_t)i * DD, ln2b + (size_t)i * DD);
    }

    cudaMemcpyAsync(d_out, h, sizeof(float) * (size_t)out_size, cudaMemcpyDeviceToDevice);
}

// round 15
// speedup vs baseline: 1.6974x; 1.0420x over previous
#include <cuda_runtime.h>
#include <cuda_bf16.h>
#include <cuda_fp16.h>
#include <math.h>

#define BB 4
#define SS 512
#define DD 768
#define HH 12
#define LL 12
#define FF 3072
#define DH 64
#define PP 512
#define BH (BB*HH)
#define MM (BB*SS)

// fp32 buffers (residual stream)
__device__ __align__(256) float g_h   [MM*DD];
__device__ __align__(256) float g_s1  [MM*DD];
__device__ __align__(256) float g_s2  [MM*DD];
// fp16 buffers
__device__ __align__(256) __half g_scores16[(size_t)BH*SS*SS];   // logits -> probs (in-place)
__device__ __align__(256) __half g_h16 [MM*DD];
__device__ __align__(256) __half g_q16 [MM*DD];
__device__ __align__(256) __half g_k16 [MM*DD];
__device__ __align__(256) __half g_v16 [MM*DD];
__device__ __align__(256) __half g_ctx16[MM*DD];
__device__ __align__(256) __half g_tmp16[MM*FF];
__device__ __align__(256) __half g_posk16[(size_t)LL*PP*DD];
__device__ __align__(256) __half g_posq16[(size_t)LL*PP*DD];
__device__ __align__(256) __half g_rel16[PP*DD];
// k-pair-packed fp16 weights: per layer [Wq|Wk|Wv|Wo|W1|W2]
#define OQ 0
#define OK 589824
#define OV 1179648
#define OO 1769472
#define OW1 2359296
#define OW2 4718592
#define LSTR 7077888
__device__ __align__(256) __half g_wh[(size_t)LL*LSTR];
__device__ int g_tab[1024];

__device__ __forceinline__ unsigned pack2(float lo, float hi) {
    __half2 h = __floats2half2_rn(lo, hi);
    return *reinterpret_cast<unsigned*>(&h);
}
__device__ __forceinline__ void mma_f16(float* d, const unsigned* a, const unsigned* b) {
    asm volatile(
        "mma.sync.aligned.m16n8k16.row.col.f32.f16.f16.f32 "
        "{%0,%1,%2,%3}, {%4,%5,%6,%7}, {%8,%9}, {%0,%1,%2,%3};\n"
        : "+f"(d[0]), "+f"(d[1]), "+f"(d[2]), "+f"(d[3])
        : "r"(a[0]), "r"(a[1]), "r"(a[2]), "r"(a[3]), "r"(b[0]), "r"(b[1]));
}
__device__ __forceinline__ void cp16(void* smem, const void* gmem) {
    unsigned sa = (unsigned)__cvta_generic_to_shared(smem);
    asm volatile("cp.async.cg.shared.global [%0], [%1], 16;" :: "r"(sa), "l"(gmem));
}
#define CP_COMMIT asm volatile("cp.async.commit_group;")
#define CP_WAIT1  asm volatile("cp.async.wait_group 1;")

// ---------------- embeddings + LN + mask (dual fp32/fp16 store) ----------------
__global__ void __launch_bounds__(256) embed_ln_kernel(
    const int* __restrict__ ids, const int* __restrict__ segs, const int* __restrict__ pins,
    const float* __restrict__ mask,
    const float* __restrict__ tok, const float* __restrict__ pin, const float* __restrict__ seg,
    const float* __restrict__ w, const float* __restrict__ b,
    float* __restrict__ out, __half* __restrict__ out16)
{
    int t = blockIdx.x, tid = threadIdx.x;
    __shared__ float xs[DD];
    __shared__ float red[256];
    size_t io = (size_t)ids[t] * DD, po = (size_t)pins[t] * DD, so = (size_t)segs[t] * DD;
    float s = 0.f;
    for (int d = tid; d < DD; d += 256) {
        float x = tok[io + d] + pin[po + d] + seg[so + d];
        xs[d] = x; s += x;
    }
    red[tid] = s; __syncthreads();
    for (int st = 128; st > 0; st >>= 1) { if (tid < st) red[tid] += red[tid + st]; __syncthreads(); }
    float mu = red[0] * (1.0f / DD); __syncthreads();
    float s2 = 0.f;
    for (int d = tid; d < DD; d += 256) { float dv = xs[d] - mu; s2 += dv * dv; }
    red[tid] = s2; __syncthreads();
    for (int st = 128; st > 0; st >>= 1) { if (tid < st) red[tid] += red[tid + st]; __syncthreads(); }
    float inv = rsqrtf(red[0] * (1.0f / DD) + 1e-12f);
    float m = mask[t];
    for (int d = tid; d < DD; d += 256) {
        float val = ((xs[d] - mu) * inv * w[d] + b[d]) * m;
        out[(size_t)t * DD + d] = val;
        out16[(size_t)t * DD + d] = __float2half_rn(val);
    }
}

// ---------------- bucket table ----------------
__global__ void buckets_kernel(int* __restrict__ tab)
{
    int x = blockIdx.x * blockDim.x + threadIdx.x;
    if (x >= 1023) { if (x == 1023) tab[1023] = 0; return; }
    int rel = x - 511;
    const int mid = 128;
    int ap = (rel < mid && rel > -mid) ? (mid - 1) : (rel < 0 ? -rel : rel);
    int bucket;
    if (ap <= mid) bucket = rel;
    else {
        double lp = ceil(log((double)ap / (double)mid) / log(511.0 / 128.0) * (mid - 1)) + mid;
        int sgn = (rel > 0) - (rel < 0);
        bucket = (int)lp * sgn;
    }
    int c = bucket + 256; c = c < 0 ? 0 : (c > 511 ? 511 : c);
    tab[x] = c;
}

// ---------------- weight convert (vectorized): k-pair-packed fp16 ----------------
// thread handles 4 n-cols of one k-pair: 2x float4 reads, 1x uint4 write.
__global__ void __launch_bounds__(256) convert_w(
    const float* __restrict__ in, __half* __restrict__ out,
    int N4, int N, size_t lstr_in, size_t lstr_out)
{
    const float* ip = in + (size_t)blockIdx.z * lstr_in;
    __half* op = out + (size_t)blockIdx.z * lstr_out;
    size_t i = (size_t)blockIdx.x * 256 + threadIdx.x;   // over (K/2)*(N/4)
    int k2 = (int)(i / N4), n4 = (int)(i % N4) * 4;
    const float* r0 = ip + (size_t)(2 * k2) * N + n4;
    float4 a = *(const float4*)r0;
    float4 b = *(const float4*)(r0 + N);
    uint4 o = make_uint4(pack2(a.x, b.x), pack2(a.y, b.y), pack2(a.z, b.z), pack2(a.w, b.w));
    *(uint4*)(op + ((size_t)k2 * N + n4) * 2) = o;
}

// ---------------- elementwise fp32 -> fp16 ----------------
__global__ void __launch_bounds__(256) convert_h(
    const float* __restrict__ in, __half* __restrict__ out, size_t n)
{
    size_t i = (size_t)blockIdx.x * 256 + threadIdx.x;
    if (i < n) out[i] = __float2half_rn(in[i]);
}

// ---------------- dense fp16 GEMM core, 128x128 tile, BK=16, 3-stage cp.async ----------------
#define A_STR 12
#define B_STR 136
#define A_STG (128*A_STR)
#define B_STG (8*B_STR)
#define GEMM_SMEM ((A_STG + B_STG) * 3 * 4)

__device__ __forceinline__ void gemm128h_core(
    const __half* __restrict__ A, const __half* __restrict__ Bp,
    const float* __restrict__ bias, void* Cout, int outHalf,
    int m0, int n0, int N, int K, int kStart, int kLen, int act, int useBias)
{
    extern __shared__ unsigned dsm[];
    unsigned* Asm = dsm;
    unsigned* Bsm = dsm + 3 * A_STG;

    int tid = threadIdx.x;
    int w = tid >> 5, lane = tid & 31;
    int lr = lane >> 2, lc = lane & 3;
    int wm = (w >> 2) * 64, wn = (w & 3) * 32;

    int arow = tid >> 1, apart = tid & 1;
    int brow = tid >> 5;

    const __half* abase = A + (size_t)(m0 + arow) * K + kStart + apart * 8;
    const __half* bbase = Bp + ((size_t)(kStart / 2 + brow) * N + n0 + lane * 4) * 2;

    const int kTiles = kLen >> 4;

    #define GISSUE(s, kt) do { \
        unsigned* as_ = Asm + (s) * A_STG; \
        unsigned* bs_ = Bsm + (s) * B_STG; \
        cp16(as_ + arow * A_STR + apart * 4, abase + (size_t)(kt) * 16); \
        cp16(bs_ + brow * B_STR + lane * 4, bbase + (size_t)(kt) * 16 * N); \
    } while (0)

    GISSUE(0, 0); CP_COMMIT;
    GISSUE(1, 1); CP_COMMIT;

    float acc[4][4][4] = {};

    for (int kt = 0; kt < kTiles; kt++) {
        CP_WAIT1;
        __syncthreads();
        if (kt + 2 < kTiles) GISSUE((kt + 2) % 3, kt + 2);
        CP_COMMIT;

        const unsigned* as = Asm + (kt % 3) * A_STG;
        const unsigned* bs = Bsm + (kt % 3) * B_STG;

        unsigned af[4][4], bf[4][2];
        #pragma unroll
        for (int mt = 0; mt < 4; mt++) {
            int m = wm + mt * 16 + lr;
            af[mt][0] = as[m * A_STR + lc];
            af[mt][1] = as[(m + 8) * A_STR + lc];
            af[mt][2] = as[m * A_STR + lc + 4];
            af[mt][3] = as[(m + 8) * A_STR + lc + 4];
        }
        #pragma unroll
        for (int nt = 0; nt < 4; nt++) {
            int n = wn + nt * 8 + lr;
            bf[nt][0] = bs[lc * B_STR + n];
            bf[nt][1] = bs[(lc + 4) * B_STR + n];
        }
        #pragma unroll
        for (int mt = 0; mt < 4; mt++)
            #pragma unroll
            for (int nt = 0; nt < 4; nt++)
                mma_f16(acc[mt][nt], af[mt], bf[nt]);
    }
    #undef GISSUE

    #pragma unroll
    for (int mt = 0; mt < 4; mt++) {
        int r = m0 + wm + mt * 16 + lr;
        #pragma unroll
        for (int nt = 0; nt < 4; nt++) {
            int c = n0 + wn + nt * 8 + lc * 2;
            float bv0 = useBias ? bias[c] : 0.f, bv1 = useBias ? bias[c + 1] : 0.f;
            float v00 = acc[mt][nt][0] + bv0, v01 = acc[mt][nt][1] + bv1;
            float v10 = acc[mt][nt][2] + bv0, v11 = acc[mt][nt][3] + bv1;
            if (act) {
                v00 = 0.5f * v00 * (1.0f + erff(v00 * 0.70710678118654752f));
                v01 = 0.5f * v01 * (1.0f + erff(v01 * 0.70710678118654752f));
                v10 = 0.5f * v10 * (1.0f + erff(v10 * 0.70710678118654752f));
                v11 = 0.5f * v11 * (1.0f + erff(v11 * 0.70710678118654752f));
            }
            if (outHalf) {
                __half* C = (__half*)Cout;
                *(__half2*)(C + (size_t)r * N + c)       = __floats2half2_rn(v00, v01);
                *(__half2*)(C + (size_t)(r + 8) * N + c) = __floats2half2_rn(v10, v11);
            } else {
                float* C = (float*)Cout;
                *(float2*)(C + (size_t)r * N + c)       = make_float2(v00, v01);
                *(float2*)(C + (size_t)(r + 8) * N + c) = make_float2(v10, v11);
            }
        }
    }
}

__global__ void __launch_bounds__(256) gemm_qkv(
    const __half* __restrict__ h16, const __half* __restrict__ wh,
    const float* __restrict__ bq, const float* __restrict__ bk, const float* __restrict__ bv,
    __half* __restrict__ q, __half* __restrict__ k, __half* __restrict__ v)
{
    const int z = blockIdx.z;
    const __half* Bp   = wh + ((z == 0) ? OQ : (z == 1) ? OK : OV);
    const float*  bias = (z == 0) ? bq : (z == 1) ? bk : bv;
    __half*       C    = (z == 0) ? q  : (z == 1) ? k  : v;
    gemm128h_core(h16, Bp, bias, C, 1, blockIdx.y * 128, blockIdx.x * 128, DD, DD, 0, DD, 0, 1);
}

__global__ void __launch_bounds__(256) gemm_pos(
    const __half* __restrict__ rel16, const __half* __restrict__ wh,
    const float* __restrict__ bq, const float* __restrict__ bk,
    __half* __restrict__ posqL, __half* __restrict__ poskL)
{
    const int z = blockIdx.z;
    const int l = z >> 1;
    const int isq = z & 1;
    const __half* Bp   = wh + (size_t)l * LSTR + (isq ? OQ : OK);
    const float*  bias = (isq ? bq : bk) + (size_t)l * DD;
    __half*       C    = (isq ? posqL : poskL) + (size_t)l * PP * DD;
    gemm128h_core(rel16, Bp, bias, C, 1, blockIdx.y * 128, blockIdx.x * 128, DD, DD, 0, DD, 0, 1);
}

__global__ void __launch_bounds__(256) gemm_one(
    const __half* __restrict__ A, const __half* __restrict__ Bp, const float* __restrict__ bias,
    __half* __restrict__ C, int N, int K, int act)
{
    gemm128h_core(A, Bp, bias, C, 1, blockIdx.y * 128, blockIdx.x * 128, N, K, 0, K, act, 1);
}

__global__ void __launch_bounds__(256) gemm_sk(
    const __half* __restrict__ A, const __half* __restrict__ Bp, const float* __restrict__ bias,
    float* __restrict__ C0, float* __restrict__ C1, int N, int K)
{
    const int z = blockIdx.z;
    gemm128h_core(A, Bp, bias, z ? C1 : C0, 0, blockIdx.y * 128, blockIdx.x * 128,
                  N, K, z * (K >> 1), K >> 1, 0, z == 0);
}

// ---------------- fused disentangled score kernel — fp16 in/out ----------------
#define SC_STR 36
#define SCORE_SMEM (16896 * 4)
__global__ void __launch_bounds__(256) score_fused(
    const __half* __restrict__ Q, const __half* __restrict__ Kt,
    const __half* __restrict__ PKg, const __half* __restrict__ PQg,
    const int* __restrict__ tab, const float* __restrict__ mask,
    __half* __restrict__ scores, float scale)
{
    int z = blockIdx.z; int b = z / HH, hh = z % HH;
    int m0 = blockIdx.y * 64, n0 = blockIdx.x * 64;
    const __half* Aq = Q  + (size_t)b * SS * DD + hh * DH;
    const __half* Ak = Kt + (size_t)b * SS * DD + hh * DH;
    const __half* PK = PKg + hh * DH;
    const __half* PQ = PQg + hh * DH;

    extern __shared__ unsigned ssm[];
    unsigned* Qs  = ssm;
    unsigned* Ks  = ssm + 2304;
    unsigned* PKs = ssm + 4608;
    unsigned* PQs = ssm + 9216;
    float* C1s = (float*)ssm;
    float* C2s = (float*)(ssm + 8448);

    int tid = threadIdx.x;
    int w = tid >> 5, lane = tid & 31;
    int lr = lane >> 2, lc = lane & 3;
    int wr = w >> 2, wc = w & 3;
    const int dlo = m0 - n0 - 63;

    {
        int row = tid >> 2;
        int colh = (tid & 3) * 16;
        int colu = colh >> 1;
        {
            const __half* p = Aq + (size_t)(m0 + row) * DD + colh;
            *(uint4*)(Qs + row * SC_STR + colu)     = *(const uint4*)p;
            *(uint4*)(Qs + row * SC_STR + colu + 4) = *(const uint4*)(p + 8);
        }
        {
            const __half* p = Ak + (size_t)(n0 + row) * DD + colh;
            *(uint4*)(Ks + row * SC_STR + colu)     = *(const uint4*)p;
            *(uint4*)(Ks + row * SC_STR + colu + 4) = *(const uint4*)(p + 8);
        }
        #pragma unroll
        for (int half_ = 0; half_ < 2; half_++) {
            int t = row + half_ * 64;
            int tt = t < 127 ? t : 126;
            int pidx = tab[dlo + tt + 511];
            const __half* pk = PK + (size_t)pidx * DD + colh;
            *(uint4*)(PKs + t * SC_STR + colu)     = *(const uint4*)pk;
            *(uint4*)(PKs + t * SC_STR + colu + 4) = *(const uint4*)(pk + 8);
            const __half* pq = PQ + (size_t)pidx * DD + colh;
            *(uint4*)(PQs + t * SC_STR + colu)     = *(const uint4*)pq;
            *(uint4*)(PQs + t * SC_STR + colu + 4) = *(const uint4*)(pq + 8);
        }
    }
    __syncthreads();

    float accS[2][2][4] = {};
    float acc1[2][4][4] = {};
    float acc2[2][4][4] = {};

    #pragma unroll
    for (int c = 0; c < 4; c++) {
        int cu = c * 8;
        unsigned aq[2][4], ak[2][4];
        #pragma unroll
        for (int mt = 0; mt < 2; mt++) {
            int m = wr * 32 + mt * 16 + lr;
            aq[mt][0] = Qs[m * SC_STR + cu + lc];       aq[mt][1] = Qs[(m + 8) * SC_STR + cu + lc];
            aq[mt][2] = Qs[m * SC_STR + cu + lc + 4];   aq[mt][3] = Qs[(m + 8) * SC_STR + cu + lc + 4];
            ak[mt][0] = Ks[m * SC_STR + cu + lc];       ak[mt][1] = Ks[(m + 8) * SC_STR + cu + lc];
            ak[mt][2] = Ks[m * SC_STR + cu + lc + 4];   ak[mt][3] = Ks[(m + 8) * SC_STR + cu + lc + 4];
        }
        unsigned bS[2][2], b1[4][2], b2[4][2];
        #pragma unroll
        for (int nt = 0; nt < 2; nt++) {
            int n = wc * 16 + nt * 8 + lr;
            bS[nt][0] = Ks[n * SC_STR + cu + lc];
            bS[nt][1] = Ks[n * SC_STR + cu + lc + 4];
        }
        #pragma unroll
        for (int nt = 0; nt < 4; nt++) {
            int n = wc * 32 + nt * 8 + lr;
            b1[nt][0] = PKs[n * SC_STR + cu + lc];
            b1[nt][1] = PKs[n * SC_STR + cu + lc + 4];
            b2[nt][0] = PQs[n * SC_STR + cu + lc];
            b2[nt][1] = PQs[n * SC_STR + cu + lc + 4];
        }
        #pragma unroll
        for (int mt = 0; mt < 2; mt++) {
            #pragma unroll
            for (int nt = 0; nt < 2; nt++) mma_f16(accS[mt][nt], aq[mt], bS[nt]);
            #pragma unroll
            for (int nt = 0; nt < 4; nt++) { mma_f16(acc1[mt][nt], aq[mt], b1[nt]); mma_f16(acc2[mt][nt], ak[mt], b2[nt]); }
        }
    }
    __syncthreads();

    #pragma unroll
    for (int mt = 0; mt < 2; mt++) {
        int r = wr * 32 + mt * 16 + lr;
        #pragma unroll
        for (int nt = 0; nt < 4; nt++) {
            int c = wc * 32 + nt * 8 + lc * 2;
            C1s[r * 132 + c] = acc1[mt][nt][0]; C1s[r * 132 + c + 1] = acc1[mt][nt][1];
            C1s[(r + 8) * 132 + c] = acc1[mt][nt][2]; C1s[(r + 8) * 132 + c + 1] = acc1[mt][nt][3];
            C2s[r * 132 + c] = acc2[mt][nt][0]; C2s[r * 132 + c + 1] = acc2[mt][nt][1];
            C2s[(r + 8) * 132 + c] = acc2[mt][nt][2]; C2s[(r + 8) * 132 + c + 1] = acc2[mt][nt][3];
        }
    }
    __syncthreads();

    #pragma unroll
    for (int mt = 0; mt < 2; mt++) {
        #pragma unroll
        for (int nt = 0; nt < 2; nt++) {
            int r = wr * 32 + mt * 16 + lr;
            int c0 = wc * 16 + nt * 8 + lc * 2;
            #pragma unroll
            for (int half_ = 0; half_ < 2; half_++) {
                int rr = r + half_ * 8;
                float o[2];
                #pragma unroll
                for (int e = 0; e < 2; e++) {
                    int cc = c0 + e;
                    int t = rr - cc + 63;
                    float val = (accS[mt][nt][half_ * 2 + e] + C1s[rr * 132 + t] + C2s[cc * 132 + t]) * scale;
                    val += (1.0f - mask[b * SS + n0 + cc]) * (-1e9f);
                    o[e] = fmaxf(val, -60000.0f);   // keep fp16-finite; exp() of this is 0 anyway
                }
                *(__half2*)(scores + ((size_t)z * SS + m0 + rr) * SS + n0 + c0) = __floats2half2_rn(o[0], o[1]);
            }
        }
    }
}

// ---------------- row softmax: fp16 logits -> fp16 probs (in-place) ----------------
__global__ void __launch_bounds__(128) softmax_kernel(__half* __restrict__ scores)
{
    int q = blockIdx.x, z = blockIdx.y;
    int t = threadIdx.x;
    int lane = t & 31, wp = t >> 5;
    __half* row = scores + ((size_t)z * SS + q) * SS;

    uint2 raw = *(const uint2*)(row + t * 4);
    float2 a = __half22float2(*reinterpret_cast<__half2*>(&raw.x));
    float2 bb = __half22float2(*reinterpret_cast<__half2*>(&raw.y));
    float4 v = make_float4(a.x, a.y, bb.x, bb.y);

    float mx = fmaxf(fmaxf(v.x, v.y), fmaxf(v.z, v.w));
    #pragma unroll
    for (int o = 16; o > 0; o >>= 1) mx = fmaxf(mx, __shfl_xor_sync(0xffffffffu, mx, o));
    __shared__ float sm[4];
    if (lane == 0) sm[wp] = mx;
    __syncthreads();
    mx = fmaxf(fmaxf(sm[0], sm[1]), fmaxf(sm[2], sm[3]));

    float4 e = make_float4(expf(v.x - mx), expf(v.y - mx), expf(v.z - mx), expf(v.w - mx));
    float s = e.x + e.y + e.z + e.w;
    #pragma unroll
    for (int o = 16; o > 0; o >>= 1) s += __shfl_xor_sync(0xffffffffu, s, o);
    __shared__ float sm2[4];
    if (lane == 0) sm2[wp] = s;
    __syncthreads();
    float inv = 1.0f / (sm2[0] + sm2[1] + sm2[2] + sm2[3]);
    uint2 ow;
    ow.x = pack2(e.x * inv, e.y * inv);
    ow.y = pack2(e.z * inv, e.w * inv);
    *(uint2*)(row + t * 4) = ow;
}

// ---------------- batched ctx GEMM — fp16 probs/V ----------------
#define CTXB_STR 72
#define CTX_SMEM ((2 * (128 * A_STR) + 2 * (8 * CTXB_STR)) * 4)
__global__ void __launch_bounds__(256) ctx_f16(
    const __half* __restrict__ Pm, const __half* __restrict__ V, __half* __restrict__ O)
{
    int z = blockIdx.y; int b = z / HH, hh = z % HH;
    int m0 = blockIdx.x * 128;
    const __half* A = Pm + (size_t)z * SS * SS;
    const __half* Bv = V + (size_t)b * SS * DD + hh * DH;

    extern __shared__ unsigned dsm[];
    unsigned* Asm = dsm;
    unsigned* Bsm = dsm + 2 * 128 * A_STR;

    int tid = threadIdx.x;
    int w = tid >> 5, lane = tid & 31;
    int lr = lane >> 2, lc = lane & 3;
    int wm = (w >> 1) * 32, wn = (w & 1) * 32;

    int arow = tid & 127, apart = tid >> 7;
    int brow2 = (tid >> 4) & 7, bcoln = (tid & 15) * 4;
    bool bload = tid < 128;

    const __half* aptr  = A + (size_t)(m0 + arow) * SS + apart * 8;
    const __half* bptr0 = Bv + (size_t)(2 * brow2) * DD + bcoln;
    const __half* bptr1 = bptr0 + DD;
    const size_t bstep = (size_t)16 * DD;

    const int kTiles = SS / 16;

    uint4 ra = *(const uint4*)aptr;
    uint2 xb0 = make_uint2(0, 0), xb1 = xb0;
    if (bload) { xb0 = *(const uint2*)bptr0; xb1 = *(const uint2*)bptr1; }

    float acc[2][4][4] = {};

    for (int kt = 0; kt < kTiles; kt++) {
        unsigned* as = Asm + (kt & 1) * (128 * A_STR);
        unsigned* bs = Bsm + (kt & 1) * (8 * CTXB_STR);
        *(uint4*)(as + arow * A_STR + apart * 4) = ra;
        if (bload) {
            uint4 o;
            o.x = __byte_perm(xb0.x, xb1.x, 0x5410);
            o.y = __byte_perm(xb0.x, xb1.x, 0x7632);
            o.z = __byte_perm(xb0.y, xb1.y, 0x5410);
            o.w = __byte_perm(xb0.y, xb1.y, 0x7632);
            *(uint4*)(bs + brow2 * CTXB_STR + bcoln) = o;
        }
        __syncthreads();

        if (kt + 1 < kTiles) {
            aptr += 16;
            ra = *(const uint4*)aptr;
            if (bload) {
                bptr0 += bstep; bptr1 += bstep;
                xb0 = *(const uint2*)bptr0;
                xb1 = *(const uint2*)bptr1;
            }
        }

        unsigned af[2][4], bf[4][2];
        #pragma unroll
        for (int mt = 0; mt < 2; mt++) {
            int m = wm + mt * 16 + lr;
            af[mt][0] = as[m * A_STR + lc];
            af[mt][1] = as[(m + 8) * A_STR + lc];
            af[mt][2] = as[m * A_STR + lc + 4];
            af[mt][3] = as[(m + 8) * A_STR + lc + 4];
        }
        #pragma unroll
        for (int nt = 0; nt < 4; nt++) {
            int n = wn + nt * 8 + lr;
            bf[nt][0] = bs[lc * CTXB_STR + n];
            bf[nt][1] = bs[(lc + 4) * CTXB_STR + n];
        }
        #pragma unroll
        for (int mt = 0; mt < 2; mt++)
            #pragma unroll
            for (int nt = 0; nt < 4; nt++)
                mma_f16(acc[mt][nt], af[mt], bf[nt]);
    }

    #pragma unroll
    for (int mt = 0; mt < 2; mt++) {
        int r = m0 + wm + mt * 16 + lr;
        #pragma unroll
        for (int nt = 0; nt < 4; nt++) {
            int c = wn + nt * 8 + lc * 2;
            *(__half2*)(O + ((size_t)b * SS + r) * DD + hh * DH + c)     = __floats2half2_rn(acc[mt][nt][0], acc[mt][nt][1]);
            *(__half2*)(O + ((size_t)b * SS + r + 8) * DD + hh * DH + c) = __floats2half2_rn(acc[mt][nt][2], acc[mt][nt][3]);
        }
    }
}

// ---------------- residual add (two deltas) + LN (dual fp32/fp16 store) ----------------
__global__ void __launch_bounds__(256) add_ln3_kernel(
    float* __restrict__ h, __half* __restrict__ h16,
    const float* __restrict__ d1, const float* __restrict__ d2,
    const float* __restrict__ w, const float* __restrict__ b)
{
    int t = blockIdx.x, tid = threadIdx.x;
    __shared__ float xs[DD];
    __shared__ float red[256];
    float* hr = h + (size_t)t * DD;
    __half* hr16 = h16 + (size_t)t * DD;
    const float* r1 = d1 + (size_t)t * DD;
    const float* r2 = d2 + (size_t)t * DD;

    float s = 0.f;
    for (int d = tid; d < DD; d += 256) { float x = hr[d] + r1[d] + r2[d]; xs[d] = x; s += x; }
    red[tid] = s; __syncthreads();
    for (int st = 128; st > 0; st >>= 1) { if (tid < st) red[tid] += red[tid + st]; __syncthreads(); }
    float mu = red[0] * (1.0f / DD); __syncthreads();
    float s2 = 0.f;
    for (int d = tid; d < DD; d += 256) { float dv = xs[d] - mu; s2 += dv * dv; }
    red[tid] = s2; __syncthreads();
    for (int st = 128; st > 0; st >>= 1) { if (tid < st) red[tid] += red[tid + st]; __syncthreads(); }
    float inv = rsqrtf(red[0] * (1.0f / DD) + 1e-12f);
    for (int d = tid; d < DD; d += 256) {
        float val = (xs[d] - mu) * inv * w[d] + b[d];
        hr[d] = val;
        hr16[d] = __float2half_rn(val);
    }
}

// ---------------- host orchestration ----------------
extern "C" void kernel_launch(void* const* d_in, const int* in_sizes, int n_in,
                              void* d_out, int out_size)
{
    const int*   input_ids   = (const int*)  d_in[0];
    const int*   segment_ids = (const int*)  d_in[1];
    const int*   pinyin_ids  = (const int*)  d_in[2];
    const float* attn_mask   = (const float*)d_in[3];
    const float* tok_emb     = (const float*)d_in[4];
    const float* pin_emb     = (const float*)d_in[5];
    const float* seg_emb     = (const float*)d_in[6];
    const float* emb_ln_w    = (const float*)d_in[7];
    const float* emb_ln_b    = (const float*)d_in[8];
    const float* rel_emb     = (const float*)d_in[9];
    const float* Wq = (const float*)d_in[10]; const float* bq = (const float*)d_in[11];
    const float* Wk = (const float*)d_in[12]; const float* bk = (const float*)d_in[13];
    const float* Wv = (const float*)d_in[14]; const float* bv = (const float*)d_in[15];
    const float* Wo = (const float*)d_in[16]; const float* bo = (const float*)d_in[17];
    const float* ln1w = (const float*)d_in[18]; const float* ln1b = (const float*)d_in[19];
    const float* W1 = (const float*)d_in[20]; const float* b1 = (const float*)d_in[21];
    const float* W2 = (const float*)d_in[22]; const float* b2 = (const float*)d_in[23];
    const float* ln2w = (const float*)d_in[24]; const float* ln2b = (const float*)d_in[25];

    float *h, *s1, *s2;
    __half *scores16, *h16, *q16, *k16, *v16, *ctx16, *tmp16, *posk16, *posq16, *rel16, *wh;
    int *tab;
    cudaGetSymbolAddress((void**)&h,        g_h);
    cudaGetSymbolAddress((void**)&s1,       g_s1);
    cudaGetSymbolAddress((void**)&s2,       g_s2);
    cudaGetSymbolAddress((void**)&scores16, g_scores16);
    cudaGetSymbolAddress((void**)&h16,      g_h16);
    cudaGetSymbolAddress((void**)&q16,      g_q16);
    cudaGetSymbolAddress((void**)&k16,      g_k16);
    cudaGetSymbolAddress((void**)&v16,      g_v16);
    cudaGetSymbolAddress((void**)&ctx16,    g_ctx16);
    cudaGetSymbolAddress((void**)&tmp16,    g_tmp16);
    cudaGetSymbolAddress((void**)&posk16,   g_posk16);
    cudaGetSymbolAddress((void**)&posq16,   g_posq16);
    cudaGetSymbolAddress((void**)&rel16,    g_rel16);
    cudaGetSymbolAddress((void**)&wh,       g_wh);
    cudaGetSymbolAddress((void**)&tab,      g_tab);

    cudaFuncSetAttribute(gemm_qkv,    cudaFuncAttributeMaxDynamicSharedMemorySize, GEMM_SMEM);
    cudaFuncSetAttribute(gemm_pos,    cudaFuncAttributeMaxDynamicSharedMemorySize, GEMM_SMEM);
    cudaFuncSetAttribute(gemm_one,    cudaFuncAttributeMaxDynamicSharedMemorySize, GEMM_SMEM);
    cudaFuncSetAttribute(gemm_sk,     cudaFuncAttributeMaxDynamicSharedMemorySize, GEMM_SMEM);
    cudaFuncSetAttribute(ctx_f16,     cudaFuncAttributeMaxDynamicSharedMemorySize, CTX_SMEM);
    cudaFuncSetAttribute(score_fused, cudaFuncAttributeMaxDynamicSharedMemorySize, SCORE_SMEM);

    const float scale = 0.07216878364870323f;  // 1/sqrt(3*DH)

    embed_ln_kernel<<<MM, 256>>>(input_ids, segment_ids, pinyin_ids, attn_mask,
                                 tok_emb, pin_emb, seg_emb, emb_ln_w, emb_ln_b, h, h16);
    buckets_kernel<<<4, 256>>>(tab);
    convert_h<<<(PP * DD + 255) / 256, 256>>>(rel_emb, rel16, (size_t)PP * DD);

    // pack all weights to fp16 k-pair layout (vectorized, once per call)
    convert_w<<<dim3(288,  1, LL), 256>>>(Wq, wh + OQ,  DD / 4, DD, (size_t)DD * DD, LSTR);
    convert_w<<<dim3(288,  1, LL), 256>>>(Wk, wh + OK,  DD / 4, DD, (size_t)DD * DD, LSTR);
    convert_w<<<dim3(288,  1, LL), 256>>>(Wv, wh + OV,  DD / 4, DD, (size_t)DD * DD, LSTR);
    convert_w<<<dim3(288,  1, LL), 256>>>(Wo, wh + OO,  DD / 4, DD, (size_t)DD * DD, LSTR);
    convert_w<<<dim3(1152, 1, LL), 256>>>(W1, wh + OW1, FF / 4, FF, (size_t)DD * FF, LSTR);
    convert_w<<<dim3(1152, 1, LL), 256>>>(W2, wh + OW2, DD / 4, DD, (size_t)FF * DD, LSTR);

    // all positional projections upfront
    gemm_pos<<<dim3(DD / 128, PP / 128, 2 * LL), 256, GEMM_SMEM>>>(
        rel16, wh, bq, bk, posq16, posk16);

    for (int i = 0; i < LL; i++) {
        const __half* wl = wh + (size_t)i * LSTR;
        const float* bq_i = bq + (size_t)i * DD;
        const float* bk_i = bk + (size_t)i * DD;
        const float* bv_i = bv + (size_t)i * DD;
        const float* bo_i = bo + (size_t)i * DD;
        const float* b1_i = b1 + (size_t)i * FF;
        const float* b2_i = b2 + (size_t)i * DD;
        const __half* posk_i = posk16 + (size_t)i * PP * DD;
        const __half* posq_i = posq16 + (size_t)i * PP * DD;

        gemm_qkv<<<dim3(DD / 128, MM / 128, 3), 256, GEMM_SMEM>>>(
            h16, wl, bq_i, bk_i, bv_i, q16, k16, v16);

        score_fused<<<dim3(8, 8, BH), 256, SCORE_SMEM>>>(
            q16, k16, posk_i, posq_i, tab, attn_mask, scores16, scale);
        softmax_kernel<<<dim3(SS, BH), 128>>>(scores16);
        ctx_f16<<<dim3(SS / 128, BH), 256, CTX_SMEM>>>(scores16, v16, ctx16);

        gemm_sk<<<dim3(DD / 128, MM / 128, 2), 256, GEMM_SMEM>>>(
            ctx16, wl + OO, bo_i, s1, s2, DD, DD);
        add_ln3_kernel<<<MM, 256>>>(h, h16, s1, s2, ln1w + (size_t)i * DD, ln1b + (size_t)i * DD);

        gemm_one<<<dim3(FF / 128, MM / 128), 256, GEMM_SMEM>>>(h16, wl + OW1, b1_i, tmp16, FF, DD, 1);
        gemm_sk<<<dim3(DD / 128, MM / 128, 2), 256, GEMM_SMEM>>>(
            tmp16, wl + OW2, b2_i, s1, s2, DD, FF);
        add_ln3_kernel<<<MM, 256>>>(h, h16, s1, s2, ln2w + (size_t)i * DD, ln2b + (size_t)i * DD);
    }

    cudaMemcpyAsync(d_out, h, sizeof(float) * (size_t)out_size, cudaMemcpyDeviceToDevice);
}

// round 16
// speedup vs baseline: 1.7447x; 1.0278x over previous
#include <cuda_runtime.h>
#include <cuda_bf16.h>
#include <cuda_fp16.h>
#include <math.h>

#define BB 4
#define SS 512
#define DD 768
#define HH 12
#define LL 12
#define FF 3072
#define DH 64
#define PP 512
#define BH (BB*HH)
#define MM (BB*SS)

// fp32 buffers (residual stream)
__device__ __align__(256) float g_h   [MM*DD];
__device__ __align__(256) float g_s1  [MM*DD];
__device__ __align__(256) float g_s2  [MM*DD];
// fp16 buffers
__device__ __align__(256) __half g_scores16[(size_t)BH*SS*SS];
__device__ __align__(256) __half g_h16 [MM*DD];
__device__ __align__(256) __half g_q16 [MM*DD];
__device__ __align__(256) __half g_k16 [MM*DD];
__device__ __align__(256) __half g_v16 [MM*DD];
__device__ __align__(256) __half g_ctx16[MM*DD];
__device__ __align__(256) __half g_tmp16[MM*FF];
__device__ __align__(256) __half g_posk16[(size_t)LL*PP*DD];
__device__ __align__(256) __half g_posq16[(size_t)LL*PP*DD];
__device__ __align__(256) __half g_rel16[PP*DD];
__device__ __align__(256) unsigned g_vpk[(size_t)BH*256*64];   // V k-pair packed per (b,h)
// k-pair-packed fp16 weights
#define OQ 0
#define OK 589824
#define OV 1179648
#define OO 1769472
#define OW1 2359296
#define OW2 4718592
#define LSTR 7077888
__device__ __align__(256) __half g_wh[(size_t)LL*LSTR];
__device__ int g_tab[1024];

__device__ __forceinline__ unsigned pack2(float lo, float hi) {
    __half2 h = __floats2half2_rn(lo, hi);
    return *reinterpret_cast<unsigned*>(&h);
}
__device__ __forceinline__ void mma_f16(float* d, const unsigned* a, const unsigned* b) {
    asm volatile(
        "mma.sync.aligned.m16n8k16.row.col.f32.f16.f16.f32 "
        "{%0,%1,%2,%3}, {%4,%5,%6,%7}, {%8,%9}, {%0,%1,%2,%3};\n"
        : "+f"(d[0]), "+f"(d[1]), "+f"(d[2]), "+f"(d[3])
        : "r"(a[0]), "r"(a[1]), "r"(a[2]), "r"(a[3]), "r"(b[0]), "r"(b[1]));
}
__device__ __forceinline__ void cp16(void* smem, const void* gmem) {
    unsigned sa = (unsigned)__cvta_generic_to_shared(smem);
    asm volatile("cp.async.cg.shared.global [%0], [%1], 16;" :: "r"(sa), "l"(gmem));
}
#define CP_COMMIT asm volatile("cp.async.commit_group;")
#define CP_WAIT1  asm volatile("cp.async.wait_group 1;")
#define CP_WAIT0  asm volatile("cp.async.wait_group 0;")

// ---------------- embeddings + LN + mask ----------------
__global__ void __launch_bounds__(256) embed_ln_kernel(
    const int* __restrict__ ids, const int* __restrict__ segs, const int* __restrict__ pins,
    const float* __restrict__ mask,
    const float* __restrict__ tok, const float* __restrict__ pin, const float* __restrict__ seg,
    const float* __restrict__ w, const float* __restrict__ b,
    float* __restrict__ out, __half* __restrict__ out16)
{
    int t = blockIdx.x, tid = threadIdx.x;
    __shared__ float xs[DD];
    __shared__ float red[256];
    size_t io = (size_t)ids[t] * DD, po = (size_t)pins[t] * DD, so = (size_t)segs[t] * DD;
    float s = 0.f;
    for (int d = tid; d < DD; d += 256) {
        float x = tok[io + d] + pin[po + d] + seg[so + d];
        xs[d] = x; s += x;
    }
    red[tid] = s; __syncthreads();
    for (int st = 128; st > 0; st >>= 1) { if (tid < st) red[tid] += red[tid + st]; __syncthreads(); }
    float mu = red[0] * (1.0f / DD); __syncthreads();
    float s2 = 0.f;
    for (int d = tid; d < DD; d += 256) { float dv = xs[d] - mu; s2 += dv * dv; }
    red[tid] = s2; __syncthreads();
    for (int st = 128; st > 0; st >>= 1) { if (tid < st) red[tid] += red[tid + st]; __syncthreads(); }
    float inv = rsqrtf(red[0] * (1.0f / DD) + 1e-12f);
    float m = mask[t];
    for (int d = tid; d < DD; d += 256) {
        float val = ((xs[d] - mu) * inv * w[d] + b[d]) * m;
        out[(size_t)t * DD + d] = val;
        out16[(size_t)t * DD + d] = __float2half_rn(val);
    }
}

// ---------------- bucket table ----------------
__global__ void buckets_kernel(int* __restrict__ tab)
{
    int x = blockIdx.x * blockDim.x + threadIdx.x;
    if (x >= 1023) { if (x == 1023) tab[1023] = 0; return; }
    int rel = x - 511;
    const int mid = 128;
    int ap = (rel < mid && rel > -mid) ? (mid - 1) : (rel < 0 ? -rel : rel);
    int bucket;
    if (ap <= mid) bucket = rel;
    else {
        double lp = ceil(log((double)ap / (double)mid) / log(511.0 / 128.0) * (mid - 1)) + mid;
        int sgn = (rel > 0) - (rel < 0);
        bucket = (int)lp * sgn;
    }
    int c = bucket + 256; c = c < 0 ? 0 : (c > 511 ? 511 : c);
    tab[x] = c;
}

// ---------------- weight convert (vectorized) ----------------
__global__ void __launch_bounds__(256) convert_w(
    const float* __restrict__ in, __half* __restrict__ out,
    int N4, int N, size_t lstr_in, size_t lstr_out)
{
    const float* ip = in + (size_t)blockIdx.z * lstr_in;
    __half* op = out + (size_t)blockIdx.z * lstr_out;
    size_t i = (size_t)blockIdx.x * 256 + threadIdx.x;
    int k2 = (int)(i / N4), n4 = (int)(i % N4) * 4;
    const float* r0 = ip + (size_t)(2 * k2) * N + n4;
    float4 a = *(const float4*)r0;
    float4 b = *(const float4*)(r0 + N);
    uint4 o = make_uint4(pack2(a.x, b.x), pack2(a.y, b.y), pack2(a.z, b.z), pack2(a.w, b.w));
    *(uint4*)(op + ((size_t)k2 * N + n4) * 2) = o;
}

__global__ void __launch_bounds__(256) convert_h(
    const float* __restrict__ in, __half* __restrict__ out, size_t n)
{
    size_t i = (size_t)blockIdx.x * 256 + threadIdx.x;
    if (i < n) out[i] = __float2half_rn(in[i]);
}

// ---------------- V repack: vpk[bh][k2][n] = (V[2k2,n], V[2k2+1,n]) halves in u32 ----------------
__global__ void __launch_bounds__(256) repack_v(
    const __half* __restrict__ V, unsigned* __restrict__ vpk)
{
    size_t i = (size_t)blockIdx.x * 256 + threadIdx.x;   // over BH*256*16
    int n4 = (int)(i & 15) * 4;
    int k2 = (int)((i >> 4) & 255);
    int bh = (int)(i >> 12);
    int b = bh / HH, hh = bh % HH;
    const __half* src = V + ((size_t)b * SS + 2 * k2) * DD + hh * DH + n4;
    uint2 r0 = *(const uint2*)src;
    uint2 r1 = *(const uint2*)(src + DD);
    uint4 o;
    o.x = __byte_perm(r0.x, r1.x, 0x5410);
    o.y = __byte_perm(r0.x, r1.x, 0x7632);
    o.z = __byte_perm(r0.y, r1.y, 0x5410);
    o.w = __byte_perm(r0.y, r1.y, 0x7632);
    *(uint4*)(vpk + ((size_t)bh * 256 + k2) * 64 + n4) = o;
}

// ---------------- dense fp16 GEMM core (proven R14/15) ----------------
#define A_STR 12
#define B_STR 136
#define A_STG (128*A_STR)
#define B_STG (8*B_STR)
#define GEMM_SMEM ((A_STG + B_STG) * 3 * 4)

__device__ __forceinline__ void gemm128h_core(
    const __half* __restrict__ A, const __half* __restrict__ Bp,
    const float* __restrict__ bias, void* Cout, int outHalf,
    int m0, int n0, int N, int K, int kStart, int kLen, int act, int useBias)
{
    extern __shared__ unsigned dsm[];
    unsigned* Asm = dsm;
    unsigned* Bsm = dsm + 3 * A_STG;

    int tid = threadIdx.x;
    int w = tid >> 5, lane = tid & 31;
    int lr = lane >> 2, lc = lane & 3;
    int wm = (w >> 2) * 64, wn = (w & 3) * 32;

    int arow = tid >> 1, apart = tid & 1;
    int brow = tid >> 5;

    const __half* abase = A + (size_t)(m0 + arow) * K + kStart + apart * 8;
    const __half* bbase = Bp + ((size_t)(kStart / 2 + brow) * N + n0 + lane * 4) * 2;

    const int kTiles = kLen >> 4;

    #define GISSUE(s, kt) do { \
        unsigned* as_ = Asm + (s) * A_STG; \
        unsigned* bs_ = Bsm + (s) * B_STG; \
        cp16(as_ + arow * A_STR + apart * 4, abase + (size_t)(kt) * 16); \
        cp16(bs_ + brow * B_STR + lane * 4, bbase + (size_t)(kt) * 16 * N); \
    } while (0)

    GISSUE(0, 0); CP_COMMIT;
    GISSUE(1, 1); CP_COMMIT;

    float acc[4][4][4] = {};

    for (int kt = 0; kt < kTiles; kt++) {
        CP_WAIT1;
        __syncthreads();
        if (kt + 2 < kTiles) GISSUE((kt + 2) % 3, kt + 2);
        CP_COMMIT;

        const unsigned* as = Asm + (kt % 3) * A_STG;
        const unsigned* bs = Bsm + (kt % 3) * B_STG;

        unsigned af[4][4], bf[4][2];
        #pragma unroll
        for (int mt = 0; mt < 4; mt++) {
            int m = wm + mt * 16 + lr;
            af[mt][0] = as[m * A_STR + lc];
            af[mt][1] = as[(m + 8) * A_STR + lc];
            af[mt][2] = as[m * A_STR + lc + 4];
            af[mt][3] = as[(m + 8) * A_STR + lc + 4];
        }
        #pragma unroll
        for (int nt = 0; nt < 4; nt++) {
            int n = wn + nt * 8 + lr;
            bf[nt][0] = bs[lc * B_STR + n];
            bf[nt][1] = bs[(lc + 4) * B_STR + n];
        }
        #pragma unroll
        for (int mt = 0; mt < 4; mt++)
            #pragma unroll
            for (int nt = 0; nt < 4; nt++)
                mma_f16(acc[mt][nt], af[mt], bf[nt]);
    }
    #undef GISSUE

    #pragma unroll
    for (int mt = 0; mt < 4; mt++) {
        int r = m0 + wm + mt * 16 + lr;
        #pragma unroll
        for (int nt = 0; nt < 4; nt++) {
            int c = n0 + wn + nt * 8 + lc * 2;
            float bv0 = useBias ? bias[c] : 0.f, bv1 = useBias ? bias[c + 1] : 0.f;
            float v00 = acc[mt][nt][0] + bv0, v01 = acc[mt][nt][1] + bv1;
            float v10 = acc[mt][nt][2] + bv0, v11 = acc[mt][nt][3] + bv1;
            if (act) {
                v00 = 0.5f * v00 * (1.0f + erff(v00 * 0.70710678118654752f));
                v01 = 0.5f * v01 * (1.0f + erff(v01 * 0.70710678118654752f));
                v10 = 0.5f * v10 * (1.0f + erff(v10 * 0.70710678118654752f));
                v11 = 0.5f * v11 * (1.0f + erff(v11 * 0.70710678118654752f));
            }
            if (outHalf) {
                __half* C = (__half*)Cout;
                *(__half2*)(C + (size_t)r * N + c)       = __floats2half2_rn(v00, v01);
                *(__half2*)(C + (size_t)(r + 8) * N + c) = __floats2half2_rn(v10, v11);
            } else {
                float* C = (float*)Cout;
                *(float2*)(C + (size_t)r * N + c)       = make_float2(v00, v01);
                *(float2*)(C + (size_t)(r + 8) * N + c) = make_float2(v10, v11);
            }
        }
    }
}

__global__ void __launch_bounds__(256) gemm_qkv(
    const __half* __restrict__ h16, const __half* __restrict__ wh,
    const float* __restrict__ bq, const float* __restrict__ bk, const float* __restrict__ bv,
    __half* __restrict__ q, __half* __restrict__ k, __half* __restrict__ v)
{
    const int z = blockIdx.z;
    const __half* Bp   = wh + ((z == 0) ? OQ : (z == 1) ? OK : OV);
    const float*  bias = (z == 0) ? bq : (z == 1) ? bk : bv;
    __half*       C    = (z == 0) ? q  : (z == 1) ? k  : v;
    gemm128h_core(h16, Bp, bias, C, 1, blockIdx.y * 128, blockIdx.x * 128, DD, DD, 0, DD, 0, 1);
}

__global__ void __launch_bounds__(256) gemm_pos(
    const __half* __restrict__ rel16, const __half* __restrict__ wh,
    const float* __restrict__ bq, const float* __restrict__ bk,
    __half* __restrict__ posqL, __half* __restrict__ poskL)
{
    const int z = blockIdx.z;
    const int l = z >> 1;
    const int isq = z & 1;
    const __half* Bp   = wh + (size_t)l * LSTR + (isq ? OQ : OK);
    const float*  bias = (isq ? bq : bk) + (size_t)l * DD;
    __half*       C    = (isq ? posqL : poskL) + (size_t)l * PP * DD;
    gemm128h_core(rel16, Bp, bias, C, 1, blockIdx.y * 128, blockIdx.x * 128, DD, DD, 0, DD, 0, 1);
}

__global__ void __launch_bounds__(256) gemm_one(
    const __half* __restrict__ A, const __half* __restrict__ Bp, const float* __restrict__ bias,
    __half* __restrict__ C, int N, int K, int act)
{
    gemm128h_core(A, Bp, bias, C, 1, blockIdx.y * 128, blockIdx.x * 128, N, K, 0, K, act, 1);
}

__global__ void __launch_bounds__(256) gemm_sk(
    const __half* __restrict__ A, const __half* __restrict__ Bp, const float* __restrict__ bias,
    float* __restrict__ C0, float* __restrict__ C1, int N, int K)
{
    const int z = blockIdx.z;
    gemm128h_core(A, Bp, bias, z ? C1 : C0, 0, blockIdx.y * 128, blockIdx.x * 128,
                  N, K, z * (K >> 1), K >> 1, 0, z == 0);
}

// ---------------- fused disentangled score kernel — cp.async loads ----------------
#define SC_STR 36
#define SCORE_SMEM (16896 * 4)
__global__ void __launch_bounds__(256) score_fused(
    const __half* __restrict__ Q, const __half* __restrict__ Kt,
    const __half* __restrict__ PKg, const __half* __restrict__ PQg,
    const int* __restrict__ tab, const float* __restrict__ mask,
    __half* __restrict__ scores, float scale)
{
    int z = blockIdx.z; int b = z / HH, hh = z % HH;
    int m0 = blockIdx.y * 64, n0 = blockIdx.x * 64;
    const __half* Aq = Q  + (size_t)b * SS * DD + hh * DH;
    const __half* Ak = Kt + (size_t)b * SS * DD + hh * DH;
    const __half* PK = PKg + hh * DH;
    const __half* PQ = PQg + hh * DH;

    extern __shared__ unsigned ssm[];
    unsigned* Qs  = ssm;
    unsigned* Ks  = ssm + 2304;
    unsigned* PKs = ssm + 4608;
    unsigned* PQs = ssm + 9216;
    float* C1s = (float*)ssm;
    float* C2s = (float*)(ssm + 8448);

    int tid = threadIdx.x;
    int w = tid >> 5, lane = tid & 31;
    int lr = lane >> 2, lc = lane & 3;
    int wr = w >> 2, wc = w & 3;
    const int dlo = m0 - n0 - 63;

    {
        int row = tid >> 2;
        int colh = (tid & 3) * 16;
        int colu = colh >> 1;
        const __half* pq_ = Aq + (size_t)(m0 + row) * DD + colh;
        cp16(Qs + row * SC_STR + colu,     pq_);
        cp16(Qs + row * SC_STR + colu + 4, pq_ + 8);
        const __half* pk_ = Ak + (size_t)(n0 + row) * DD + colh;
        cp16(Ks + row * SC_STR + colu,     pk_);
        cp16(Ks + row * SC_STR + colu + 4, pk_ + 8);
        #pragma unroll
        for (int half_ = 0; half_ < 2; half_++) {
            int t = row + half_ * 64;
            int tt = t < 127 ? t : 126;
            int pidx = tab[dlo + tt + 511];
            const __half* pk2 = PK + (size_t)pidx * DD + colh;
            cp16(PKs + t * SC_STR + colu,     pk2);
            cp16(PKs + t * SC_STR + colu + 4, pk2 + 8);
            const __half* pq2 = PQ + (size_t)pidx * DD + colh;
            cp16(PQs + t * SC_STR + colu,     pq2);
            cp16(PQs + t * SC_STR + colu + 4, pq2 + 8);
        }
        CP_COMMIT;
        CP_WAIT0;
    }
    __syncthreads();

    float accS[2][2][4] = {};
    float acc1[2][4][4] = {};
    float acc2[2][4][4] = {};

    #pragma unroll
    for (int c = 0; c < 4; c++) {
        int cu = c * 8;
        unsigned aq[2][4], ak[2][4];
        #pragma unroll
        for (int mt = 0; mt < 2; mt++) {
            int m = wr * 32 + mt * 16 + lr;
            aq[mt][0] = Qs[m * SC_STR + cu + lc];       aq[mt][1] = Qs[(m + 8) * SC_STR + cu + lc];
            aq[mt][2] = Qs[m * SC_STR + cu + lc + 4];   aq[mt][3] = Qs[(m + 8) * SC_STR + cu + lc + 4];
            ak[mt][0] = Ks[m * SC_STR + cu + lc];       ak[mt][1] = Ks[(m + 8) * SC_STR + cu + lc];
            ak[mt][2] = Ks[m * SC_STR + cu + lc + 4];   ak[mt][3] = Ks[(m + 8) * SC_STR + cu + lc + 4];
        }
        unsigned bS[2][2], b1[4][2], b2[4][2];
        #pragma unroll
        for (int nt = 0; nt < 2; nt++) {
            int n = wc * 16 + nt * 8 + lr;
            bS[nt][0] = Ks[n * SC_STR + cu + lc];
            bS[nt][1] = Ks[n * SC_STR + cu + lc + 4];
        }
        #pragma unroll
        for (int nt = 0; nt < 4; nt++) {
            int n = wc * 32 + nt * 8 + lr;
            b1[nt][0] = PKs[n * SC_STR + cu + lc];
            b1[nt][1] = PKs[n * SC_STR + cu + lc + 4];
            b2[nt][0] = PQs[n * SC_STR + cu + lc];
            b2[nt][1] = PQs[n * SC_STR + cu + lc + 4];
        }
        #pragma unroll
        for (int mt = 0; mt < 2; mt++) {
            #pragma unroll
            for (int nt = 0; nt < 2; nt++) mma_f16(accS[mt][nt], aq[mt], bS[nt]);
            #pragma unroll
            for (int nt = 0; nt < 4; nt++) { mma_f16(acc1[mt][nt], aq[mt], b1[nt]); mma_f16(acc2[mt][nt], ak[mt], b2[nt]); }
        }
    }
    __syncthreads();

    #pragma unroll
    for (int mt = 0; mt < 2; mt++) {
        int r = wr * 32 + mt * 16 + lr;
        #pragma unroll
        for (int nt = 0; nt < 4; nt++) {
            int c = wc * 32 + nt * 8 + lc * 2;
            C1s[r * 132 + c] = acc1[mt][nt][0]; C1s[r * 132 + c + 1] = acc1[mt][nt][1];
            C1s[(r + 8) * 132 + c] = acc1[mt][nt][2]; C1s[(r + 8) * 132 + c + 1] = acc1[mt][nt][3];
            C2s[r * 132 + c] = acc2[mt][nt][0]; C2s[r * 132 + c + 1] = acc2[mt][nt][1];
            C2s[(r + 8) * 132 + c] = acc2[mt][nt][2]; C2s[(r + 8) * 132 + c + 1] = acc2[mt][nt][3];
        }
    }
    __syncthreads();

    #pragma unroll
    for (int mt = 0; mt < 2; mt++) {
        #pragma unroll
        for (int nt = 0; nt < 2; nt++) {
            int r = wr * 32 + mt * 16 + lr;
            int c0 = wc * 16 + nt * 8 + lc * 2;
            #pragma unroll
            for (int half_ = 0; half_ < 2; half_++) {
                int rr = r + half_ * 8;
                float o[2];
                #pragma unroll
                for (int e = 0; e < 2; e++) {
                    int cc = c0 + e;
                    int t = rr - cc + 63;
                    float val = (accS[mt][nt][half_ * 2 + e] + C1s[rr * 132 + t] + C2s[cc * 132 + t]) * scale;
                    val += (1.0f - mask[b * SS + n0 + cc]) * (-1e9f);
                    o[e] = fmaxf(val, -60000.0f);
                }
                *(__half2*)(scores + ((size_t)z * SS + m0 + rr) * SS + n0 + c0) = __floats2half2_rn(o[0], o[1]);
            }
        }
    }
}

// ---------------- warp-per-row softmax: fp16 in-place, shuffle-only ----------------
__global__ void __launch_bounds__(256) softmax_kernel(__half* __restrict__ scores)
{
    int wid = threadIdx.x >> 5, lane = threadIdx.x & 31;
    int row = blockIdx.x * 8 + wid;
    int z = blockIdx.y;
    __half* rp = scores + ((size_t)z * SS + row) * SS + lane * 16;

    uint4 u0 = *(const uint4*)rp;
    uint4 u1 = *(const uint4*)(rp + 8);
    float f[16];
    {
        const unsigned* uu = &u0.x;
        #pragma unroll
        for (int i = 0; i < 4; i++) {
            float2 p = __half22float2(*reinterpret_cast<const __half2*>(&uu[i]));
            f[i * 2] = p.x; f[i * 2 + 1] = p.y;
        }
        const unsigned* vv = &u1.x;
        #pragma unroll
        for (int i = 0; i < 4; i++) {
            float2 p = __half22float2(*reinterpret_cast<const __half2*>(&vv[i]));
            f[8 + i * 2] = p.x; f[8 + i * 2 + 1] = p.y;
        }
    }
    float mx = f[0];
    #pragma unroll
    for (int i = 1; i < 16; i++) mx = fmaxf(mx, f[i]);
    #pragma unroll
    for (int o = 16; o > 0; o >>= 1) mx = fmaxf(mx, __shfl_xor_sync(0xffffffffu, mx, o));
    float s = 0.f;
    #pragma unroll
    for (int i = 0; i < 16; i++) { f[i] = expf(f[i] - mx); s += f[i]; }
    #pragma unroll
    for (int o = 16; o > 0; o >>= 1) s += __shfl_xor_sync(0xffffffffu, s, o);
    float inv = 1.0f / s;
    uint4 o0, o1;
    o0.x = pack2(f[0] * inv, f[1] * inv);   o0.y = pack2(f[2] * inv, f[3] * inv);
    o0.z = pack2(f[4] * inv, f[5] * inv);   o0.w = pack2(f[6] * inv, f[7] * inv);
    o1.x = pack2(f[8] * inv, f[9] * inv);   o1.y = pack2(f[10] * inv, f[11] * inv);
    o1.z = pack2(f[12] * inv, f[13] * inv); o1.w = pack2(f[14] * inv, f[15] * inv);
    *(uint4*)rp = o0;
    *(uint4*)(rp + 8) = o1;
}

// ---------------- batched ctx GEMM — fully async, 3-stage ----------------
#define CTXB_STR 72
#define CTXA_STG (128*A_STR)
#define CTXB_STG (8*CTXB_STR)
#define CTX_SMEM ((CTXA_STG + CTXB_STG) * 3 * 4)
__global__ void __launch_bounds__(256) ctx_f16(
    const __half* __restrict__ Pm, const unsigned* __restrict__ vpk, __half* __restrict__ O)
{
    int z = blockIdx.y; int b = z / HH, hh = z % HH;
    int m0 = blockIdx.x * 128;
    const __half* A = Pm + (size_t)z * SS * SS;
    const unsigned* Bv = vpk + (size_t)z * 256 * 64;

    extern __shared__ unsigned dsm[];
    unsigned* Asm = dsm;
    unsigned* Bsm = dsm + 3 * CTXA_STG;

    int tid = threadIdx.x;
    int w = tid >> 5, lane = tid & 31;
    int lr = lane >> 2, lc = lane & 3;
    int wm = (w >> 1) * 32, wn = (w & 1) * 32;

    int arow = tid >> 1, apart = tid & 1;
    int brow2 = (tid >> 4) & 7, bcol4 = (tid & 15) * 4;
    bool bload = tid < 128;

    const __half*   abase = A + (size_t)(m0 + arow) * SS + apart * 8;
    const unsigned* bbase = Bv + brow2 * 64 + bcol4;

    const int kTiles = SS / 16;

    #define CISSUE(s, kt) do { \
        unsigned* as_ = Asm + (s) * CTXA_STG; \
        unsigned* bs_ = Bsm + (s) * CTXB_STG; \
        cp16(as_ + arow * A_STR + apart * 4, abase + (size_t)(kt) * 16); \
        if (bload) cp16(bs_ + brow2 * CTXB_STR + bcol4, bbase + (size_t)(kt) * 8 * 64); \
    } while (0)

    CISSUE(0, 0); CP_COMMIT;
    CISSUE(1, 1); CP_COMMIT;

    float acc[2][4][4] = {};

    for (int kt = 0; kt < kTiles; kt++) {
        CP_WAIT1;
        __syncthreads();
        if (kt + 2 < kTiles) CISSUE((kt + 2) % 3, kt + 2);
        CP_COMMIT;

        const unsigned* as = Asm + (kt % 3) * CTXA_STG;
        const unsigned* bs = Bsm + (kt % 3) * CTXB_STG;

        unsigned af[2][4], bf[4][2];
        #pragma unroll
        for (int mt = 0; mt < 2; mt++) {
            int m = wm + mt * 16 + lr;
            af[mt][0] = as[m * A_STR + lc];
            af[mt][1] = as[(m + 8) * A_STR + lc];
            af[mt][2] = as[m * A_STR + lc + 4];
            af[mt][3] = as[(m + 8) * A_STR + lc + 4];
        }
        #pragma unroll
        for (int nt = 0; nt < 4; nt++) {
            int n = wn + nt * 8 + lr;
            bf[nt][0] = bs[lc * CTXB_STR + n];
            bf[nt][1] = bs[(lc + 4) * CTXB_STR + n];
        }
        #pragma unroll
        for (int mt = 0; mt < 2; mt++)
            #pragma unroll
            for (int nt = 0; nt < 4; nt++)
                mma_f16(acc[mt][nt], af[mt], bf[nt]);
    }
    #undef CISSUE

    #pragma unroll
    for (int mt = 0; mt < 2; mt++) {
        int r = m0 + wm + mt * 16 + lr;
        #pragma unroll
        for (int nt = 0; nt < 4; nt++) {
            int c = wn + nt * 8 + lc * 2;
            *(__half2*)(O + ((size_t)b * SS + r) * DD + hh * DH + c)     = __floats2half2_rn(acc[mt][nt][0], acc[mt][nt][1]);
            *(__half2*)(O + ((size_t)b * SS + r + 8) * DD + hh * DH + c) = __floats2half2_rn(acc[mt][nt][2], acc[mt][nt][3]);
        }
    }
}

// ---------------- residual add (two deltas) + LN ----------------
__global__ void __launch_bounds__(256) add_ln3_kernel(
    float* __restrict__ h, __half* __restrict__ h16,
    const float* __restrict__ d1, const float* __restrict__ d2,
    const float* __restrict__ w, const float* __restrict__ b)
{
    int t = blockIdx.x, tid = threadIdx.x;
    __shared__ float xs[DD];
    __shared__ float red[256];
    float* hr = h + (size_t)t * DD;
    __half* hr16 = h16 + (size_t)t * DD;
    const float* r1 = d1 + (size_t)t * DD;
    const float* r2 = d2 + (size_t)t * DD;

    float s = 0.f;
    for (int d = tid; d < DD; d += 256) { float x = hr[d] + r1[d] + r2[d]; xs[d] = x; s += x; }
    red[tid] = s; __syncthreads();
    for (int st = 128; st > 0; st >>= 1) { if (tid < st) red[tid] += red[tid + st]; __syncthreads(); }
    float mu = red[0] * (1.0f / DD); __syncthreads();
    float s2 = 0.f;
    for (int d = tid; d < DD; d += 256) { float dv = xs[d] - mu; s2 += dv * dv; }
    red[tid] = s2; __syncthreads();
    for (int st = 128; st > 0; st >>= 1) { if (tid < st) red[tid] += red[tid + st]; __syncthreads(); }
    float inv = rsqrtf(red[0] * (1.0f / DD) + 1e-12f);
    for (int d = tid; d < DD; d += 256) {
        float val = (xs[d] - mu) * inv * w[d] + b[d];
        hr[d] = val;
        hr16[d] = __float2half_rn(val);
    }
}

// ---------------- host orchestration ----------------
extern "C" void kernel_launch(void* const* d_in, const int* in_sizes, int n_in,
                              void* d_out, int out_size)
{
    const int*   input_ids   = (const int*)  d_in[0];
    const int*   segment_ids = (const int*)  d_in[1];
    const int*   pinyin_ids  = (const int*)  d_in[2];
    const float* attn_mask   = (const float*)d_in[3];
    const float* tok_emb     = (const float*)d_in[4];
    const float* pin_emb     = (const float*)d_in[5];
    const float* seg_emb     = (const float*)d_in[6];
    const float* emb_ln_w    = (const float*)d_in[7];
    const float* emb_ln_b    = (const float*)d_in[8];
    const float* rel_emb     = (const float*)d_in[9];
    const float* Wq = (const float*)d_in[10]; const float* bq = (const float*)d_in[11];
    const float* Wk = (const float*)d_in[12]; const float* bk = (const float*)d_in[13];
    const float* Wv = (const float*)d_in[14]; const float* bv = (const float*)d_in[15];
    const float* Wo = (const float*)d_in[16]; const float* bo = (const float*)d_in[17];
    const float* ln1w = (const float*)d_in[18]; const float* ln1b = (const float*)d_in[19];
    const float* W1 = (const float*)d_in[20]; const float* b1 = (const float*)d_in[21];
    const float* W2 = (const float*)d_in[22]; const float* b2 = (const float*)d_in[23];
    const float* ln2w = (const float*)d_in[24]; const float* ln2b = (const float*)d_in[25];

    float *h, *s1, *s2;
    __half *scores16, *h16, *q16, *k16, *v16, *ctx16, *tmp16, *posk16, *posq16, *rel16, *wh;
    unsigned *vpk;
    int *tab;
    cudaGetSymbolAddress((void**)&h,        g_h);
    cudaGetSymbolAddress((void**)&s1,       g_s1);
    cudaGetSymbolAddress((void**)&s2,       g_s2);
    cudaGetSymbolAddress((void**)&scores16, g_scores16);
    cudaGetSymbolAddress((void**)&h16,      g_h16);
    cudaGetSymbolAddress((void**)&q16,      g_q16);
    cudaGetSymbolAddress((void**)&k16,      g_k16);
    cudaGetSymbolAddress((void**)&v16,      g_v16);
    cudaGetSymbolAddress((void**)&ctx16,    g_ctx16);
    cudaGetSymbolAddress((void**)&tmp16,    g_tmp16);
    cudaGetSymbolAddress((void**)&posk16,   g_posk16);
    cudaGetSymbolAddress((void**)&posq16,   g_posq16);
    cudaGetSymbolAddress((void**)&rel16,    g_rel16);
    cudaGetSymbolAddress((void**)&vpk,      g_vpk);
    cudaGetSymbolAddress((void**)&wh,       g_wh);
    cudaGetSymbolAddress((void**)&tab,      g_tab);

    cudaFuncSetAttribute(gemm_qkv,    cudaFuncAttributeMaxDynamicSharedMemorySize, GEMM_SMEM);
    cudaFuncSetAttribute(gemm_pos,    cudaFuncAttributeMaxDynamicSharedMemorySize, GEMM_SMEM);
    cudaFuncSetAttribute(gemm_one,    cudaFuncAttributeMaxDynamicSharedMemorySize, GEMM_SMEM);
    cudaFuncSetAttribute(gemm_sk,     cudaFuncAttributeMaxDynamicSharedMemorySize, GEMM_SMEM);
    cudaFuncSetAttribute(ctx_f16,     cudaFuncAttributeMaxDynamicSharedMemorySize, CTX_SMEM);
    cudaFuncSetAttribute(score_fused, cudaFuncAttributeMaxDynamicSharedMemorySize, SCORE_SMEM);

    const float scale = 0.07216878364870323f;  // 1/sqrt(3*DH)

    embed_ln_kernel<<<MM, 256>>>(input_ids, segment_ids, pinyin_ids, attn_mask,
                                 tok_emb, pin_emb, seg_emb, emb_ln_w, emb_ln_b, h, h16);
    buckets_kernel<<<4, 256>>>(tab);
    convert_h<<<(PP * DD + 255) / 256, 256>>>(rel_emb, rel16, (size_t)PP * DD);

    convert_w<<<dim3(288,  1, LL), 256>>>(Wq, wh + OQ,  DD / 4, DD, (size_t)DD * DD, LSTR);
    convert_w<<<dim3(288,  1, LL), 256>>>(Wk, wh + OK,  DD / 4, DD, (size_t)DD * DD, LSTR);
    convert_w<<<dim3(288,  1, LL), 256>>>(Wv, wh + OV,  DD / 4, DD, (size_t)DD * DD, LSTR);
    convert_w<<<dim3(288,  1, LL), 256>>>(Wo, wh + OO,  DD / 4, DD, (size_t)DD * DD, LSTR);
    convert_w<<<dim3(1152, 1, LL), 256>>>(W1, wh + OW1, FF / 4, FF, (size_t)DD * FF, LSTR);
    convert_w<<<dim3(1152, 1, LL), 256>>>(W2, wh + OW2, DD / 4, DD, (size_t)FF * DD, LSTR);

    gemm_pos<<<dim3(DD / 128, PP / 128, 2 * LL), 256, GEMM_SMEM>>>(
        rel16, wh, bq, bk, posq16, posk16);

    for (int i = 0; i < LL; i++) {
        const __half* wl = wh + (size_t)i * LSTR;
        const float* bq_i = bq + (size_t)i * DD;
        const float* bk_i = bk + (size_t)i * DD;
        const float* bv_i = bv + (size_t)i * DD;
        const float* bo_i = bo + (size_t)i * DD;
        const float* b1_i = b1 + (size_t)i * FF;
        const float* b2_i = b2 + (size_t)i * DD;
        const __half* posk_i = posk16 + (size_t)i * PP * DD;
        const __half* posq_i = posq16 + (size_t)i * PP * DD;

        gemm_qkv<<<dim3(DD / 128, MM / 128, 3), 256, GEMM_SMEM>>>(
            h16, wl, bq_i, bk_i, bv_i, q16, k16, v16);
        repack_v<<<768, 256>>>(v16, vpk);

        score_fused<<<dim3(8, 8, BH), 256, SCORE_SMEM>>>(
            q16, k16, posk_i, posq_i, tab, attn_mask, scores16, scale);
        softmax_kernel<<<dim3(SS / 8, BH), 256>>>(scores16);
        ctx_f16<<<dim3(SS / 128, BH), 256, CTX_SMEM>>>(scores16, vpk, ctx16);

        gemm_sk<<<dim3(DD / 128, MM / 128, 2), 256, GEMM_SMEM>>>(
            ctx16, wl + OO, bo_i, s1, s2, DD, DD);
        add_ln3_kernel<<<MM, 256>>>(h, h16, s1, s2, ln1w + (size_t)i * DD, ln1b + (size_t)i * DD);

        gemm_one<<<dim3(FF / 128, MM / 128), 256, GEMM_SMEM>>>(h16, wl + OW1, b1_i, tmp16, FF, DD, 1);
        gemm_sk<<<dim3(DD / 128, MM / 128, 2), 256, GEMM_SMEM>>>(
            tmp16, wl + OW2, b2_i, s1, s2, DD, FF);
        add_ln3_kernel<<<MM, 256>>>(h, h16, s1, s2, ln2w + (size_t)i * DD, ln2b + (size_t)i * DD);
    }

    cudaMemcpyAsync(d_out, h, sizeof(float) * (size_t)out_size, cudaMemcpyDeviceToDevice);
}

// round 17
// speedup vs baseline: 1.7626x; 1.0103x over previous
#include <cuda_runtime.h>
#include <cuda_bf16.h>
#include <cuda_fp16.h>
#include <math.h>

#define BB 4
#define SS 512
#define DD 768
#define HH 12
#define LL 12
#define FF 3072
#define DH 64
#define PP 512
#define BH (BB*HH)
#define MM (BB*SS)

// fp32 residual stream
__device__ __align__(256) float g_h   [MM*DD];
// fp16 buffers
__device__ __align__(256) __half g_s1  [MM*DD];
__device__ __align__(256) __half g_s2  [MM*DD];
__device__ __align__(256) __half g_scores16[(size_t)BH*SS*SS];
__device__ __align__(256) __half g_h16 [MM*DD];
__device__ __align__(256) __half g_q16 [MM*DD];
__device__ __align__(256) __half g_k16 [MM*DD];
__device__ __align__(256) __half g_ctx16[MM*DD];
__device__ __align__(256) __half g_tmp16[MM*FF];
__device__ __align__(256) __half g_posk16[(size_t)LL*PP*DD];
__device__ __align__(256) __half g_posq16[(size_t)LL*PP*DD];
__device__ __align__(256) __half g_rel16[PP*DD];
__device__ __align__(256) unsigned g_vpk[(size_t)BH*256*64];   // V k-pair packed per (b,h)
// k-pair-packed fp16 weights
#define OQ 0
#define OK 589824
#define OV 1179648
#define OO 1769472
#define OW1 2359296
#define OW2 4718592
#define LSTR 7077888
__device__ __align__(256) __half g_wh[(size_t)LL*LSTR];
__device__ int g_tab[1024];

__device__ __forceinline__ unsigned pack2(float lo, float hi) {
    __half2 h = __floats2half2_rn(lo, hi);
    return *reinterpret_cast<unsigned*>(&h);
}
__device__ __forceinline__ void mma_f16(float* d, const unsigned* a, const unsigned* b) {
    asm volatile(
        "mma.sync.aligned.m16n8k16.row.col.f32.f16.f16.f32 "
        "{%0,%1,%2,%3}, {%4,%5,%6,%7}, {%8,%9}, {%0,%1,%2,%3};\n"
        : "+f"(d[0]), "+f"(d[1]), "+f"(d[2]), "+f"(d[3])
        : "r"(a[0]), "r"(a[1]), "r"(a[2]), "r"(a[3]), "r"(b[0]), "r"(b[1]));
}
__device__ __forceinline__ void cp16(void* smem, const void* gmem) {
    unsigned sa = (unsigned)__cvta_generic_to_shared(smem);
    asm volatile("cp.async.cg.shared.global [%0], [%1], 16;" :: "r"(sa), "l"(gmem));
}
#define CP_COMMIT asm volatile("cp.async.commit_group;")
#define CP_WAIT1  asm volatile("cp.async.wait_group 1;")
#define CP_WAIT0  asm volatile("cp.async.wait_group 0;")

// ---------------- embeddings + LN + mask ----------------
__global__ void __launch_bounds__(256) embed_ln_kernel(
    const int* __restrict__ ids, const int* __restrict__ segs, const int* __restrict__ pins,
    const float* __restrict__ mask,
    const float* __restrict__ tok, const float* __restrict__ pin, const float* __restrict__ seg,
    const float* __restrict__ w, const float* __restrict__ b,
    float* __restrict__ out, __half* __restrict__ out16)
{
    int t = blockIdx.x, tid = threadIdx.x;
    __shared__ float xs[DD];
    __shared__ float red[256];
    size_t io = (size_t)ids[t] * DD, po = (size_t)pins[t] * DD, so = (size_t)segs[t] * DD;
    float s = 0.f;
    for (int d = tid; d < DD; d += 256) {
        float x = tok[io + d] + pin[po + d] + seg[so + d];
        xs[d] = x; s += x;
    }
    red[tid] = s; __syncthreads();
    for (int st = 128; st > 0; st >>= 1) { if (tid < st) red[tid] += red[tid + st]; __syncthreads(); }
    float mu = red[0] * (1.0f / DD); __syncthreads();
    float s2 = 0.f;
    for (int d = tid; d < DD; d += 256) { float dv = xs[d] - mu; s2 += dv * dv; }
    red[tid] = s2; __syncthreads();
    for (int st = 128; st > 0; st >>= 1) { if (tid < st) red[tid] += red[tid + st]; __syncthreads(); }
    float inv = rsqrtf(red[0] * (1.0f / DD) + 1e-12f);
    float m = mask[t];
    for (int d = tid; d < DD; d += 256) {
        float val = ((xs[d] - mu) * inv * w[d] + b[d]) * m;
        out[(size_t)t * DD + d] = val;
        out16[(size_t)t * DD + d] = __float2half_rn(val);
    }
}

// ---------------- bucket table ----------------
__global__ void buckets_kernel(int* __restrict__ tab)
{
    int x = blockIdx.x * blockDim.x + threadIdx.x;
    if (x >= 1023) { if (x == 1023) tab[1023] = 0; return; }
    int rel = x - 511;
    const int mid = 128;
    int ap = (rel < mid && rel > -mid) ? (mid - 1) : (rel < 0 ? -rel : rel);
    int bucket;
    if (ap <= mid) bucket = rel;
    else {
        double lp = ceil(log((double)ap / (double)mid) / log(511.0 / 128.0) * (mid - 1)) + mid;
        int sgn = (rel > 0) - (rel < 0);
        bucket = (int)lp * sgn;
    }
    int c = bucket + 256; c = c < 0 ? 0 : (c > 511 ? 511 : c);
    tab[x] = c;
}

// ---------------- weight convert: merged 4x (Wq|Wk|Wv|Wo), vectorized ----------------
__global__ void __launch_bounds__(256) convert_w4(
    const float* __restrict__ Wq, const float* __restrict__ Wk,
    const float* __restrict__ Wv, const float* __restrict__ Wo,
    __half* __restrict__ wh)
{
    int z = blockIdx.z;
    int l = z >> 2, sel = z & 3;
    const float* ip = ((sel == 0) ? Wq : (sel == 1) ? Wk : (sel == 2) ? Wv : Wo) + (size_t)l * DD * DD;
    __half* op = wh + (size_t)l * LSTR + ((sel == 0) ? OQ : (sel == 1) ? OK : (sel == 2) ? OV : OO);
    size_t i = (size_t)blockIdx.x * 256 + threadIdx.x;   // over (768/2)*(768/4)
    int k2 = (int)(i / (DD / 4)), n4 = (int)(i % (DD / 4)) * 4;
    const float* r0 = ip + (size_t)(2 * k2) * DD + n4;
    float4 a = *(const float4*)r0;
    float4 b = *(const float4*)(r0 + DD);
    uint4 o = make_uint4(pack2(a.x, b.x), pack2(a.y, b.y), pack2(a.z, b.z), pack2(a.w, b.w));
    *(uint4*)(op + ((size_t)k2 * DD + n4) * 2) = o;
}

__global__ void __launch_bounds__(256) convert_w(
    const float* __restrict__ in, __half* __restrict__ out,
    int N4, int N, size_t lstr_in, size_t lstr_out)
{
    const float* ip = in + (size_t)blockIdx.z * lstr_in;
    __half* op = out + (size_t)blockIdx.z * lstr_out;
    size_t i = (size_t)blockIdx.x * 256 + threadIdx.x;
    int k2 = (int)(i / N4), n4 = (int)(i % N4) * 4;
    const float* r0 = ip + (size_t)(2 * k2) * N + n4;
    float4 a = *(const float4*)r0;
    float4 b = *(const float4*)(r0 + N);
    uint4 o = make_uint4(pack2(a.x, b.x), pack2(a.y, b.y), pack2(a.z, b.z), pack2(a.w, b.w));
    *(uint4*)(op + ((size_t)k2 * N + n4) * 2) = o;
}

__global__ void __launch_bounds__(256) convert_h(
    const float* __restrict__ in, __half* __restrict__ out, size_t n)
{
    size_t i = (size_t)blockIdx.x * 256 + threadIdx.x;
    if (i < n) out[i] = __float2half_rn(in[i]);
}

// ---------------- dense fp16 GEMM core; outMode: 0=fp32, 1=fp16, 2=vpk-packed (V) ----------------
#define A_STR 12
#define B_STR 136
#define A_STG (128*A_STR)
#define B_STG (8*B_STR)
#define GEMM_SMEM ((A_STG + B_STG) * 3 * 4)

__device__ __forceinline__ void gemm128h_core(
    const __half* __restrict__ A, const __half* __restrict__ Bp,
    const float* __restrict__ bias, void* Cout, int outMode,
    int m0, int n0, int N, int K, int kStart, int kLen, int act, int useBias)
{
    extern __shared__ unsigned dsm[];
    unsigned* Asm = dsm;
    unsigned* Bsm = dsm + 3 * A_STG;

    int tid = threadIdx.x;
    int w = tid >> 5, lane = tid & 31;
    int lr = lane >> 2, lc = lane & 3;
    int wm = (w >> 2) * 64, wn = (w & 3) * 32;

    int arow = tid >> 1, apart = tid & 1;
    int brow = tid >> 5;

    const __half* abase = A + (size_t)(m0 + arow) * K + kStart + apart * 8;
    const __half* bbase = Bp + ((size_t)(kStart / 2 + brow) * N + n0 + lane * 4) * 2;

    const int kTiles = kLen >> 4;

    #define GISSUE(s, kt) do { \
        unsigned* as_ = Asm + (s) * A_STG; \
        unsigned* bs_ = Bsm + (s) * B_STG; \
        cp16(as_ + arow * A_STR + apart * 4, abase + (size_t)(kt) * 16); \
        cp16(bs_ + brow * B_STR + lane * 4, bbase + (size_t)(kt) * 16 * N); \
    } while (0)

    GISSUE(0, 0); CP_COMMIT;
    GISSUE(1, 1); CP_COMMIT;

    float acc[4][4][4] = {};

    for (int kt = 0; kt < kTiles; kt++) {
        CP_WAIT1;
        __syncthreads();
        if (kt + 2 < kTiles) GISSUE((kt + 2) % 3, kt + 2);
        CP_COMMIT;

        const unsigned* as = Asm + (kt % 3) * A_STG;
        const unsigned* bs = Bsm + (kt % 3) * B_STG;

        unsigned af[4][4], bf[4][2];
        #pragma unroll
        for (int mt = 0; mt < 4; mt++) {
            int m = wm + mt * 16 + lr;
            af[mt][0] = as[m * A_STR + lc];
            af[mt][1] = as[(m + 8) * A_STR + lc];
            af[mt][2] = as[m * A_STR + lc + 4];
            af[mt][3] = as[(m + 8) * A_STR + lc + 4];
        }
        #pragma unroll
        for (int nt = 0; nt < 4; nt++) {
            int n = wn + nt * 8 + lr;
            bf[nt][0] = bs[lc * B_STR + n];
            bf[nt][1] = bs[(lc + 4) * B_STR + n];
        }
        #pragma unroll
        for (int mt = 0; mt < 4; mt++)
            #pragma unroll
            for (int nt = 0; nt < 4; nt++)
                mma_f16(acc[mt][nt], af[mt], bf[nt]);
    }
    #undef GISSUE

    #pragma unroll
    for (int mt = 0; mt < 4; mt++) {
        int r = m0 + wm + mt * 16 + lr;
        #pragma unroll
        for (int nt = 0; nt < 4; nt++) {
            int c = n0 + wn + nt * 8 + lc * 2;
            float bv0 = useBias ? bias[c] : 0.f, bv1 = useBias ? bias[c + 1] : 0.f;
            float v00 = acc[mt][nt][0] + bv0, v01 = acc[mt][nt][1] + bv1;
            float v10 = acc[mt][nt][2] + bv0, v11 = acc[mt][nt][3] + bv1;
            if (act) {
                v00 = 0.5f * v00 * (1.0f + erff(v00 * 0.70710678118654752f));
                v01 = 0.5f * v01 * (1.0f + erff(v01 * 0.70710678118654752f));
                v10 = 0.5f * v10 * (1.0f + erff(v10 * 0.70710678118654752f));
                v11 = 0.5f * v11 * (1.0f + erff(v11 * 0.70710678118654752f));
            }
            if (outMode == 1) {
                __half* C = (__half*)Cout;
                *(__half2*)(C + (size_t)r * N + c)       = __floats2half2_rn(v00, v01);
                *(__half2*)(C + (size_t)(r + 8) * N + c) = __floats2half2_rn(v10, v11);
            } else if (outMode == 0) {
                float* C = (float*)Cout;
                *(float2*)(C + (size_t)r * N + c)       = make_float2(v00, v01);
                *(float2*)(C + (size_t)(r + 8) * N + c) = make_float2(v10, v11);
            } else {
                // vpk-packed: pair row r (even, lr even) with row r+1 (lane+4)
                float p00 = __shfl_down_sync(0xffffffffu, v00, 4);
                float p01 = __shfl_down_sync(0xffffffffu, v01, 4);
                float p10 = __shfl_down_sync(0xffffffffu, v10, 4);
                float p11 = __shfl_down_sync(0xffffffffu, v11, 4);
                if (!(lr & 1)) {
                    unsigned* vpk = (unsigned*)Cout;
                    int b = r >> 9, s = r & 511;
                    int hh = c / DH, n = c - hh * DH;
                    size_t base = ((size_t)(b * HH + hh) * 256) * 64 + n;
                    unsigned* d0 = vpk + base + (size_t)(s >> 1) * 64;
                    d0[0] = pack2(v00, p00);
                    d0[1] = pack2(v01, p01);
                    unsigned* d1 = vpk + base + (size_t)((s + 8) >> 1) * 64;
                    d1[0] = pack2(v10, p10);
                    d1[1] = pack2(v11, p11);
                }
            }
        }
    }
}

// QKV: z=0 -> q16, z=1 -> k16, z=2 -> V directly into vpk (fused repack)
__global__ void __launch_bounds__(256) gemm_qkv(
    const __half* __restrict__ h16, const __half* __restrict__ wh,
    const float* __restrict__ bq, const float* __restrict__ bk, const float* __restrict__ bv,
    __half* __restrict__ q, __half* __restrict__ k, unsigned* __restrict__ vpk)
{
    const int z = blockIdx.z;
    const __half* Bp   = wh + ((z == 0) ? OQ : (z == 1) ? OK : OV);
    const float*  bias = (z == 0) ? bq : (z == 1) ? bk : bv;
    void* C = (z == 0) ? (void*)q : (z == 1) ? (void*)k : (void*)vpk;
    gemm128h_core(h16, Bp, bias, C, (z == 2) ? 2 : 1,
                  blockIdx.y * 128, blockIdx.x * 128, DD, DD, 0, DD, 0, 1);
}

__global__ void __launch_bounds__(256) gemm_pos(
    const __half* __restrict__ rel16, const __half* __restrict__ wh,
    const float* __restrict__ bq, const float* __restrict__ bk,
    __half* __restrict__ posqL, __half* __restrict__ poskL)
{
    const int z = blockIdx.z;
    const int l = z >> 1;
    const int isq = z & 1;
    const __half* Bp   = wh + (size_t)l * LSTR + (isq ? OQ : OK);
    const float*  bias = (isq ? bq : bk) + (size_t)l * DD;
    __half*       C    = (isq ? posqL : poskL) + (size_t)l * PP * DD;
    gemm128h_core(rel16, Bp, bias, C, 1, blockIdx.y * 128, blockIdx.x * 128, DD, DD, 0, DD, 0, 1);
}

__global__ void __launch_bounds__(256) gemm_one(
    const __half* __restrict__ A, const __half* __restrict__ Bp, const float* __restrict__ bias,
    __half* __restrict__ C, int N, int K, int act)
{
    gemm128h_core(A, Bp, bias, C, 1, blockIdx.y * 128, blockIdx.x * 128, N, K, 0, K, act, 1);
}

// split-K=2, fp16 delta outputs
__global__ void __launch_bounds__(256) gemm_sk(
    const __half* __restrict__ A, const __half* __restrict__ Bp, const float* __restrict__ bias,
    __half* __restrict__ C0, __half* __restrict__ C1, int N, int K)
{
    const int z = blockIdx.z;
    gemm128h_core(A, Bp, bias, z ? C1 : C0, 1, blockIdx.y * 128, blockIdx.x * 128,
                  N, K, z * (K >> 1), K >> 1, 0, z == 0);
}

// ---------------- fused disentangled score kernel (proven R16) ----------------
#define SC_STR 36
#define SCORE_SMEM (16896 * 4)
__global__ void __launch_bounds__(256) score_fused(
    const __half* __restrict__ Q, const __half* __restrict__ Kt,
    const __half* __restrict__ PKg, const __half* __restrict__ PQg,
    const int* __restrict__ tab, const float* __restrict__ mask,
    __half* __restrict__ scores, float scale)
{
    int z = blockIdx.z; int b = z / HH, hh = z % HH;
    int m0 = blockIdx.y * 64, n0 = blockIdx.x * 64;
    const __half* Aq = Q  + (size_t)b * SS * DD + hh * DH;
    const __half* Ak = Kt + (size_t)b * SS * DD + hh * DH;
    const __half* PK = PKg + hh * DH;
    const __half* PQ = PQg + hh * DH;

    extern __shared__ unsigned ssm[];
    unsigned* Qs  = ssm;
    unsigned* Ks  = ssm + 2304;
    unsigned* PKs = ssm + 4608;
    unsigned* PQs = ssm + 9216;
    float* C1s = (float*)ssm;
    float* C2s = (float*)(ssm + 8448);

    int tid = threadIdx.x;
    int w = tid >> 5, lane = tid & 31;
    int lr = lane >> 2, lc = lane & 3;
    int wr = w >> 2, wc = w & 3;
    const int dlo = m0 - n0 - 63;

    {
        int row = tid >> 2;
        int colh = (tid & 3) * 16;
        int colu = colh >> 1;
        const __half* pq_ = Aq + (size_t)(m0 + row) * DD + colh;
        cp16(Qs + row * SC_STR + colu,     pq_);
        cp16(Qs + row * SC_STR + colu + 4, pq_ + 8);
        const __half* pk_ = Ak + (size_t)(n0 + row) * DD + colh;
        cp16(Ks + row * SC_STR + colu,     pk_);
        cp16(Ks + row * SC_STR + colu + 4, pk_ + 8);
        #pragma unroll
        for (int half_ = 0; half_ < 2; half_++) {
            int t = row + half_ * 64;
            int tt = t < 127 ? t : 126;
            int pidx = tab[dlo + tt + 511];
            const __half* pk2 = PK + (size_t)pidx * DD + colh;
            cp16(PKs + t * SC_STR + colu,     pk2);
            cp16(PKs + t * SC_STR + colu + 4, pk2 + 8);
            const __half* pq2 = PQ + (size_t)pidx * DD + colh;
            cp16(PQs + t * SC_STR + colu,     pq2);
            cp16(PQs + t * SC_STR + colu + 4, pq2 + 8);
        }
        CP_COMMIT;
        CP_WAIT0;
    }
    __syncthreads();

    float accS[2][2][4] = {};
    float acc1[2][4][4] = {};
    float acc2[2][4][4] = {};

    #pragma unroll
    for (int c = 0; c < 4; c++) {
        int cu = c * 8;
        unsigned aq[2][4], ak[2][4];
        #pragma unroll
        for (int mt = 0; mt < 2; mt++) {
            int m = wr * 32 + mt * 16 + lr;
            aq[mt][0] = Qs[m * SC_STR + cu + lc];       aq[mt][1] = Qs[(m + 8) * SC_STR + cu + lc];
            aq[mt][2] = Qs[m * SC_STR + cu + lc + 4];   aq[mt][3] = Qs[(m + 8) * SC_STR + cu + lc + 4];
            ak[mt][0] = Ks[m * SC_STR + cu + lc];       ak[mt][1] = Ks[(m + 8) * SC_STR + cu + lc];
            ak[mt][2] = Ks[m * SC_STR + cu + lc + 4];   ak[mt][3] = Ks[(m + 8) * SC_STR + cu + lc + 4];
        }
        unsigned bS[2][2], b1[4][2], b2[4][2];
        #pragma unroll
        for (int nt = 0; nt < 2; nt++) {
            int n = wc * 16 + nt * 8 + lr;
            bS[nt][0] = Ks[n * SC_STR + cu + lc];
            bS[nt][1] = Ks[n * SC_STR + cu + lc + 4];
        }
        #pragma unroll
        for (int nt = 0; nt < 4; nt++) {
            int n = wc * 32 + nt * 8 + lr;
            b1[nt][0] = PKs[n * SC_STR + cu + lc];
            b1[nt][1] = PKs[n * SC_STR + cu + lc + 4];
            b2[nt][0] = PQs[n * SC_STR + cu + lc];
            b2[nt][1] = PQs[n * SC_STR + cu + lc + 4];
        }
        #pragma unroll
        for (int mt = 0; mt < 2; mt++) {
            #pragma unroll
            for (int nt = 0; nt < 2; nt++) mma_f16(accS[mt][nt], aq[mt], bS[nt]);
            #pragma unroll
            for (int nt = 0; nt < 4; nt++) { mma_f16(acc1[mt][nt], aq[mt], b1[nt]); mma_f16(acc2[mt][nt], ak[mt], b2[nt]); }
        }
    }
    __syncthreads();

    #pragma unroll
    for (int mt = 0; mt < 2; mt++) {
        int r = wr * 32 + mt * 16 + lr;
        #pragma unroll
        for (int nt = 0; nt < 4; nt++) {
            int c = wc * 32 + nt * 8 + lc * 2;
            C1s[r * 132 + c] = acc1[mt][nt][0]; C1s[r * 132 + c + 1] = acc1[mt][nt][1];
            C1s[(r + 8) * 132 + c] = acc1[mt][nt][2]; C1s[(r + 8) * 132 + c + 1] = acc1[mt][nt][3];
            C2s[r * 132 + c] = acc2[mt][nt][0]; C2s[r * 132 + c + 1] = acc2[mt][nt][1];
            C2s[(r + 8) * 132 + c] = acc2[mt][nt][2]; C2s[(r + 8) * 132 + c + 1] = acc2[mt][nt][3];
        }
    }
    __syncthreads();

    #pragma unroll
    for (int mt = 0; mt < 2; mt++) {
        #pragma unroll
        for (int nt = 0; nt < 2; nt++) {
            int r = wr * 32 + mt * 16 + lr;
            int c0 = wc * 16 + nt * 8 + lc * 2;
            #pragma unroll
            for (int half_ = 0; half_ < 2; half_++) {
                int rr = r + half_ * 8;
                float o[2];
                #pragma unroll
                for (int e = 0; e < 2; e++) {
                    int cc = c0 + e;
                    int t = rr - cc + 63;
                    float val = (accS[mt][nt][half_ * 2 + e] + C1s[rr * 132 + t] + C2s[cc * 132 + t]) * scale;
                    val += (1.0f - mask[b * SS + n0 + cc]) * (-1e9f);
                    o[e] = fmaxf(val, -60000.0f);
                }
                *(__half2*)(scores + ((size_t)z * SS + m0 + rr) * SS + n0 + c0) = __floats2half2_rn(o[0], o[1]);
            }
        }
    }
}

// ---------------- warp-per-row softmax (proven R16) ----------------
__global__ void __launch_bounds__(256) softmax_kernel(__half* __restrict__ scores)
{
    int wid = threadIdx.x >> 5, lane = threadIdx.x & 31;
    int row = blockIdx.x * 8 + wid;
    int z = blockIdx.y;
    __half* rp = scores + ((size_t)z * SS + row) * SS + lane * 16;

    uint4 u0 = *(const uint4*)rp;
    uint4 u1 = *(const uint4*)(rp + 8);
    float f[16];
    {
        const unsigned* uu = &u0.x;
        #pragma unroll
        for (int i = 0; i < 4; i++) {
            float2 p = __half22float2(*reinterpret_cast<const __half2*>(&uu[i]));
            f[i * 2] = p.x; f[i * 2 + 1] = p.y;
        }
        const unsigned* vv = &u1.x;
        #pragma unroll
        for (int i = 0; i < 4; i++) {
            float2 p = __half22float2(*reinterpret_cast<const __half2*>(&vv[i]));
            f[8 + i * 2] = p.x; f[8 + i * 2 + 1] = p.y;
        }
    }
    float mx = f[0];
    #pragma unroll
    for (int i = 1; i < 16; i++) mx = fmaxf(mx, f[i]);
    #pragma unroll
    for (int o = 16; o > 0; o >>= 1) mx = fmaxf(mx, __shfl_xor_sync(0xffffffffu, mx, o));
    float s = 0.f;
    #pragma unroll
    for (int i = 0; i < 16; i++) { f[i] = expf(f[i] - mx); s += f[i]; }
    #pragma unroll
    for (int o = 16; o > 0; o >>= 1) s += __shfl_xor_sync(0xffffffffu, s, o);
    float inv = 1.0f / s;
    uint4 o0, o1;
    o0.x = pack2(f[0] * inv, f[1] * inv);   o0.y = pack2(f[2] * inv, f[3] * inv);
    o0.z = pack2(f[4] * inv, f[5] * inv);   o0.w = pack2(f[6] * inv, f[7] * inv);
    o1.x = pack2(f[8] * inv, f[9] * inv);   o1.y = pack2(f[10] * inv, f[11] * inv);
    o1.z = pack2(f[12] * inv, f[13] * inv); o1.w = pack2(f[14] * inv, f[15] * inv);
    *(uint4*)rp = o0;
    *(uint4*)(rp + 8) = o1;
}

// ---------------- batched ctx GEMM — fully async, 3-stage (proven R16) ----------------
#define CTXB_STR 72
#define CTXA_STG (128*A_STR)
#define CTXB_STG (8*CTXB_STR)
#define CTX_SMEM ((CTXA_STG + CTXB_STG) * 3 * 4)
__global__ void __launch_bounds__(256) ctx_f16(
    const __half* __restrict__ Pm, const unsigned* __restrict__ vpk, __half* __restrict__ O)
{
    int z = blockIdx.y; int b = z / HH, hh = z % HH;
    int m0 = blockIdx.x * 128;
    const __half* A = Pm + (size_t)z * SS * SS;
    const unsigned* Bv = vpk + (size_t)z * 256 * 64;

    extern __shared__ unsigned dsm[];
    unsigned* Asm = dsm;
    unsigned* Bsm = dsm + 3 * CTXA_STG;

    int tid = threadIdx.x;
    int w = tid >> 5, lane = tid & 31;
    int lr = lane >> 2, lc = lane & 3;
    int wm = (w >> 1) * 32, wn = (w & 1) * 32;

    int arow = tid >> 1, apart = tid & 1;
    int brow2 = (tid >> 4) & 7, bcol4 = (tid & 15) * 4;
    bool bload = tid < 128;

    const __half*   abase = A + (size_t)(m0 + arow) * SS + apart * 8;
    const unsigned* bbase = Bv + brow2 * 64 + bcol4;

    const int kTiles = SS / 16;

    #define CISSUE(s, kt) do { \
        unsigned* as_ = Asm + (s) * CTXA_STG; \
        unsigned* bs_ = Bsm + (s) * CTXB_STG; \
        cp16(as_ + arow * A_STR + apart * 4, abase + (size_t)(kt) * 16); \
        if (bload) cp16(bs_ + brow2 * CTXB_STR + bcol4, bbase + (size_t)(kt) * 8 * 64); \
    } while (0)

    CISSUE(0, 0); CP_COMMIT;
    CISSUE(1, 1); CP_COMMIT;

    float acc[2][4][4] = {};

    for (int kt = 0; kt < kTiles; kt++) {
        CP_WAIT1;
        __syncthreads();
        if (kt + 2 < kTiles) CISSUE((kt + 2) % 3, kt + 2);
        CP_COMMIT;

        const unsigned* as = Asm + (kt % 3) * CTXA_STG;
        const unsigned* bs = Bsm + (kt % 3) * CTXB_STG;

        unsigned af[2][4], bf[4][2];
        #pragma unroll
        for (int mt = 0; mt < 2; mt++) {
            int m = wm + mt * 16 + lr;
            af[mt][0] = as[m * A_STR + lc];
            af[mt][1] = as[(m + 8) * A_STR + lc];
            af[mt][2] = as[m * A_STR + lc + 4];
            af[mt][3] = as[(m + 8) * A_STR + lc + 4];
        }
        #pragma unroll
        for (int nt = 0; nt < 4; nt++) {
            int n = wn + nt * 8 + lr;
            bf[nt][0] = bs[lc * CTXB_STR + n];
            bf[nt][1] = bs[(lc + 4) * CTXB_STR + n];
        }
        #pragma unroll
        for (int mt = 0; mt < 2; mt++)
            #pragma unroll
            for (int nt = 0; nt < 4; nt++)
                mma_f16(acc[mt][nt], af[mt], bf[nt]);
    }
    #undef CISSUE

    #pragma unroll
    for (int mt = 0; mt < 2; mt++) {
        int r = m0 + wm + mt * 16 + lr;
        #pragma unroll
        for (int nt = 0; nt < 4; nt++) {
            int c = wn + nt * 8 + lc * 2;
            *(__half2*)(O + ((size_t)b * SS + r) * DD + hh * DH + c)     = __floats2half2_rn(acc[mt][nt][0], acc[mt][nt][1]);
            *(__half2*)(O + ((size_t)b * SS + r + 8) * DD + hh * DH + c) = __floats2half2_rn(acc[mt][nt][2], acc[mt][nt][3]);
        }
    }
}

// ---------------- residual add (two fp16 deltas) + LN ----------------
__global__ void __launch_bounds__(256) add_ln3_kernel(
    float* __restrict__ h, __half* __restrict__ h16,
    const __half* __restrict__ d1, const __half* __restrict__ d2,
    const float* __restrict__ w, const float* __restrict__ b)
{
    int t = blockIdx.x, tid = threadIdx.x;
    __shared__ float xs[DD];
    __shared__ float red[256];
    float* hr = h + (size_t)t * DD;
    __half* hr16 = h16 + (size_t)t * DD;
    const __half* r1 = d1 + (size_t)t * DD;
    const __half* r2 = d2 + (size_t)t * DD;

    float s = 0.f;
    for (int d = tid; d < DD; d += 256) {
        float x = hr[d] + __half2float(r1[d]) + __half2float(r2[d]);
        xs[d] = x; s += x;
    }
    red[tid] = s; __syncthreads();
    for (int st = 128; st > 0; st >>= 1) { if (tid < st) red[tid] += red[tid + st]; __syncthreads(); }
    float mu = red[0] * (1.0f / DD); __syncthreads();
    float s2 = 0.f;
    for (int d = tid; d < DD; d += 256) { float dv = xs[d] - mu; s2 += dv * dv; }
    red[tid] = s2; __syncthreads();
    for (int st = 128; st > 0; st >>= 1) { if (tid < st) red[tid] += red[tid + st]; __syncthreads(); }
    float inv = rsqrtf(red[0] * (1.0f / DD) + 1e-12f);
    for (int d = tid; d < DD; d += 256) {
        float val = (xs[d] - mu) * inv * w[d] + b[d];
        hr[d] = val;
        hr16[d] = __float2half_rn(val);
    }
}

// ---------------- host orchestration ----------------
extern "C" void kernel_launch(void* const* d_in, const int* in_sizes, int n_in,
                              void* d_out, int out_size)
{
    const int*   input_ids   = (const int*)  d_in[0];
    const int*   segment_ids = (const int*)  d_in[1];
    const int*   pinyin_ids  = (const int*)  d_in[2];
    const float* attn_mask   = (const float*)d_in[3];
    const float* tok_emb     = (const float*)d_in[4];
    const float* pin_emb     = (const float*)d_in[5];
    const float* seg_emb     = (const float*)d_in[6];
    const float* emb_ln_w    = (const float*)d_in[7];
    const float* emb_ln_b    = (const float*)d_in[8];
    const float* rel_emb     = (const float*)d_in[9];
    const float* Wq = (const float*)d_in[10]; const float* bq = (const float*)d_in[11];
    const float* Wk = (const float*)d_in[12]; const float* bk = (const float*)d_in[13];
    const float* Wv = (const float*)d_in[14]; const float* bv = (const float*)d_in[15];
    const float* Wo = (const float*)d_in[16]; const float* bo = (const float*)d_in[17];
    const float* ln1w = (const float*)d_in[18]; const float* ln1b = (const float*)d_in[19];
    const float* W1 = (const float*)d_in[20]; const float* b1 = (const float*)d_in[21];
    const float* W2 = (const float*)d_in[22]; const float* b2 = (const float*)d_in[23];
    const float* ln2w = (const float*)d_in[24]; const float* ln2b = (const float*)d_in[25];

    float *h;
    __half *s1, *s2, *scores16, *h16, *q16, *k16, *ctx16, *tmp16, *posk16, *posq16, *rel16, *wh;
    unsigned *vpk;
    int *tab;
    cudaGetSymbolAddress((void**)&h,        g_h);
    cudaGetSymbolAddress((void**)&s1,       g_s1);
    cudaGetSymbolAddress((void**)&s2,       g_s2);
    cudaGetSymbolAddress((void**)&scores16, g_scores16);
    cudaGetSymbolAddress((void**)&h16,      g_h16);
    cudaGetSymbolAddress((void**)&q16,      g_q16);
    cudaGetSymbolAddress((void**)&k16,      g_k16);
    cudaGetSymbolAddress((void**)&ctx16,    g_ctx16);
    cudaGetSymbolAddress((void**)&tmp16,    g_tmp16);
    cudaGetSymbolAddress((void**)&posk16,   g_posk16);
    cudaGetSymbolAddress((void**)&posq16,   g_posq16);
    cudaGetSymbolAddress((void**)&rel16,    g_rel16);
    cudaGetSymbolAddress((void**)&vpk,      g_vpk);
    cudaGetSymbolAddress((void**)&wh,       g_wh);
    cudaGetSymbolAddress((void**)&tab,      g_tab);

    cudaFuncSetAttribute(gemm_qkv,    cudaFuncAttributeMaxDynamicSharedMemorySize, GEMM_SMEM);
    cudaFuncSetAttribute(gemm_pos,    cudaFuncAttributeMaxDynamicSharedMemorySize, GEMM_SMEM);
    cudaFuncSetAttribute(gemm_one,    cudaFuncAttributeMaxDynamicSharedMemorySize, GEMM_SMEM);
    cudaFuncSetAttribute(gemm_sk,     cudaFuncAttributeMaxDynamicSharedMemorySize, GEMM_SMEM);
    cudaFuncSetAttribute(ctx_f16,     cudaFuncAttributeMaxDynamicSharedMemorySize, CTX_SMEM);
    cudaFuncSetAttribute(score_fused, cudaFuncAttributeMaxDynamicSharedMemorySize, SCORE_SMEM);

    const float scale = 0.07216878364870323f;  // 1/sqrt(3*DH)

    embed_ln_kernel<<<MM, 256>>>(input_ids, segment_ids, pinyin_ids, attn_mask,
                                 tok_emb, pin_emb, seg_emb, emb_ln_w, emb_ln_b, h, h16);
    buckets_kernel<<<4, 256>>>(tab);
    convert_h<<<(PP * DD + 255) / 256, 256>>>(rel_emb, rel16, (size_t)PP * DD);

    convert_w4<<<dim3(288, 1, 4 * LL), 256>>>(Wq, Wk, Wv, Wo, wh);
    convert_w<<<dim3(1152, 1, LL), 256>>>(W1, wh + OW1, FF / 4, FF, (size_t)DD * FF, LSTR);
    convert_w<<<dim3(1152, 1, LL), 256>>>(W2, wh + OW2, DD / 4, DD, (size_t)FF * DD, LSTR);

    gemm_pos<<<dim3(DD / 128, PP / 128, 2 * LL), 256, GEMM_SMEM>>>(
        rel16, wh, bq, bk, posq16, posk16);

    for (int i = 0; i < LL; i++) {
        const __half* wl = wh + (size_t)i * LSTR;
        const float* bq_i = bq + (size_t)i * DD;
        const float* bk_i = bk + (size_t)i * DD;
        const float* bv_i = bv + (size_t)i * DD;
        const float* bo_i = bo + (size_t)i * DD;
        const float* b1_i = b1 + (size_t)i * FF;
        const float* b2_i = b2 + (size_t)i * DD;
        const __half* posk_i = posk16 + (size_t)i * PP * DD;
        const __half* posq_i = posq16 + (size_t)i * PP * DD;

        gemm_qkv<<<dim3(DD / 128, MM / 128, 3), 256, GEMM_SMEM>>>(
            h16, wl, bq_i, bk_i, bv_i, q16, k16, vpk);

        score_fused<<<dim3(8, 8, BH), 256, SCORE_SMEM>>>(
            q16, k16, posk_i, posq_i, tab, attn_mask, scores16, scale);
        softmax_kernel<<<dim3(SS / 8, BH), 256>>>(scores16);
        ctx_f16<<<dim3(SS / 128, BH), 256, CTX_SMEM>>>(scores16, vpk, ctx16);

        gemm_sk<<<dim3(DD / 128, MM / 128, 2), 256, GEMM_SMEM>>>(
            ctx16, wl + OO, bo_i, s1, s2, DD, DD);
        add_ln3_kernel<<<MM, 256>>>(h, h16, s1, s2, ln1w + (size_t)i * DD, ln1b + (size_t)i * DD);

        gemm_one<<<dim3(FF / 128, MM / 128), 256, GEMM_SMEM>>>(h16, wl + OW1, b1_i, tmp16, FF, DD, 1);
        gemm_sk<<<dim3(DD / 128, MM / 128, 2), 256, GEMM_SMEM>>>(
            tmp16, wl + OW2, b2_i, s1, s2, DD, FF);
        add_ln3_kernel<<<MM, 256>>>(h, h16, s1, s2, ln2w + (size_t)i * DD, ln2b + (size_t)i * DD);
    }

    cudaMemcpyAsync(d_out, h, sizeof(float) * (size_t)out_size, cudaMemcpyDeviceToDevice);
}